// round 9
// baseline (speedup 1.0000x reference)
#include <cuda_runtime.h>
#include <cuda_bf16.h>
#include <cstdint>
#include <math.h>

// Problem constants
#define PB 2
#define PL 2048
#define PD 1024
#define PH 16
#define PDK 64
#define PM (PB * PL)   // 4096
#define MD (PM * PD)
#define DD (PD * PD)

// Scratch (device globals)
__device__ __nv_bfloat16 g_xhi[3 * MD];   // Q,K,V input splits
__device__ __nv_bfloat16 g_xlo[3 * MD];
__device__ __nv_bfloat16 g_whi[4 * DD];   // Wq,Wk,Wv,fc
__device__ __nv_bfloat16 g_wlo[4 * DD];
__device__ __nv_bfloat16 g_yhi[3 * MD];   // q,k,v projections
__device__ __nv_bfloat16 g_ylo[3 * MD];
__device__ __nv_bfloat16 g_ahi[MD];       // attention output split
__device__ __nv_bfloat16 g_alo[MD];

// ---------------------------------------------------------------------------
// PTX helpers
// ---------------------------------------------------------------------------
__device__ __forceinline__ uint32_t smem_u32(const void* p) {
    uint32_t a;
    asm("{ .reg .u64 t; cvta.to.shared.u64 t, %1; cvt.u32.u64 %0, t; }"
        : "=r"(a) : "l"(p));
    return a;
}

// NOTE: non-volatile — lets the compiler interleave independent MMAs.
#define MMA16816(c, a, b) \
    asm("mma.sync.aligned.m16n8k16.row.col.f32.bf16.bf16.f32 " \
        "{%0,%1,%2,%3}, {%4,%5,%6,%7}, {%8,%9}, {%0,%1,%2,%3};" \
        : "+f"((c)[0]), "+f"((c)[1]), "+f"((c)[2]), "+f"((c)[3]) \
        : "r"((a)[0]), "r"((a)[1]), "r"((a)[2]), "r"((a)[3]), \
          "r"((b)[0]), "r"((b)[1]))

#define LDSM_X4(r0, r1, r2, r3, addr) \
    asm volatile("ldmatrix.sync.aligned.m8n8.x4.shared.b16 {%0,%1,%2,%3}, [%4];" \
        : "=r"(r0), "=r"(r1), "=r"(r2), "=r"(r3) : "r"(addr))

#define LDSM_X4_T(r0, r1, r2, r3, addr) \
    asm volatile("ldmatrix.sync.aligned.m8n8.x4.trans.shared.b16 {%0,%1,%2,%3}, [%4];" \
        : "=r"(r0), "=r"(r1), "=r"(r2), "=r"(r3) : "r"(addr))

#define CP_ASYNC16(smem, gptr) \
    asm volatile("cp.async.cg.shared.global [%0], [%1], 16;" \
        :: "r"(smem), "l"(gptr))
#define CP_COMMIT() asm volatile("cp.async.commit_group;" ::: "memory")
#define CP_WAIT0()  asm volatile("cp.async.wait_group 0;" ::: "memory")
#define CP_WAIT1()  asm volatile("cp.async.wait_group 1;" ::: "memory")

__device__ __forceinline__ float ex2f(float x) {
    float r;
    asm("ex2.approx.f32 %0, %1;" : "=f"(r) : "f"(x));
    return r;
}

__device__ __forceinline__ void split2(float a, float b, uint32_t& hi, uint32_t& lo) {
    __nv_bfloat16 ha = __float2bfloat16(a);
    __nv_bfloat16 hb = __float2bfloat16(b);
    float ra = a - __bfloat162float(ha);
    float rb = b - __bfloat162float(hb);
    __nv_bfloat162 H; H.x = ha; H.y = hb;
    __nv_bfloat162 L; L.x = __float2bfloat16(ra); L.y = __float2bfloat16(rb);
    hi = *reinterpret_cast<uint32_t*>(&H);
    lo = *reinterpret_cast<uint32_t*>(&L);
}

// ---------------------------------------------------------------------------
// Batched splits
// ---------------------------------------------------------------------------
__device__ __forceinline__ void split_body(
    const float* x, __nv_bfloat16* hi, __nv_bfloat16* lo, int i)
{
    float4 v = reinterpret_cast<const float4*>(x)[i];
    uint32_t h0, l0, h1, l1;
    split2(v.x, v.y, h0, l0);
    split2(v.z, v.w, h1, l1);
    reinterpret_cast<uint2*>(hi)[i] = make_uint2(h0, h1);
    reinterpret_cast<uint2*>(lo)[i] = make_uint2(l0, l1);
}

__global__ __launch_bounds__(256) void split3_in(
    const float* __restrict__ x0, const float* __restrict__ x1,
    const float* __restrict__ x2,
    __nv_bfloat16* hi, __nv_bfloat16* lo)
{
    const int i = blockIdx.x * 256 + threadIdx.x;
    const int z = blockIdx.z;
    const float* x = (z == 0) ? x0 : (z == 1) ? x1 : x2;
    split_body(x, hi + (size_t)z * MD, lo + (size_t)z * MD, i);
}

__global__ __launch_bounds__(256) void split4_w(
    const float* __restrict__ x0, const float* __restrict__ x1,
    const float* __restrict__ x2, const float* __restrict__ x3,
    __nv_bfloat16* hi, __nv_bfloat16* lo)
{
    const int i = blockIdx.x * 256 + threadIdx.x;
    const int z = blockIdx.z;
    const float* x = (z == 0) ? x0 : (z == 1) ? x1 : (z == 2) ? x2 : x3;
    split_body(x, hi + (size_t)z * DD, lo + (size_t)z * DD, i);
}

// ---------------------------------------------------------------------------
// mma.sync bf16 GEMM (3-term split): round-6 shape + MMA pass-splitting.
// 128x256x32 tiles, 256 threads (2m x 4n warps), 3-stage cp.async.
// ---------------------------------------------------------------------------
#define BGM 128
#define BGN 256
#define BGK 32
#define GP 40                             // smem pitch (bf16)
#define A_T (BGM * GP * 2)                // 10240 B
#define B_T (BGN * GP * 2)                // 20480 B
#define OFF_GA_HI 0
#define OFF_GA_LO A_T
#define OFF_GB_HI (2 * A_T)
#define OFF_GB_LO (2 * A_T + B_T)
#define STG_B (2 * A_T + 2 * B_T)         // 61440 B
#define NST 3
#define G_SMEM (NST * STG_B)              // 184320 B

template <bool SPLIT>
__global__ __launch_bounds__(256, 1) void gemm3_mma(
    const __nv_bfloat16* __restrict__ Ahi, const __nv_bfloat16* __restrict__ Alo,
    const __nv_bfloat16* __restrict__ Bhi, const __nv_bfloat16* __restrict__ Blo,
    const float* __restrict__ bias, float* __restrict__ C,
    __nv_bfloat16* __restrict__ Chi, __nv_bfloat16* __restrict__ Clo,
    int K, int N)
{
    extern __shared__ char dsm[];
    __shared__ float sbias[BGN];

    const int tid = threadIdx.x;
    const int w = tid >> 5;
    const int lane = tid & 31;
    const int wm = w >> 2;
    const int wn = w & 3;
    const int g = lane >> 2;
    const int tq = lane & 3;
    const int bm = blockIdx.y * BGM;
    const int bn = blockIdx.x * BGN;
    const uint32_t sbase = smem_u32(dsm);

    const int lr = tid >> 2;              // 0..63
    const int lc = (tid & 3) * 8;         // 0,8,16,24

    auto issue = [&](int c, int buf) {
        const uint32_t sb = sbase + buf * STG_B;
        const int kofs = c * BGK;
#pragma unroll
        for (int it = 0; it < 2; ++it) {
            const int r = lr + it * 64;
            const uint32_t so = (uint32_t)(r * GP + lc) * 2;
            const size_t go = (size_t)(bm + r) * K + kofs + lc;
            CP_ASYNC16(sb + OFF_GA_HI + so, (const char*)(Ahi + go));
            CP_ASYNC16(sb + OFF_GA_LO + so, (const char*)(Alo + go));
        }
#pragma unroll
        for (int it = 0; it < 4; ++it) {
            const int r = lr + it * 64;
            const uint32_t so = (uint32_t)(r * GP + lc) * 2;
            const size_t go = (size_t)(bn + r) * K + kofs + lc;
            CP_ASYNC16(sb + OFF_GB_HI + so, (const char*)(Bhi + go));
            CP_ASYNC16(sb + OFF_GB_LO + so, (const char*)(Blo + go));
        }
    };

    issue(0, 0); CP_COMMIT();
    issue(1, 1); CP_COMMIT();

    sbias[tid] = bias[bn + tid];

    float acc[4][8][4];
#pragma unroll
    for (int mi = 0; mi < 4; ++mi)
#pragma unroll
        for (int nb = 0; nb < 8; ++nb)
#pragma unroll
            for (int e = 0; e < 4; ++e) acc[mi][nb][e] = 0.0f;

    const int a_r = (lane & 7) + ((lane >> 3) & 1) * 8;
    const int a_c = ((lane >> 4) & 1) * 8;
    const int b_r = (lane & 7) + ((lane >> 4) & 1) * 8;
    const int b_c = ((lane >> 3) & 1) * 8;

    const int nchunk = K / BGK;   // 32
    for (int c = 0; c < nchunk; ++c) {
        if (c + 1 < nchunk) CP_WAIT1(); else CP_WAIT0();
        __syncthreads();
        if (c + 2 < nchunk) { issue(c + 2, (c + 2) % NST); CP_COMMIT(); }

        const uint32_t sb = sbase + (c % NST) * STG_B;
#pragma unroll
        for (int kk = 0; kk < 2; ++kk) {
            uint32_t ah[4][4], al[4][4];
#pragma unroll
            for (int mi = 0; mi < 4; ++mi) {
                const uint32_t off =
                    (uint32_t)((wm * 64 + mi * 16 + a_r) * GP + kk * 16 + a_c) * 2;
                LDSM_X4(ah[mi][0], ah[mi][1], ah[mi][2], ah[mi][3],
                        sb + OFF_GA_HI + off);
                LDSM_X4(al[mi][0], al[mi][1], al[mi][2], al[mi][3],
                        sb + OFF_GA_LO + off);
            }
            uint32_t bh[8][2], bl[8][2];
#pragma unroll
            for (int np = 0; np < 4; ++np) {
                const uint32_t off =
                    (uint32_t)((wn * 64 + np * 16 + b_r) * GP + kk * 16 + b_c) * 2;
                LDSM_X4(bh[2 * np][0], bh[2 * np][1], bh[2 * np + 1][0], bh[2 * np + 1][1],
                        sb + OFF_GB_HI + off);
                LDSM_X4(bl[2 * np][0], bl[2 * np][1], bl[2 * np + 1][0], bl[2 * np + 1][1],
                        sb + OFF_GB_LO + off);
            }
            // Three independent passes: consecutive MMAs hit different
            // accumulators (dependency distance 32) instead of a 3-chain.
#pragma unroll
            for (int mi = 0; mi < 4; ++mi)
#pragma unroll
                for (int nb = 0; nb < 8; ++nb)
                    MMA16816(acc[mi][nb], ah[mi], bh[nb]);
#pragma unroll
            for (int mi = 0; mi < 4; ++mi)
#pragma unroll
                for (int nb = 0; nb < 8; ++nb)
                    MMA16816(acc[mi][nb], ah[mi], bl[nb]);
#pragma unroll
            for (int mi = 0; mi < 4; ++mi)
#pragma unroll
                for (int nb = 0; nb < 8; ++nb)
                    MMA16816(acc[mi][nb], al[mi], bh[nb]);
        }
    }

    // epilogue: bias add + direct store from registers
#pragma unroll
    for (int mi = 0; mi < 4; ++mi) {
        const int row0 = bm + wm * 64 + mi * 16 + g;
        const int row1 = row0 + 8;
#pragma unroll
        for (int nb = 0; nb < 8; ++nb) {
            const int coll = wn * 64 + nb * 8 + 2 * tq;
            const float b0 = sbias[coll];
            const float b1 = sbias[coll + 1];
            const float v0 = acc[mi][nb][0] + b0;
            const float v1 = acc[mi][nb][1] + b1;
            const float v2 = acc[mi][nb][2] + b0;
            const float v3 = acc[mi][nb][3] + b1;
            const size_t o0 = (size_t)row0 * N + bn + coll;
            const size_t o1 = (size_t)row1 * N + bn + coll;
            if (SPLIT) {
                uint32_t hi, lo;
                split2(v0, v1, hi, lo);
                *(uint32_t*)(Chi + o0) = hi;
                *(uint32_t*)(Clo + o0) = lo;
                split2(v2, v3, hi, lo);
                *(uint32_t*)(Chi + o1) = hi;
                *(uint32_t*)(Clo + o1) = lo;
            } else {
                *(float2*)(C + o0) = make_float2(v0, v1);
                *(float2*)(C + o1) = make_float2(v2, v3);
            }
        }
    }
}

// ---------------------------------------------------------------------------
// Register-resident FA2 on mma.sync — 64-row q-tiles, 128 threads, occ 2,
// MMA pass-splitting.
// ---------------------------------------------------------------------------
#define FPITCH 72
#define AQ_HI 0
#define AQ_LO 9216
#define AKV   18432
#define KV_STAGE 36864
#define AK_HI 0
#define AK_LO 9216
#define AV_HI 18432
#define AV_LO 27648
#define ATT_SMEM (AKV + 2 * KV_STAGE)     // 92160

#define SFC 0.18033688f                   // 0.125 * log2(e)

__global__ __launch_bounds__(128, 2) void flash_attn_mma(
    const __nv_bfloat16* __restrict__ qhi, const __nv_bfloat16* __restrict__ qlo,
    const __nv_bfloat16* __restrict__ khi, const __nv_bfloat16* __restrict__ klo,
    const __nv_bfloat16* __restrict__ vhi, const __nv_bfloat16* __restrict__ vlo,
    __nv_bfloat16* __restrict__ ohi, __nv_bfloat16* __restrict__ olo)
{
    extern __shared__ char dsm[];
    const int tid = threadIdx.x;
    const int w = tid >> 5;
    const int lane = tid & 31;
    const int g = lane >> 2;
    const int tq = lane & 3;
    const int qt = (int)(gridDim.x - 1) - (int)blockIdx.x;
    const int b = blockIdx.y >> 4;
    const int h = blockIdx.y & 15;
    const size_t rowbase = (size_t)b * PL * PD + (size_t)h * PDK;

    const uint32_t sQh = smem_u32(dsm + AQ_HI);
    const uint32_t sQl = smem_u32(dsm + AQ_LO);
    const uint32_t sKV = smem_u32(dsm + AKV);

    const int kr0 = tid >> 3;
    const int kc0 = (tid & 7) * 8;

    {
        const uint32_t sb = sKV;
#pragma unroll
        for (int it = 0; it < 4; ++it) {
            const int r = kr0 + it * 16;
            const uint32_t so = (uint32_t)(r * FPITCH + kc0) * 2;
            const size_t go = rowbase + (size_t)r * PD + kc0;
            CP_ASYNC16(sb + AK_HI + so, (const char*)(khi + go));
            CP_ASYNC16(sb + AK_LO + so, (const char*)(klo + go));
            CP_ASYNC16(sb + AV_HI + so, (const char*)(vhi + go));
            CP_ASYNC16(sb + AV_LO + so, (const char*)(vlo + go));
        }
        CP_COMMIT();
    }

#pragma unroll
    for (int it = 0; it < 4; ++it) {
        const int idx = tid + it * 128;
        const int r = idx >> 3;
        const int c = (idx & 7) * 8;
        const size_t go = rowbase + (size_t)(qt * 64 + r) * PD + c;
        const uint32_t so = (uint32_t)(r * FPITCH + c) * 2;
        *(uint4*)(dsm + AQ_HI + so) = *(const uint4*)(qhi + go);
        *(uint4*)(dsm + AQ_LO + so) = *(const uint4*)(qlo + go);
    }
    CP_WAIT0();
    __syncthreads();

    uint32_t qh[4][4], ql[4][4];
    {
        const int row = w * 16 + (lane & 7) + ((lane >> 3) & 1) * 8;
#pragma unroll
        for (int kb = 0; kb < 4; ++kb) {
            const int col = kb * 16 + ((lane >> 4) & 1) * 8;
            const uint32_t off = (uint32_t)(row * FPITCH + col) * 2;
            LDSM_X4(qh[kb][0], qh[kb][1], qh[kb][2], qh[kb][3], sQh + off);
            LDSM_X4(ql[kb][0], ql[kb][1], ql[kb][2], ql[kb][3], sQl + off);
        }
    }

    float oacc[8][4];
#pragma unroll
    for (int nb = 0; nb < 8; ++nb)
#pragma unroll
        for (int e = 0; e < 4; ++e) oacc[nb][e] = 0.0f;
    float m0 = -1.0e30f, m1 = -1.0e30f, l0 = 0.0f, l1 = 0.0f;

    const int jmax = qt;
    for (int j = 0; j <= jmax; ++j) {
        const int buf = j & 1;
        const uint32_t sb = sKV + buf * KV_STAGE;

        if (j < jmax) {
            const uint32_t nb_ = sKV + (buf ^ 1) * KV_STAGE;
#pragma unroll
            for (int it = 0; it < 4; ++it) {
                const int r = kr0 + it * 16;
                const uint32_t so = (uint32_t)(r * FPITCH + kc0) * 2;
                const size_t go = rowbase + (size_t)((j + 1) * 64 + r) * PD + kc0;
                CP_ASYNC16(nb_ + AK_HI + so, (const char*)(khi + go));
                CP_ASYNC16(nb_ + AK_LO + so, (const char*)(klo + go));
                CP_ASYNC16(nb_ + AV_HI + so, (const char*)(vhi + go));
                CP_ASYNC16(nb_ + AV_LO + so, (const char*)(vlo + go));
            }
            CP_COMMIT();
        }

        float sacc[8][4];
#pragma unroll
        for (int nb = 0; nb < 8; ++nb)
#pragma unroll
            for (int e = 0; e < 4; ++e) sacc[nb][e] = 0.0f;

#pragma unroll
        for (int kb = 0; kb < 4; ++kb) {
            uint32_t kh[8][2], kl[8][2];
            const int kcol = kb * 16 + ((lane >> 3) & 1) * 8;
#pragma unroll
            for (int np = 0; np < 4; ++np) {
                const int krow = np * 16 + (lane & 7) + ((lane >> 4) & 1) * 8;
                const uint32_t off = (uint32_t)(krow * FPITCH + kcol) * 2;
                LDSM_X4(kh[2 * np][0], kh[2 * np][1], kh[2 * np + 1][0], kh[2 * np + 1][1],
                        sb + AK_HI + off);
                LDSM_X4(kl[2 * np][0], kl[2 * np][1], kl[2 * np + 1][0], kl[2 * np + 1][1],
                        sb + AK_LO + off);
            }
            // pass-split MMAs (dependency distance 8)
#pragma unroll
            for (int nb = 0; nb < 8; ++nb) MMA16816(sacc[nb], qh[kb], kh[nb]);
#pragma unroll
            for (int nb = 0; nb < 8; ++nb) MMA16816(sacc[nb], qh[kb], kl[nb]);
#pragma unroll
            for (int nb = 0; nb < 8; ++nb) MMA16816(sacc[nb], ql[kb], kh[nb]);
        }

        if (j == qt) {
            const int row0 = qt * 64 + w * 16 + g;
            const int row1 = row0 + 8;
            const int cb = j * 64 + 2 * tq;
#pragma unroll
            for (int nb = 0; nb < 8; ++nb) {
                const int c0 = cb + nb * 8, c1 = c0 + 1;
                if (c0 > row0) sacc[nb][0] = -1.0e30f;
                if (c1 > row0) sacc[nb][1] = -1.0e30f;
                if (c0 > row1) sacc[nb][2] = -1.0e30f;
                if (c1 > row1) sacc[nb][3] = -1.0e30f;
            }
        }

        float mx0 = -1.0e30f, mx1 = -1.0e30f;
#pragma unroll
        for (int nb = 0; nb < 8; ++nb) {
            mx0 = fmaxf(mx0, fmaxf(sacc[nb][0], sacc[nb][1]));
            mx1 = fmaxf(mx1, fmaxf(sacc[nb][2], sacc[nb][3]));
        }
        mx0 = fmaxf(mx0, __shfl_xor_sync(0xffffffffu, mx0, 1));
        mx0 = fmaxf(mx0, __shfl_xor_sync(0xffffffffu, mx0, 2));
        mx1 = fmaxf(mx1, __shfl_xor_sync(0xffffffffu, mx1, 1));
        mx1 = fmaxf(mx1, __shfl_xor_sync(0xffffffffu, mx1, 2));

        const float mn0 = fmaxf(m0, mx0);
        const float mn1 = fmaxf(m1, mx1);
        const float em0 = mn0 * SFC;
        const float em1 = mn1 * SFC;
        const float cr0 = ex2f((m0 - mn0) * SFC);
        const float cr1 = ex2f((m1 - mn1) * SFC);
        m0 = mn0; m1 = mn1;

        float s0 = 0.0f, s1 = 0.0f;
#pragma unroll
        for (int nb = 0; nb < 8; ++nb) {
            float p0 = ex2f(fmaf(sacc[nb][0], SFC, -em0));
            float p1 = ex2f(fmaf(sacc[nb][1], SFC, -em0));
            float p2 = ex2f(fmaf(sacc[nb][2], SFC, -em1));
            float p3 = ex2f(fmaf(sacc[nb][3], SFC, -em1));
            sacc[nb][0] = p0; sacc[nb][1] = p1;
            sacc[nb][2] = p2; sacc[nb][3] = p3;
            s0 += p0 + p1; s1 += p2 + p3;
        }
        s0 += __shfl_xor_sync(0xffffffffu, s0, 1);
        s0 += __shfl_xor_sync(0xffffffffu, s0, 2);
        s1 += __shfl_xor_sync(0xffffffffu, s1, 1);
        s1 += __shfl_xor_sync(0xffffffffu, s1, 2);
        l0 = l0 * cr0 + s0;
        l1 = l1 * cr1 + s1;

#pragma unroll
        for (int nb = 0; nb < 8; ++nb) {
            oacc[nb][0] *= cr0; oacc[nb][1] *= cr0;
            oacc[nb][2] *= cr1; oacc[nb][3] *= cr1;
        }

        uint32_t pa[4][4], pl[4][4];
#pragma unroll
        for (int kb = 0; kb < 4; ++kb) {
            split2(sacc[2 * kb][0], sacc[2 * kb][1], pa[kb][0], pl[kb][0]);
            split2(sacc[2 * kb][2], sacc[2 * kb][3], pa[kb][1], pl[kb][1]);
            split2(sacc[2 * kb + 1][0], sacc[2 * kb + 1][1], pa[kb][2], pl[kb][2]);
            split2(sacc[2 * kb + 1][2], sacc[2 * kb + 1][3], pa[kb][3], pl[kb][3]);
        }

#pragma unroll
        for (int kb = 0; kb < 4; ++kb) {
            uint32_t vh[8][2], vl[8][2];
            const int vrow = kb * 16 + (lane & 7) + ((lane >> 3) & 1) * 8;
#pragma unroll
            for (int np = 0; np < 4; ++np) {
                const int vcol = np * 16 + ((lane >> 4) & 1) * 8;
                const uint32_t off = (uint32_t)(vrow * FPITCH + vcol) * 2;
                LDSM_X4_T(vh[2 * np][0], vh[2 * np][1], vh[2 * np + 1][0], vh[2 * np + 1][1],
                          sb + AV_HI + off);
                LDSM_X4_T(vl[2 * np][0], vl[2 * np][1], vl[2 * np + 1][0], vl[2 * np + 1][1],
                          sb + AV_LO + off);
            }
#pragma unroll
            for (int nb = 0; nb < 8; ++nb) MMA16816(oacc[nb], pa[kb], vh[nb]);
#pragma unroll
            for (int nb = 0; nb < 8; ++nb) MMA16816(oacc[nb], pa[kb], vl[nb]);
#pragma unroll
            for (int nb = 0; nb < 8; ++nb) MMA16816(oacc[nb], pl[kb], vh[nb]);
        }

        if (j < jmax) {
            CP_WAIT0();
            __syncthreads();
        }
    }

    const float inv0 = 1.0f / l0;
    const float inv1 = 1.0f / l1;
    const int row0 = qt * 64 + w * 16 + g;
#pragma unroll
    for (int nb = 0; nb < 8; ++nb) {
        const int col = nb * 8 + 2 * tq;
        uint32_t hi, lo;
        split2(oacc[nb][0] * inv0, oacc[nb][1] * inv0, hi, lo);
        const size_t g0 = rowbase + (size_t)row0 * PD + col;
        *(uint32_t*)(ohi + g0) = hi;
        *(uint32_t*)(olo + g0) = lo;
        split2(oacc[nb][2] * inv1, oacc[nb][3] * inv1, hi, lo);
        const size_t g1 = rowbase + (size_t)(row0 + 8) * PD + col;
        *(uint32_t*)(ohi + g1) = hi;
        *(uint32_t*)(olo + g1) = lo;
    }
}

// ---------------------------------------------------------------------------
extern "C" void kernel_launch(void* const* d_in, const int* in_sizes, int n_in,
                              void* d_out, int out_size)
{
    const float* Q    = (const float*)d_in[0];
    const float* K    = (const float*)d_in[1];
    const float* V    = (const float*)d_in[2];
    const float* Wq_w = (const float*)d_in[4];
    const float* Wq_b = (const float*)d_in[5];
    const float* Wk_w = (const float*)d_in[6];
    const float* Wk_b = (const float*)d_in[7];
    const float* Wv_w = (const float*)d_in[8];
    const float* Wv_b = (const float*)d_in[9];
    const float* fc_w = (const float*)d_in[10];
    const float* fc_b = (const float*)d_in[11];
    float* out = (float*)d_out;

    __nv_bfloat16 *xhi, *xlo, *whi, *wlo, *yhi, *ylo, *ahi, *alo;
    cudaGetSymbolAddress((void**)&xhi, g_xhi);
    cudaGetSymbolAddress((void**)&xlo, g_xlo);
    cudaGetSymbolAddress((void**)&whi, g_whi);
    cudaGetSymbolAddress((void**)&wlo, g_wlo);
    cudaGetSymbolAddress((void**)&yhi, g_yhi);
    cudaGetSymbolAddress((void**)&ylo, g_ylo);
    cudaGetSymbolAddress((void**)&ahi, g_ahi);
    cudaGetSymbolAddress((void**)&alo, g_alo);

    cudaFuncSetAttribute(gemm3_mma<true>,
                         cudaFuncAttributeMaxDynamicSharedMemorySize, G_SMEM);
    cudaFuncSetAttribute(gemm3_mma<false>,
                         cudaFuncAttributeMaxDynamicSharedMemorySize, G_SMEM);
    cudaFuncSetAttribute(flash_attn_mma,
                         cudaFuncAttributeMaxDynamicSharedMemorySize, ATT_SMEM);

    const int nA4 = MD / 4;
    const int nW4 = DD / 4;
    dim3 ggrid(PD / BGN, PM / BGM);   // (4, 32) = 128 CTAs, single wave

    // Splits (2 launches)
    split3_in<<<dim3(nA4 / 256, 1, 3), 256>>>(Q, K, V, xhi, xlo);
    split4_w<<<dim3(nW4 / 256, 1, 4), 256>>>(Wq_w, Wk_w, Wv_w, fc_w, whi, wlo);

    // Projections (single-wave launches)
    gemm3_mma<true><<<ggrid, 256, G_SMEM>>>(
        xhi, xlo, whi, wlo, Wq_b, nullptr, yhi, ylo, PD, PD);
    gemm3_mma<true><<<ggrid, 256, G_SMEM>>>(
        xhi + MD, xlo + MD, whi + DD, wlo + DD, Wk_b,
        nullptr, yhi + MD, ylo + MD, PD, PD);
    gemm3_mma<true><<<ggrid, 256, G_SMEM>>>(
        xhi + 2 * (size_t)MD, xlo + 2 * (size_t)MD,
        whi + 2 * (size_t)DD, wlo + 2 * (size_t)DD, Wv_b,
        nullptr, yhi + 2 * (size_t)MD, ylo + 2 * (size_t)MD, PD, PD);

    // Attention
    flash_attn_mma<<<dim3(PL / 64, PB * PH), 128, ATT_SMEM>>>(
        yhi, ylo, yhi + MD, ylo + MD, yhi + 2 * (size_t)MD, ylo + 2 * (size_t)MD,
        ahi, alo);

    // Output projection (fp32 out)
    gemm3_mma<false><<<ggrid, 256, G_SMEM>>>(
        ahi, alo, whi + 3 * (size_t)DD, wlo + 3 * (size_t)DD, fc_b,
        out, nullptr, nullptr, PD, PD);
}

// round 10
// speedup vs baseline: 1.2178x; 1.2178x over previous
#include <cuda_runtime.h>
#include <cuda_fp16.h>
#include <cstdint>
#include <math.h>

// Problem constants
#define PB 2
#define PL 2048
#define PD 1024
#define PH 16
#define PDK 64
#define PM (PB * PL)   // 4096
#define MD (PM * PD)
#define DD (PD * PD)

// Scratch (device globals), fp16
__device__ __half g_xhi[3 * MD];   // Q,K,V input splits (hi)
__device__ __half g_xlo[3 * MD];   //                    (lo)
__device__ __half g_wh[4 * DD];    // Wq,Wk,Wv,fc weights (hi only)
__device__ __half g_yhi[3 * MD];   // q,k,v projections (hi)
__device__ __half g_ylo[3 * MD];   //                   (lo)
__device__ __half g_ahi[MD];       // attention output (hi)
__device__ __half g_alo[MD];       //                  (lo)

// ---------------------------------------------------------------------------
// PTX helpers
// ---------------------------------------------------------------------------
__device__ __forceinline__ uint32_t smem_u32(const void* p) {
    uint32_t a;
    asm("{ .reg .u64 t; cvta.to.shared.u64 t, %1; cvt.u32.u64 %0, t; }"
        : "=r"(a) : "l"(p));
    return a;
}

#define MMA16816(c, a, b) \
    asm volatile("mma.sync.aligned.m16n8k16.row.col.f32.f16.f16.f32 " \
        "{%0,%1,%2,%3}, {%4,%5,%6,%7}, {%8,%9}, {%0,%1,%2,%3};" \
        : "+f"((c)[0]), "+f"((c)[1]), "+f"((c)[2]), "+f"((c)[3]) \
        : "r"((a)[0]), "r"((a)[1]), "r"((a)[2]), "r"((a)[3]), \
          "r"((b)[0]), "r"((b)[1]))

#define LDSM_X4(r0, r1, r2, r3, addr) \
    asm volatile("ldmatrix.sync.aligned.m8n8.x4.shared.b16 {%0,%1,%2,%3}, [%4];" \
        : "=r"(r0), "=r"(r1), "=r"(r2), "=r"(r3) : "r"(addr))

#define LDSM_X4_T(r0, r1, r2, r3, addr) \
    asm volatile("ldmatrix.sync.aligned.m8n8.x4.trans.shared.b16 {%0,%1,%2,%3}, [%4];" \
        : "=r"(r0), "=r"(r1), "=r"(r2), "=r"(r3) : "r"(addr))

#define CP_ASYNC16(smem, gptr) \
    asm volatile("cp.async.cg.shared.global [%0], [%1], 16;" \
        :: "r"(smem), "l"(gptr))
#define CP_COMMIT() asm volatile("cp.async.commit_group;" ::: "memory")
#define CP_WAIT0()  asm volatile("cp.async.wait_group 0;" ::: "memory")
#define CP_WAIT1()  asm volatile("cp.async.wait_group 1;" ::: "memory")

__device__ __forceinline__ float ex2f(float x) {
    float r;
    asm("ex2.approx.f32 %0, %1;" : "=f"(r) : "f"(x));
    return r;
}

// split two floats into packed fp16x2 hi and residual lo (error ~2^-22)
__device__ __forceinline__ void split2h(float a, float b, uint32_t& hi, uint32_t& lo) {
    __half ha = __float2half_rn(a);
    __half hb = __float2half_rn(b);
    float ra = a - __half2float(ha);
    float rb = b - __half2float(hb);
    __half2 H = __halves2half2(ha, hb);
    __half2 L = __halves2half2(__float2half_rn(ra), __float2half_rn(rb));
    hi = *reinterpret_cast<uint32_t*>(&H);
    lo = *reinterpret_cast<uint32_t*>(&L);
}

// ---------------------------------------------------------------------------
// Splits
// ---------------------------------------------------------------------------
__global__ __launch_bounds__(256) void split3_in(
    const float* __restrict__ x0, const float* __restrict__ x1,
    const float* __restrict__ x2,
    __half* hi, __half* lo)
{
    const int i = blockIdx.x * 256 + threadIdx.x;
    const int z = blockIdx.z;
    const float* x = (z == 0) ? x0 : (z == 1) ? x1 : x2;
    float4 v = reinterpret_cast<const float4*>(x)[i];
    uint32_t h0, l0, h1, l1;
    split2h(v.x, v.y, h0, l0);
    split2h(v.z, v.w, h1, l1);
    reinterpret_cast<uint2*>(hi + (size_t)z * MD)[i] = make_uint2(h0, h1);
    reinterpret_cast<uint2*>(lo + (size_t)z * MD)[i] = make_uint2(l0, l1);
}

__global__ __launch_bounds__(256) void split4_wh(
    const float* __restrict__ x0, const float* __restrict__ x1,
    const float* __restrict__ x2, const float* __restrict__ x3,
    __half* wh)
{
    const int i = blockIdx.x * 256 + threadIdx.x;
    const int z = blockIdx.z;
    const float* x = (z == 0) ? x0 : (z == 1) ? x1 : (z == 2) ? x2 : x3;
    float4 v = reinterpret_cast<const float4*>(x)[i];
    __half2 a = __halves2half2(__float2half_rn(v.x), __float2half_rn(v.y));
    __half2 b = __halves2half2(__float2half_rn(v.z), __float2half_rn(v.w));
    reinterpret_cast<uint2*>(wh + (size_t)z * DD)[i] =
        make_uint2(*reinterpret_cast<uint32_t*>(&a),
                   *reinterpret_cast<uint32_t*>(&b));
}

// ---------------------------------------------------------------------------
// mma.sync fp16 GEMM (2-pass split-A): C = (Ahi+Alo) @ Wh^T + bias
// 128x256x32 tiles, 256 threads (2m x 4n warps), 3-stage cp.async.
// ---------------------------------------------------------------------------
#define BGM 128
#define BGN 256
#define BGK 32
#define GP 40                             // smem pitch (fp16)
#define A_T (BGM * GP * 2)                // 10240 B
#define B_T (BGN * GP * 2)                // 20480 B
#define OFF_A_HI 0
#define OFF_A_LO A_T
#define OFF_B    (2 * A_T)
#define STG_B (2 * A_T + B_T)             // 40960 B
#define NST 3
#define G_SMEM (NST * STG_B)              // 122880 B

template <bool SPLIT>
__global__ __launch_bounds__(256, 1) void gemm2_mma(
    const __half* __restrict__ Ahi, const __half* __restrict__ Alo,
    const __half* __restrict__ Wh,
    const float* __restrict__ bias, float* __restrict__ C,
    __half* __restrict__ Chi, __half* __restrict__ Clo,
    int K, int N)
{
    extern __shared__ char dsm[];
    __shared__ float sbias[BGN];

    const int tid = threadIdx.x;
    const int w = tid >> 5;
    const int lane = tid & 31;
    const int wm = w >> 2;
    const int wn = w & 3;
    const int g = lane >> 2;
    const int tq = lane & 3;
    const int bm = blockIdx.y * BGM;
    const int bn = blockIdx.x * BGN;
    const uint32_t sbase = smem_u32(dsm);

    const int lr = tid >> 2;              // 0..63
    const int lc = (tid & 3) * 8;         // 0,8,16,24

    auto issue = [&](int c, int buf) {
        const uint32_t sb = sbase + buf * STG_B;
        const int kofs = c * BGK;
#pragma unroll
        for (int it = 0; it < 2; ++it) {
            const int r = lr + it * 64;
            const uint32_t so = (uint32_t)(r * GP + lc) * 2;
            const size_t go = (size_t)(bm + r) * K + kofs + lc;
            CP_ASYNC16(sb + OFF_A_HI + so, (const char*)(Ahi + go));
            CP_ASYNC16(sb + OFF_A_LO + so, (const char*)(Alo + go));
        }
#pragma unroll
        for (int it = 0; it < 4; ++it) {
            const int r = lr + it * 64;
            const uint32_t so = (uint32_t)(r * GP + lc) * 2;
            const size_t go = (size_t)(bn + r) * K + kofs + lc;
            CP_ASYNC16(sb + OFF_B + so, (const char*)(Wh + go));
        }
    };

    issue(0, 0); CP_COMMIT();
    issue(1, 1); CP_COMMIT();

    sbias[tid] = bias[bn + tid];

    float acc[4][8][4];
#pragma unroll
    for (int mi = 0; mi < 4; ++mi)
#pragma unroll
        for (int nb = 0; nb < 8; ++nb)
#pragma unroll
            for (int e = 0; e < 4; ++e) acc[mi][nb][e] = 0.0f;

    const int a_r = (lane & 7) + ((lane >> 3) & 1) * 8;
    const int a_c = ((lane >> 4) & 1) * 8;
    const int b_r = (lane & 7) + ((lane >> 4) & 1) * 8;
    const int b_c = ((lane >> 3) & 1) * 8;

    const int nchunk = K / BGK;   // 32
    for (int c = 0; c < nchunk; ++c) {
        if (c + 1 < nchunk) CP_WAIT1(); else CP_WAIT0();
        __syncthreads();
        if (c + 2 < nchunk) { issue(c + 2, (c + 2) % NST); CP_COMMIT(); }

        const uint32_t sb = sbase + (c % NST) * STG_B;
#pragma unroll
        for (int kk = 0; kk < 2; ++kk) {
            uint32_t ah[4][4], al[4][4];
#pragma unroll
            for (int mi = 0; mi < 4; ++mi) {
                const uint32_t off =
                    (uint32_t)((wm * 64 + mi * 16 + a_r) * GP + kk * 16 + a_c) * 2;
                LDSM_X4(ah[mi][0], ah[mi][1], ah[mi][2], ah[mi][3],
                        sb + OFF_A_HI + off);
                LDSM_X4(al[mi][0], al[mi][1], al[mi][2], al[mi][3],
                        sb + OFF_A_LO + off);
            }
            uint32_t bh[8][2];
#pragma unroll
            for (int np = 0; np < 4; ++np) {
                const uint32_t off =
                    (uint32_t)((wn * 64 + np * 16 + b_r) * GP + kk * 16 + b_c) * 2;
                LDSM_X4(bh[2 * np][0], bh[2 * np][1], bh[2 * np + 1][0], bh[2 * np + 1][1],
                        sb + OFF_B + off);
            }
#pragma unroll
            for (int mi = 0; mi < 4; ++mi)
#pragma unroll
                for (int nb = 0; nb < 8; ++nb) {
                    MMA16816(acc[mi][nb], ah[mi], bh[nb]);
                    MMA16816(acc[mi][nb], al[mi], bh[nb]);
                }
        }
    }

    // epilogue: bias add + direct store from registers
#pragma unroll
    for (int mi = 0; mi < 4; ++mi) {
        const int row0 = bm + wm * 64 + mi * 16 + g;
        const int row1 = row0 + 8;
#pragma unroll
        for (int nb = 0; nb < 8; ++nb) {
            const int coll = wn * 64 + nb * 8 + 2 * tq;
            const float b0 = sbias[coll];
            const float b1 = sbias[coll + 1];
            const float v0 = acc[mi][nb][0] + b0;
            const float v1 = acc[mi][nb][1] + b1;
            const float v2 = acc[mi][nb][2] + b0;
            const float v3 = acc[mi][nb][3] + b1;
            const size_t o0 = (size_t)row0 * N + bn + coll;
            const size_t o1 = (size_t)row1 * N + bn + coll;
            if (SPLIT) {
                uint32_t hi, lo;
                split2h(v0, v1, hi, lo);
                *(uint32_t*)(Chi + o0) = hi;
                *(uint32_t*)(Clo + o0) = lo;
                split2h(v2, v3, hi, lo);
                *(uint32_t*)(Chi + o1) = hi;
                *(uint32_t*)(Clo + o1) = lo;
            } else {
                *(float2*)(C + o0) = make_float2(v0, v1);
                *(float2*)(C + o1) = make_float2(v2, v3);
            }
        }
    }
}

// ---------------------------------------------------------------------------
// Register-resident FA2 on mma.sync — fp16 3-term, 64-row q-tiles,
// 128 threads (4 warps), occupancy 2, heavy CTAs first.
// ---------------------------------------------------------------------------
#define FPITCH 72
#define AQ_HI 0
#define AQ_LO 9216
#define AKV   18432
#define KV_STAGE 36864
#define AK_HI 0
#define AK_LO 9216
#define AV_HI 18432
#define AV_LO 27648
#define ATT_SMEM (AKV + 2 * KV_STAGE)     // 92160

#define SFC 0.18033688f                   // 0.125 * log2(e)

__global__ __launch_bounds__(128, 2) void flash_attn_mma(
    const __half* __restrict__ qhi, const __half* __restrict__ qlo,
    const __half* __restrict__ khi, const __half* __restrict__ klo,
    const __half* __restrict__ vhi, const __half* __restrict__ vlo,
    __half* __restrict__ ohi, __half* __restrict__ olo)
{
    extern __shared__ char dsm[];
    const int tid = threadIdx.x;
    const int w = tid >> 5;
    const int lane = tid & 31;
    const int g = lane >> 2;
    const int tq = lane & 3;
    const int qt = (int)(gridDim.x - 1) - (int)blockIdx.x;
    const int b = blockIdx.y >> 4;
    const int h = blockIdx.y & 15;
    const size_t rowbase = (size_t)b * PL * PD + (size_t)h * PDK;

    const uint32_t sQh = smem_u32(dsm + AQ_HI);
    const uint32_t sQl = smem_u32(dsm + AQ_LO);
    const uint32_t sKV = smem_u32(dsm + AKV);

    const int kr0 = tid >> 3;
    const int kc0 = (tid & 7) * 8;

    {
        const uint32_t sb = sKV;
#pragma unroll
        for (int it = 0; it < 4; ++it) {
            const int r = kr0 + it * 16;
            const uint32_t so = (uint32_t)(r * FPITCH + kc0) * 2;
            const size_t go = rowbase + (size_t)r * PD + kc0;
            CP_ASYNC16(sb + AK_HI + so, (const char*)(khi + go));
            CP_ASYNC16(sb + AK_LO + so, (const char*)(klo + go));
            CP_ASYNC16(sb + AV_HI + so, (const char*)(vhi + go));
            CP_ASYNC16(sb + AV_LO + so, (const char*)(vlo + go));
        }
        CP_COMMIT();
    }

#pragma unroll
    for (int it = 0; it < 4; ++it) {
        const int idx = tid + it * 128;
        const int r = idx >> 3;
        const int c = (idx & 7) * 8;
        const size_t go = rowbase + (size_t)(qt * 64 + r) * PD + c;
        const uint32_t so = (uint32_t)(r * FPITCH + c) * 2;
        *(uint4*)(dsm + AQ_HI + so) = *(const uint4*)(qhi + go);
        *(uint4*)(dsm + AQ_LO + so) = *(const uint4*)(qlo + go);
    }
    CP_WAIT0();
    __syncthreads();

    uint32_t qh[4][4], ql[4][4];
    {
        const int row = w * 16 + (lane & 7) + ((lane >> 3) & 1) * 8;
#pragma unroll
        for (int kb = 0; kb < 4; ++kb) {
            const int col = kb * 16 + ((lane >> 4) & 1) * 8;
            const uint32_t off = (uint32_t)(row * FPITCH + col) * 2;
            LDSM_X4(qh[kb][0], qh[kb][1], qh[kb][2], qh[kb][3], sQh + off);
            LDSM_X4(ql[kb][0], ql[kb][1], ql[kb][2], ql[kb][3], sQl + off);
        }
    }

    float oacc[8][4];
#pragma unroll
    for (int nb = 0; nb < 8; ++nb)
#pragma unroll
        for (int e = 0; e < 4; ++e) oacc[nb][e] = 0.0f;
    float m0 = -1.0e30f, m1 = -1.0e30f, l0 = 0.0f, l1 = 0.0f;

    const int jmax = qt;
    for (int j = 0; j <= jmax; ++j) {
        const int buf = j & 1;
        const uint32_t sb = sKV + buf * KV_STAGE;

        if (j < jmax) {
            const uint32_t nb_ = sKV + (buf ^ 1) * KV_STAGE;
#pragma unroll
            for (int it = 0; it < 4; ++it) {
                const int r = kr0 + it * 16;
                const uint32_t so = (uint32_t)(r * FPITCH + kc0) * 2;
                const size_t go = rowbase + (size_t)((j + 1) * 64 + r) * PD + kc0;
                CP_ASYNC16(nb_ + AK_HI + so, (const char*)(khi + go));
                CP_ASYNC16(nb_ + AK_LO + so, (const char*)(klo + go));
                CP_ASYNC16(nb_ + AV_HI + so, (const char*)(vhi + go));
                CP_ASYNC16(nb_ + AV_LO + so, (const char*)(vlo + go));
            }
            CP_COMMIT();
        }

        float sacc[8][4];
#pragma unroll
        for (int nb = 0; nb < 8; ++nb)
#pragma unroll
            for (int e = 0; e < 4; ++e) sacc[nb][e] = 0.0f;

#pragma unroll
        for (int kb = 0; kb < 4; ++kb) {
            uint32_t kh[8][2], kl[8][2];
            const int kcol = kb * 16 + ((lane >> 3) & 1) * 8;
#pragma unroll
            for (int np = 0; np < 4; ++np) {
                const int krow = np * 16 + (lane & 7) + ((lane >> 4) & 1) * 8;
                const uint32_t off = (uint32_t)(krow * FPITCH + kcol) * 2;
                LDSM_X4(kh[2 * np][0], kh[2 * np][1], kh[2 * np + 1][0], kh[2 * np + 1][1],
                        sb + AK_HI + off);
                LDSM_X4(kl[2 * np][0], kl[2 * np][1], kl[2 * np + 1][0], kl[2 * np + 1][1],
                        sb + AK_LO + off);
            }
#pragma unroll
            for (int nb = 0; nb < 8; ++nb) {
                MMA16816(sacc[nb], qh[kb], kh[nb]);
                MMA16816(sacc[nb], qh[kb], kl[nb]);
                MMA16816(sacc[nb], ql[kb], kh[nb]);
            }
        }

        if (j == qt) {
            const int row0 = qt * 64 + w * 16 + g;
            const int row1 = row0 + 8;
            const int cb = j * 64 + 2 * tq;
#pragma unroll
            for (int nb = 0; nb < 8; ++nb) {
                const int c0 = cb + nb * 8, c1 = c0 + 1;
                if (c0 > row0) sacc[nb][0] = -1.0e30f;
                if (c1 > row0) sacc[nb][1] = -1.0e30f;
                if (c0 > row1) sacc[nb][2] = -1.0e30f;
                if (c1 > row1) sacc[nb][3] = -1.0e30f;
            }
        }

        float mx0 = -1.0e30f, mx1 = -1.0e30f;
#pragma unroll
        for (int nb = 0; nb < 8; ++nb) {
            mx0 = fmaxf(mx0, fmaxf(sacc[nb][0], sacc[nb][1]));
            mx1 = fmaxf(mx1, fmaxf(sacc[nb][2], sacc[nb][3]));
        }
        mx0 = fmaxf(mx0, __shfl_xor_sync(0xffffffffu, mx0, 1));
        mx0 = fmaxf(mx0, __shfl_xor_sync(0xffffffffu, mx0, 2));
        mx1 = fmaxf(mx1, __shfl_xor_sync(0xffffffffu, mx1, 1));
        mx1 = fmaxf(mx1, __shfl_xor_sync(0xffffffffu, mx1, 2));

        const float mn0 = fmaxf(m0, mx0);
        const float mn1 = fmaxf(m1, mx1);
        const float em0 = mn0 * SFC;
        const float em1 = mn1 * SFC;
        const float cr0 = ex2f((m0 - mn0) * SFC);
        const float cr1 = ex2f((m1 - mn1) * SFC);
        m0 = mn0; m1 = mn1;

        float s0 = 0.0f, s1 = 0.0f;
#pragma unroll
        for (int nb = 0; nb < 8; ++nb) {
            float p0 = ex2f(fmaf(sacc[nb][0], SFC, -em0));
            float p1 = ex2f(fmaf(sacc[nb][1], SFC, -em0));
            float p2 = ex2f(fmaf(sacc[nb][2], SFC, -em1));
            float p3 = ex2f(fmaf(sacc[nb][3], SFC, -em1));
            sacc[nb][0] = p0; sacc[nb][1] = p1;
            sacc[nb][2] = p2; sacc[nb][3] = p3;
            s0 += p0 + p1; s1 += p2 + p3;
        }
        s0 += __shfl_xor_sync(0xffffffffu, s0, 1);
        s0 += __shfl_xor_sync(0xffffffffu, s0, 2);
        s1 += __shfl_xor_sync(0xffffffffu, s1, 1);
        s1 += __shfl_xor_sync(0xffffffffu, s1, 2);
        l0 = l0 * cr0 + s0;
        l1 = l1 * cr1 + s1;

#pragma unroll
        for (int nb = 0; nb < 8; ++nb) {
            oacc[nb][0] *= cr0; oacc[nb][1] *= cr0;
            oacc[nb][2] *= cr1; oacc[nb][3] *= cr1;
        }

        uint32_t pa[4][4], pl[4][4];
#pragma unroll
        for (int kb = 0; kb < 4; ++kb) {
            split2h(sacc[2 * kb][0], sacc[2 * kb][1], pa[kb][0], pl[kb][0]);
            split2h(sacc[2 * kb][2], sacc[2 * kb][3], pa[kb][1], pl[kb][1]);
            split2h(sacc[2 * kb + 1][0], sacc[2 * kb + 1][1], pa[kb][2], pl[kb][2]);
            split2h(sacc[2 * kb + 1][2], sacc[2 * kb + 1][3], pa[kb][3], pl[kb][3]);
        }

#pragma unroll
        for (int kb = 0; kb < 4; ++kb) {
            uint32_t vh[8][2], vl[8][2];
            const int vrow = kb * 16 + (lane & 7) + ((lane >> 3) & 1) * 8;
#pragma unroll
            for (int np = 0; np < 4; ++np) {
                const int vcol = np * 16 + ((lane >> 4) & 1) * 8;
                const uint32_t off = (uint32_t)(vrow * FPITCH + vcol) * 2;
                LDSM_X4_T(vh[2 * np][0], vh[2 * np][1], vh[2 * np + 1][0], vh[2 * np + 1][1],
                          sb + AV_HI + off);
                LDSM_X4_T(vl[2 * np][0], vl[2 * np][1], vl[2 * np + 1][0], vl[2 * np + 1][1],
                          sb + AV_LO + off);
            }
#pragma unroll
            for (int nb = 0; nb < 8; ++nb) {
                MMA16816(oacc[nb], pa[kb], vh[nb]);
                MMA16816(oacc[nb], pa[kb], vl[nb]);
                MMA16816(oacc[nb], pl[kb], vh[nb]);
            }
        }

        if (j < jmax) {
            CP_WAIT0();
            __syncthreads();
        }
    }

    const float inv0 = 1.0f / l0;
    const float inv1 = 1.0f / l1;
    const int row0 = qt * 64 + w * 16 + g;
#pragma unroll
    for (int nb = 0; nb < 8; ++nb) {
        const int col = nb * 8 + 2 * tq;
        uint32_t hi, lo;
        split2h(oacc[nb][0] * inv0, oacc[nb][1] * inv0, hi, lo);
        const size_t g0 = rowbase + (size_t)row0 * PD + col;
        *(uint32_t*)(ohi + g0) = hi;
        *(uint32_t*)(olo + g0) = lo;
        split2h(oacc[nb][2] * inv1, oacc[nb][3] * inv1, hi, lo);
        const size_t g1 = rowbase + (size_t)(row0 + 8) * PD + col;
        *(uint32_t*)(ohi + g1) = hi;
        *(uint32_t*)(olo + g1) = lo;
    }
}

// ---------------------------------------------------------------------------
extern "C" void kernel_launch(void* const* d_in, const int* in_sizes, int n_in,
                              void* d_out, int out_size)
{
    const float* Q    = (const float*)d_in[0];
    const float* K    = (const float*)d_in[1];
    const float* V    = (const float*)d_in[2];
    const float* Wq_w = (const float*)d_in[4];
    const float* Wq_b = (const float*)d_in[5];
    const float* Wk_w = (const float*)d_in[6];
    const float* Wk_b = (const float*)d_in[7];
    const float* Wv_w = (const float*)d_in[8];
    const float* Wv_b = (const float*)d_in[9];
    const float* fc_w = (const float*)d_in[10];
    const float* fc_b = (const float*)d_in[11];
    float* out = (float*)d_out;

    __half *xhi, *xlo, *wh, *yhi, *ylo, *ahi, *alo;
    cudaGetSymbolAddress((void**)&xhi, g_xhi);
    cudaGetSymbolAddress((void**)&xlo, g_xlo);
    cudaGetSymbolAddress((void**)&wh, g_wh);
    cudaGetSymbolAddress((void**)&yhi, g_yhi);
    cudaGetSymbolAddress((void**)&ylo, g_ylo);
    cudaGetSymbolAddress((void**)&ahi, g_ahi);
    cudaGetSymbolAddress((void**)&alo, g_alo);

    cudaFuncSetAttribute(gemm2_mma<true>,
                         cudaFuncAttributeMaxDynamicSharedMemorySize, G_SMEM);
    cudaFuncSetAttribute(gemm2_mma<false>,
                         cudaFuncAttributeMaxDynamicSharedMemorySize, G_SMEM);
    cudaFuncSetAttribute(flash_attn_mma,
                         cudaFuncAttributeMaxDynamicSharedMemorySize, ATT_SMEM);

    const int nA4 = MD / 4;
    const int nW4 = DD / 4;
    dim3 ggrid(PD / BGN, PM / BGM);   // (4, 32) = 128 CTAs, single wave

    // Splits (2 launches)
    split3_in<<<dim3(nA4 / 256, 1, 3), 256>>>(Q, K, V, xhi, xlo);
    split4_wh<<<dim3(nW4 / 256, 1, 4), 256>>>(Wq_w, Wk_w, Wv_w, fc_w, wh);

    // Projections (single-wave launches, 2-pass fp16)
    gemm2_mma<true><<<ggrid, 256, G_SMEM>>>(
        xhi, xlo, wh, Wq_b, nullptr, yhi, ylo, PD, PD);
    gemm2_mma<true><<<ggrid, 256, G_SMEM>>>(
        xhi + MD, xlo + MD, wh + DD, Wk_b,
        nullptr, yhi + MD, ylo + MD, PD, PD);
    gemm2_mma<true><<<ggrid, 256, G_SMEM>>>(
        xhi + 2 * (size_t)MD, xlo + 2 * (size_t)MD, wh + 2 * (size_t)DD, Wv_b,
        nullptr, yhi + 2 * (size_t)MD, ylo + 2 * (size_t)MD, PD, PD);

    // Attention (fp16 3-term)
    flash_attn_mma<<<dim3(PL / 64, PB * PH), 128, ATT_SMEM>>>(
        yhi, ylo, yhi + MD, ylo + MD, yhi + 2 * (size_t)MD, ylo + 2 * (size_t)MD,
        ahi, alo);

    // Output projection (fp32 out, 2-pass fp16)
    gemm2_mma<false><<<ggrid, 256, G_SMEM>>>(
        ahi, alo, wh + 3 * (size_t)DD, fc_b,
        out, nullptr, nullptr, PD, PD);
}

// round 11
// speedup vs baseline: 1.4116x; 1.1592x over previous
#include <cuda_runtime.h>
#include <cuda_fp16.h>
#include <cstdint>
#include <math.h>

// Problem constants
#define PB 2
#define PL 2048
#define PD 1024
#define PH 16
#define PDK 64
#define PM (PB * PL)   // 4096
#define MD (PM * PD)
#define DD (PD * PD)

// Scratch (device globals), fp16
__device__ __half g_xhi[3 * MD];   // Q,K,V input splits (hi)
__device__ __half g_xlo[3 * MD];   //                    (lo)
__device__ __half g_wh[4 * DD];    // Wq,Wk,Wv,fc weights (hi only)
__device__ __half g_qhi[MD];       // q projection hi
__device__ __half g_qlo[MD];       // q projection lo
__device__ __half g_kh[MD];        // k projection (hi only)
__device__ __half g_vh[MD];        // v projection (hi only)
__device__ __half g_ahi[MD];       // attention output (hi)
__device__ __half g_alo[MD];       //                  (lo)

// ---------------------------------------------------------------------------
// PTX helpers
// ---------------------------------------------------------------------------
__device__ __forceinline__ uint32_t smem_u32(const void* p) {
    uint32_t a;
    asm("{ .reg .u64 t; cvta.to.shared.u64 t, %1; cvt.u32.u64 %0, t; }"
        : "=r"(a) : "l"(p));
    return a;
}

#define MMA16816(c, a, b) \
    asm volatile("mma.sync.aligned.m16n8k16.row.col.f32.f16.f16.f32 " \
        "{%0,%1,%2,%3}, {%4,%5,%6,%7}, {%8,%9}, {%0,%1,%2,%3};" \
        : "+f"((c)[0]), "+f"((c)[1]), "+f"((c)[2]), "+f"((c)[3]) \
        : "r"((a)[0]), "r"((a)[1]), "r"((a)[2]), "r"((a)[3]), \
          "r"((b)[0]), "r"((b)[1]))

#define LDSM_X4(r0, r1, r2, r3, addr) \
    asm volatile("ldmatrix.sync.aligned.m8n8.x4.shared.b16 {%0,%1,%2,%3}, [%4];" \
        : "=r"(r0), "=r"(r1), "=r"(r2), "=r"(r3) : "r"(addr))

#define LDSM_X4_T(r0, r1, r2, r3, addr) \
    asm volatile("ldmatrix.sync.aligned.m8n8.x4.trans.shared.b16 {%0,%1,%2,%3}, [%4];" \
        : "=r"(r0), "=r"(r1), "=r"(r2), "=r"(r3) : "r"(addr))

#define CP_ASYNC16(smem, gptr) \
    asm volatile("cp.async.cg.shared.global [%0], [%1], 16;" \
        :: "r"(smem), "l"(gptr))
#define CP_COMMIT() asm volatile("cp.async.commit_group;" ::: "memory")
#define CP_WAIT0()  asm volatile("cp.async.wait_group 0;" ::: "memory")
#define CP_WAIT1()  asm volatile("cp.async.wait_group 1;" ::: "memory")

__device__ __forceinline__ float ex2f(float x) {
    float r;
    asm("ex2.approx.f32 %0, %1;" : "=f"(r) : "f"(x));
    return r;
}

// split two floats into packed fp16x2 hi and residual lo
__device__ __forceinline__ void split2h(float a, float b, uint32_t& hi, uint32_t& lo) {
    __half ha = __float2half_rn(a);
    __half hb = __float2half_rn(b);
    float ra = a - __half2float(ha);
    float rb = b - __half2float(hb);
    __half2 H = __halves2half2(ha, hb);
    __half2 L = __halves2half2(__float2half_rn(ra), __float2half_rn(rb));
    hi = *reinterpret_cast<uint32_t*>(&H);
    lo = *reinterpret_cast<uint32_t*>(&L);
}

__device__ __forceinline__ uint32_t pack2h(float a, float b) {
    __half2 H = __halves2half2(__float2half_rn(a), __float2half_rn(b));
    return *reinterpret_cast<uint32_t*>(&H);
}

// ---------------------------------------------------------------------------
// Splits
// ---------------------------------------------------------------------------
__global__ __launch_bounds__(256) void split3_in(
    const float* __restrict__ x0, const float* __restrict__ x1,
    const float* __restrict__ x2,
    __half* hi, __half* lo)
{
    const int i = blockIdx.x * 256 + threadIdx.x;
    const int z = blockIdx.z;
    const float* x = (z == 0) ? x0 : (z == 1) ? x1 : x2;
    float4 v = reinterpret_cast<const float4*>(x)[i];
    uint32_t h0, l0, h1, l1;
    split2h(v.x, v.y, h0, l0);
    split2h(v.z, v.w, h1, l1);
    reinterpret_cast<uint2*>(hi + (size_t)z * MD)[i] = make_uint2(h0, h1);
    reinterpret_cast<uint2*>(lo + (size_t)z * MD)[i] = make_uint2(l0, l1);
}

__global__ __launch_bounds__(256) void split4_wh(
    const float* __restrict__ x0, const float* __restrict__ x1,
    const float* __restrict__ x2, const float* __restrict__ x3,
    __half* wh)
{
    const int i = blockIdx.x * 256 + threadIdx.x;
    const int z = blockIdx.z;
    const float* x = (z == 0) ? x0 : (z == 1) ? x1 : (z == 2) ? x2 : x3;
    float4 v = reinterpret_cast<const float4*>(x)[i];
    reinterpret_cast<uint2*>(wh + (size_t)z * DD)[i] =
        make_uint2(pack2h(v.x, v.y), pack2h(v.z, v.w));
}

// ---------------------------------------------------------------------------
// mma.sync fp16 GEMM (2-pass split-A): C = (Ahi+Alo) @ Wh^T + bias
// OUT_MODE: 0 = fp32, 1 = fp16 hi+lo pair, 2 = fp16 hi only.
// 128x256x32 tiles, 256 threads (2m x 4n warps), 3-stage cp.async.
// ---------------------------------------------------------------------------
#define BGM 128
#define BGN 256
#define BGK 32
#define GP 40
#define A_T (BGM * GP * 2)                // 10240 B
#define B_T (BGN * GP * 2)                // 20480 B
#define OFF_A_HI 0
#define OFF_A_LO A_T
#define OFF_B    (2 * A_T)
#define STG_B (2 * A_T + B_T)             // 40960 B
#define NST 3
#define G_SMEM (NST * STG_B)              // 122880 B

template <int OUT_MODE>
__global__ __launch_bounds__(256, 1) void gemm2_mma(
    const __half* __restrict__ Ahi, const __half* __restrict__ Alo,
    const __half* __restrict__ Wh,
    const float* __restrict__ bias, float* __restrict__ C,
    __half* __restrict__ Chi, __half* __restrict__ Clo,
    int K, int N)
{
    extern __shared__ char dsm[];
    __shared__ float sbias[BGN];

    const int tid = threadIdx.x;
    const int w = tid >> 5;
    const int lane = tid & 31;
    const int wm = w >> 2;
    const int wn = w & 3;
    const int g = lane >> 2;
    const int tq = lane & 3;
    const int bm = blockIdx.y * BGM;
    const int bn = blockIdx.x * BGN;
    const uint32_t sbase = smem_u32(dsm);

    const int lr = tid >> 2;
    const int lc = (tid & 3) * 8;

    auto issue = [&](int c, int buf) {
        const uint32_t sb = sbase + buf * STG_B;
        const int kofs = c * BGK;
#pragma unroll
        for (int it = 0; it < 2; ++it) {
            const int r = lr + it * 64;
            const uint32_t so = (uint32_t)(r * GP + lc) * 2;
            const size_t go = (size_t)(bm + r) * K + kofs + lc;
            CP_ASYNC16(sb + OFF_A_HI + so, (const char*)(Ahi + go));
            CP_ASYNC16(sb + OFF_A_LO + so, (const char*)(Alo + go));
        }
#pragma unroll
        for (int it = 0; it < 4; ++it) {
            const int r = lr + it * 64;
            const uint32_t so = (uint32_t)(r * GP + lc) * 2;
            const size_t go = (size_t)(bn + r) * K + kofs + lc;
            CP_ASYNC16(sb + OFF_B + so, (const char*)(Wh + go));
        }
    };

    issue(0, 0); CP_COMMIT();
    issue(1, 1); CP_COMMIT();

    sbias[tid] = bias[bn + tid];

    float acc[4][8][4];
#pragma unroll
    for (int mi = 0; mi < 4; ++mi)
#pragma unroll
        for (int nb = 0; nb < 8; ++nb)
#pragma unroll
            for (int e = 0; e < 4; ++e) acc[mi][nb][e] = 0.0f;

    const int a_r = (lane & 7) + ((lane >> 3) & 1) * 8;
    const int a_c = ((lane >> 4) & 1) * 8;
    const int b_r = (lane & 7) + ((lane >> 4) & 1) * 8;
    const int b_c = ((lane >> 3) & 1) * 8;

    const int nchunk = K / BGK;   // 32
    for (int c = 0; c < nchunk; ++c) {
        if (c + 1 < nchunk) CP_WAIT1(); else CP_WAIT0();
        __syncthreads();
        if (c + 2 < nchunk) { issue(c + 2, (c + 2) % NST); CP_COMMIT(); }

        const uint32_t sb = sbase + (c % NST) * STG_B;
#pragma unroll
        for (int kk = 0; kk < 2; ++kk) {
            uint32_t ah[4][4], al[4][4];
#pragma unroll
            for (int mi = 0; mi < 4; ++mi) {
                const uint32_t off =
                    (uint32_t)((wm * 64 + mi * 16 + a_r) * GP + kk * 16 + a_c) * 2;
                LDSM_X4(ah[mi][0], ah[mi][1], ah[mi][2], ah[mi][3],
                        sb + OFF_A_HI + off);
                LDSM_X4(al[mi][0], al[mi][1], al[mi][2], al[mi][3],
                        sb + OFF_A_LO + off);
            }
            uint32_t bh[8][2];
#pragma unroll
            for (int np = 0; np < 4; ++np) {
                const uint32_t off =
                    (uint32_t)((wn * 64 + np * 16 + b_r) * GP + kk * 16 + b_c) * 2;
                LDSM_X4(bh[2 * np][0], bh[2 * np][1], bh[2 * np + 1][0], bh[2 * np + 1][1],
                        sb + OFF_B + off);
            }
#pragma unroll
            for (int mi = 0; mi < 4; ++mi)
#pragma unroll
                for (int nb = 0; nb < 8; ++nb) {
                    MMA16816(acc[mi][nb], ah[mi], bh[nb]);
                    MMA16816(acc[mi][nb], al[mi], bh[nb]);
                }
        }
    }

    // epilogue
#pragma unroll
    for (int mi = 0; mi < 4; ++mi) {
        const int row0 = bm + wm * 64 + mi * 16 + g;
        const int row1 = row0 + 8;
#pragma unroll
        for (int nb = 0; nb < 8; ++nb) {
            const int coll = wn * 64 + nb * 8 + 2 * tq;
            const float b0 = sbias[coll];
            const float b1 = sbias[coll + 1];
            const float v0 = acc[mi][nb][0] + b0;
            const float v1 = acc[mi][nb][1] + b1;
            const float v2 = acc[mi][nb][2] + b0;
            const float v3 = acc[mi][nb][3] + b1;
            const size_t o0 = (size_t)row0 * N + bn + coll;
            const size_t o1 = (size_t)row1 * N + bn + coll;
            if (OUT_MODE == 1) {
                uint32_t hi, lo;
                split2h(v0, v1, hi, lo);
                *(uint32_t*)(Chi + o0) = hi;
                *(uint32_t*)(Clo + o0) = lo;
                split2h(v2, v3, hi, lo);
                *(uint32_t*)(Chi + o1) = hi;
                *(uint32_t*)(Clo + o1) = lo;
            } else if (OUT_MODE == 2) {
                *(uint32_t*)(Chi + o0) = pack2h(v0, v1);
                *(uint32_t*)(Chi + o1) = pack2h(v2, v3);
            } else {
                *(float2*)(C + o0) = make_float2(v0, v1);
                *(float2*)(C + o1) = make_float2(v2, v3);
            }
        }
    }
}

// ---------------------------------------------------------------------------
// Register-resident FA2: Q = hi+lo fp16 (exact), K/V = single fp16.
// S: 2 MMA passes, PV: 2 MMA passes. 64-row q-tiles, 128 threads, occ 2.
// ---------------------------------------------------------------------------
#define FPITCH 72
#define AQ_HI 0
#define AQ_LO 9216
#define AKV   18432
#define KV_STAGE 18432                    // K(9216) + V(9216)
#define AK_OFF 0
#define AV_OFF 9216
#define ATT_SMEM (AKV + 2 * KV_STAGE)     // 55296

#define SFC 0.18033688f                   // 0.125 * log2(e)

__global__ __launch_bounds__(128, 2) void flash_attn_mma(
    const __half* __restrict__ qhi, const __half* __restrict__ qlo,
    const __half* __restrict__ kh_g, const __half* __restrict__ vh_g,
    __half* __restrict__ ohi, __half* __restrict__ olo)
{
    extern __shared__ char dsm[];
    const int tid = threadIdx.x;
    const int w = tid >> 5;
    const int lane = tid & 31;
    const int g = lane >> 2;
    const int tq = lane & 3;
    const int qt = (int)(gridDim.x - 1) - (int)blockIdx.x;   // heavy first
    const int b = blockIdx.y >> 4;
    const int h = blockIdx.y & 15;
    const size_t rowbase = (size_t)b * PL * PD + (size_t)h * PDK;

    const uint32_t sQh = smem_u32(dsm + AQ_HI);
    const uint32_t sQl = smem_u32(dsm + AQ_LO);
    const uint32_t sKV = smem_u32(dsm + AKV);

    // KV cp.async mapping: 64 rows x 64 cols fp16 per array, 128 threads
    const int kr0 = tid >> 3;              // 0..15
    const int kc0 = (tid & 7) * 8;

    {
        const uint32_t sb = sKV;
#pragma unroll
        for (int it = 0; it < 4; ++it) {
            const int r = kr0 + it * 16;
            const uint32_t so = (uint32_t)(r * FPITCH + kc0) * 2;
            const size_t go = rowbase + (size_t)r * PD + kc0;
            CP_ASYNC16(sb + AK_OFF + so, (const char*)(kh_g + go));
            CP_ASYNC16(sb + AV_OFF + so, (const char*)(vh_g + go));
        }
        CP_COMMIT();
    }

    // Q tile (64 x 64) hi/lo
#pragma unroll
    for (int it = 0; it < 4; ++it) {
        const int idx = tid + it * 128;
        const int r = idx >> 3;
        const int c = (idx & 7) * 8;
        const size_t go = rowbase + (size_t)(qt * 64 + r) * PD + c;
        const uint32_t so = (uint32_t)(r * FPITCH + c) * 2;
        *(uint4*)(dsm + AQ_HI + so) = *(const uint4*)(qhi + go);
        *(uint4*)(dsm + AQ_LO + so) = *(const uint4*)(qlo + go);
    }
    CP_WAIT0();
    __syncthreads();

    uint32_t qh[4][4], ql[4][4];
    {
        const int row = w * 16 + (lane & 7) + ((lane >> 3) & 1) * 8;
#pragma unroll
        for (int kb = 0; kb < 4; ++kb) {
            const int col = kb * 16 + ((lane >> 4) & 1) * 8;
            const uint32_t off = (uint32_t)(row * FPITCH + col) * 2;
            LDSM_X4(qh[kb][0], qh[kb][1], qh[kb][2], qh[kb][3], sQh + off);
            LDSM_X4(ql[kb][0], ql[kb][1], ql[kb][2], ql[kb][3], sQl + off);
        }
    }

    float oacc[8][4];
#pragma unroll
    for (int nb = 0; nb < 8; ++nb)
#pragma unroll
        for (int e = 0; e < 4; ++e) oacc[nb][e] = 0.0f;
    float m0 = -1.0e30f, m1 = -1.0e30f, l0 = 0.0f, l1 = 0.0f;

    const int jmax = qt;
    for (int j = 0; j <= jmax; ++j) {
        const int buf = j & 1;
        const uint32_t sb = sKV + buf * KV_STAGE;

        if (j < jmax) {
            const uint32_t nb_ = sKV + (buf ^ 1) * KV_STAGE;
#pragma unroll
            for (int it = 0; it < 4; ++it) {
                const int r = kr0 + it * 16;
                const uint32_t so = (uint32_t)(r * FPITCH + kc0) * 2;
                const size_t go = rowbase + (size_t)((j + 1) * 64 + r) * PD + kc0;
                CP_ASYNC16(nb_ + AK_OFF + so, (const char*)(kh_g + go));
                CP_ASYNC16(nb_ + AV_OFF + so, (const char*)(vh_g + go));
            }
            CP_COMMIT();
        }

        // S = (Qhi + Qlo) K^T  (2 passes)
        float sacc[8][4];
#pragma unroll
        for (int nb = 0; nb < 8; ++nb)
#pragma unroll
            for (int e = 0; e < 4; ++e) sacc[nb][e] = 0.0f;

#pragma unroll
        for (int kb = 0; kb < 4; ++kb) {
            uint32_t kh[8][2];
            const int kcol = kb * 16 + ((lane >> 3) & 1) * 8;
#pragma unroll
            for (int np = 0; np < 4; ++np) {
                const int krow = np * 16 + (lane & 7) + ((lane >> 4) & 1) * 8;
                const uint32_t off = (uint32_t)(krow * FPITCH + kcol) * 2;
                LDSM_X4(kh[2 * np][0], kh[2 * np][1], kh[2 * np + 1][0], kh[2 * np + 1][1],
                        sb + AK_OFF + off);
            }
#pragma unroll
            for (int nb = 0; nb < 8; ++nb) {
                MMA16816(sacc[nb], qh[kb], kh[nb]);
                MMA16816(sacc[nb], ql[kb], kh[nb]);
            }
        }

        if (j == qt) {   // diagonal tile: causal mask
            const int row0 = qt * 64 + w * 16 + g;
            const int row1 = row0 + 8;
            const int cb = j * 64 + 2 * tq;
#pragma unroll
            for (int nb = 0; nb < 8; ++nb) {
                const int c0 = cb + nb * 8, c1 = c0 + 1;
                if (c0 > row0) sacc[nb][0] = -1.0e30f;
                if (c1 > row0) sacc[nb][1] = -1.0e30f;
                if (c0 > row1) sacc[nb][2] = -1.0e30f;
                if (c1 > row1) sacc[nb][3] = -1.0e30f;
            }
        }

        // online softmax
        float mx0 = -1.0e30f, mx1 = -1.0e30f;
#pragma unroll
        for (int nb = 0; nb < 8; ++nb) {
            mx0 = fmaxf(mx0, fmaxf(sacc[nb][0], sacc[nb][1]));
            mx1 = fmaxf(mx1, fmaxf(sacc[nb][2], sacc[nb][3]));
        }
        mx0 = fmaxf(mx0, __shfl_xor_sync(0xffffffffu, mx0, 1));
        mx0 = fmaxf(mx0, __shfl_xor_sync(0xffffffffu, mx0, 2));
        mx1 = fmaxf(mx1, __shfl_xor_sync(0xffffffffu, mx1, 1));
        mx1 = fmaxf(mx1, __shfl_xor_sync(0xffffffffu, mx1, 2));

        const float mn0 = fmaxf(m0, mx0);
        const float mn1 = fmaxf(m1, mx1);
        const float em0 = mn0 * SFC;
        const float em1 = mn1 * SFC;
        const float cr0 = ex2f((m0 - mn0) * SFC);
        const float cr1 = ex2f((m1 - mn1) * SFC);
        m0 = mn0; m1 = mn1;

        float s0 = 0.0f, s1 = 0.0f;
#pragma unroll
        for (int nb = 0; nb < 8; ++nb) {
            float p0 = ex2f(fmaf(sacc[nb][0], SFC, -em0));
            float p1 = ex2f(fmaf(sacc[nb][1], SFC, -em0));
            float p2 = ex2f(fmaf(sacc[nb][2], SFC, -em1));
            float p3 = ex2f(fmaf(sacc[nb][3], SFC, -em1));
            sacc[nb][0] = p0; sacc[nb][1] = p1;
            sacc[nb][2] = p2; sacc[nb][3] = p3;
            s0 += p0 + p1; s1 += p2 + p3;
        }
        s0 += __shfl_xor_sync(0xffffffffu, s0, 1);
        s0 += __shfl_xor_sync(0xffffffffu, s0, 2);
        s1 += __shfl_xor_sync(0xffffffffu, s1, 1);
        s1 += __shfl_xor_sync(0xffffffffu, s1, 2);
        l0 = l0 * cr0 + s0;
        l1 = l1 * cr1 + s1;

#pragma unroll
        for (int nb = 0; nb < 8; ++nb) {
            oacc[nb][0] *= cr0; oacc[nb][1] *= cr0;
            oacc[nb][2] *= cr1; oacc[nb][3] *= cr1;
        }

        // P split (exact): C-frag -> A-frag relayout in registers
        uint32_t pa[4][4], pl[4][4];
#pragma unroll
        for (int kb = 0; kb < 4; ++kb) {
            split2h(sacc[2 * kb][0], sacc[2 * kb][1], pa[kb][0], pl[kb][0]);
            split2h(sacc[2 * kb][2], sacc[2 * kb][3], pa[kb][1], pl[kb][1]);
            split2h(sacc[2 * kb + 1][0], sacc[2 * kb + 1][1], pa[kb][2], pl[kb][2]);
            split2h(sacc[2 * kb + 1][2], sacc[2 * kb + 1][3], pa[kb][3], pl[kb][3]);
        }

        // O += (Phi + Plo) V  (2 passes)
#pragma unroll
        for (int kb = 0; kb < 4; ++kb) {
            uint32_t vh[8][2];
            const int vrow = kb * 16 + (lane & 7) + ((lane >> 3) & 1) * 8;
#pragma unroll
            for (int np = 0; np < 4; ++np) {
                const int vcol = np * 16 + ((lane >> 4) & 1) * 8;
                const uint32_t off = (uint32_t)(vrow * FPITCH + vcol) * 2;
                LDSM_X4_T(vh[2 * np][0], vh[2 * np][1], vh[2 * np + 1][0], vh[2 * np + 1][1],
                          sb + AV_OFF + off);
            }
#pragma unroll
            for (int nb = 0; nb < 8; ++nb) {
                MMA16816(oacc[nb], pa[kb], vh[nb]);
                MMA16816(oacc[nb], pl[kb], vh[nb]);
            }
        }

        if (j < jmax) {
            CP_WAIT0();
            __syncthreads();
        }
    }

    // epilogue: normalize, split hi/lo, store
    const float inv0 = 1.0f / l0;
    const float inv1 = 1.0f / l1;
    const int row0 = qt * 64 + w * 16 + g;
#pragma unroll
    for (int nb = 0; nb < 8; ++nb) {
        const int col = nb * 8 + 2 * tq;
        uint32_t hi, lo;
        split2h(oacc[nb][0] * inv0, oacc[nb][1] * inv0, hi, lo);
        const size_t g0 = rowbase + (size_t)row0 * PD + col;
        *(uint32_t*)(ohi + g0) = hi;
        *(uint32_t*)(olo + g0) = lo;
        split2h(oacc[nb][2] * inv1, oacc[nb][3] * inv1, hi, lo);
        const size_t g1 = rowbase + (size_t)(row0 + 8) * PD + col;
        *(uint32_t*)(ohi + g1) = hi;
        *(uint32_t*)(olo + g1) = lo;
    }
}

// ---------------------------------------------------------------------------
extern "C" void kernel_launch(void* const* d_in, const int* in_sizes, int n_in,
                              void* d_out, int out_size)
{
    const float* Q    = (const float*)d_in[0];
    const float* K    = (const float*)d_in[1];
    const float* V    = (const float*)d_in[2];
    const float* Wq_w = (const float*)d_in[4];
    const float* Wq_b = (const float*)d_in[5];
    const float* Wk_w = (const float*)d_in[6];
    const float* Wk_b = (const float*)d_in[7];
    const float* Wv_w = (const float*)d_in[8];
    const float* Wv_b = (const float*)d_in[9];
    const float* fc_w = (const float*)d_in[10];
    const float* fc_b = (const float*)d_in[11];
    float* out = (float*)d_out;

    __half *xhi, *xlo, *wh, *qhi, *qlo, *kh, *vh, *ahi, *alo;
    cudaGetSymbolAddress((void**)&xhi, g_xhi);
    cudaGetSymbolAddress((void**)&xlo, g_xlo);
    cudaGetSymbolAddress((void**)&wh, g_wh);
    cudaGetSymbolAddress((void**)&qhi, g_qhi);
    cudaGetSymbolAddress((void**)&qlo, g_qlo);
    cudaGetSymbolAddress((void**)&kh, g_kh);
    cudaGetSymbolAddress((void**)&vh, g_vh);
    cudaGetSymbolAddress((void**)&ahi, g_ahi);
    cudaGetSymbolAddress((void**)&alo, g_alo);

    cudaFuncSetAttribute(gemm2_mma<0>,
                         cudaFuncAttributeMaxDynamicSharedMemorySize, G_SMEM);
    cudaFuncSetAttribute(gemm2_mma<1>,
                         cudaFuncAttributeMaxDynamicSharedMemorySize, G_SMEM);
    cudaFuncSetAttribute(gemm2_mma<2>,
                         cudaFuncAttributeMaxDynamicSharedMemorySize, G_SMEM);
    cudaFuncSetAttribute(flash_attn_mma,
                         cudaFuncAttributeMaxDynamicSharedMemorySize, ATT_SMEM);

    const int nA4 = MD / 4;
    const int nW4 = DD / 4;
    dim3 ggrid(PD / BGN, PM / BGM);   // (4, 32) = 128 CTAs, single wave

    // Splits (2 launches)
    split3_in<<<dim3(nA4 / 256, 1, 3), 256>>>(Q, K, V, xhi, xlo);
    split4_wh<<<dim3(nW4 / 256, 1, 4), 256>>>(Wq_w, Wk_w, Wv_w, fc_w, wh);

    // Projections: q -> hi/lo, k/v -> hi only
    gemm2_mma<1><<<ggrid, 256, G_SMEM>>>(
        xhi, xlo, wh, Wq_b, nullptr, qhi, qlo, PD, PD);
    gemm2_mma<2><<<ggrid, 256, G_SMEM>>>(
        xhi + MD, xlo + MD, wh + DD, Wk_b, nullptr, kh, nullptr, PD, PD);
    gemm2_mma<2><<<ggrid, 256, G_SMEM>>>(
        xhi + 2 * (size_t)MD, xlo + 2 * (size_t)MD, wh + 2 * (size_t)DD, Wv_b,
        nullptr, vh, nullptr, PD, PD);

    // Attention (S: 2 passes, PV: 2 passes)
    flash_attn_mma<<<dim3(PL / 64, PB * PH), 128, ATT_SMEM>>>(
        qhi, qlo, kh, vh, ahi, alo);

    // Output projection (fp32 out, 2-pass split-A)
    gemm2_mma<0><<<ggrid, 256, G_SMEM>>>(
        ahi, alo, wh + 3 * (size_t)DD, fc_b, out, nullptr, nullptr, PD, PD);
}

// round 12
// speedup vs baseline: 1.5926x; 1.1282x over previous
#include <cuda_runtime.h>
#include <cuda_fp16.h>
#include <cstdint>
#include <math.h>

// Problem constants
#define PB 2
#define PL 2048
#define PD 1024
#define PH 16
#define PDK 64
#define PM (PB * PL)   // 4096
#define MD (PM * PD)
#define DD (PD * PD)

// Scratch (device globals), fp16
__device__ __half g_xhi[3 * MD];   // Q,K,V input splits (hi)
__device__ __half g_xlo[3 * MD];   //                    (lo)
__device__ __half g_wh[4 * DD];    // Wq,Wk,Wv,fc weights (hi only)
__device__ __half g_qh[MD];        // q projection (hi only)
__device__ __half g_kh[MD];        // k projection (hi only)
__device__ __half g_vh[MD];        // v projection (hi only)
__device__ __half g_ahi[MD];       // attention output (hi)
__device__ __half g_alo[MD];       //                  (lo)

// ---------------------------------------------------------------------------
// PTX helpers
// ---------------------------------------------------------------------------
__device__ __forceinline__ uint32_t smem_u32(const void* p) {
    uint32_t a;
    asm("{ .reg .u64 t; cvta.to.shared.u64 t, %1; cvt.u32.u64 %0, t; }"
        : "=r"(a) : "l"(p));
    return a;
}

#define MMA16816(c, a, b) \
    asm volatile("mma.sync.aligned.m16n8k16.row.col.f32.f16.f16.f32 " \
        "{%0,%1,%2,%3}, {%4,%5,%6,%7}, {%8,%9}, {%0,%1,%2,%3};" \
        : "+f"((c)[0]), "+f"((c)[1]), "+f"((c)[2]), "+f"((c)[3]) \
        : "r"((a)[0]), "r"((a)[1]), "r"((a)[2]), "r"((a)[3]), \
          "r"((b)[0]), "r"((b)[1]))

#define LDSM_X4(r0, r1, r2, r3, addr) \
    asm volatile("ldmatrix.sync.aligned.m8n8.x4.shared.b16 {%0,%1,%2,%3}, [%4];" \
        : "=r"(r0), "=r"(r1), "=r"(r2), "=r"(r3) : "r"(addr))

#define LDSM_X4_T(r0, r1, r2, r3, addr) \
    asm volatile("ldmatrix.sync.aligned.m8n8.x4.trans.shared.b16 {%0,%1,%2,%3}, [%4];" \
        : "=r"(r0), "=r"(r1), "=r"(r2), "=r"(r3) : "r"(addr))

#define CP_ASYNC16(smem, gptr) \
    asm volatile("cp.async.cg.shared.global [%0], [%1], 16;" \
        :: "r"(smem), "l"(gptr))
#define CP_COMMIT() asm volatile("cp.async.commit_group;" ::: "memory")
#define CP_WAIT0()  asm volatile("cp.async.wait_group 0;" ::: "memory")
#define CP_WAIT1()  asm volatile("cp.async.wait_group 1;" ::: "memory")

__device__ __forceinline__ float ex2f(float x) {
    float r;
    asm("ex2.approx.f32 %0, %1;" : "=f"(r) : "f"(x));
    return r;
}

__device__ __forceinline__ void split2h(float a, float b, uint32_t& hi, uint32_t& lo) {
    __half ha = __float2half_rn(a);
    __half hb = __float2half_rn(b);
    float ra = a - __half2float(ha);
    float rb = b - __half2float(hb);
    __half2 H = __halves2half2(ha, hb);
    __half2 L = __halves2half2(__float2half_rn(ra), __float2half_rn(rb));
    hi = *reinterpret_cast<uint32_t*>(&H);
    lo = *reinterpret_cast<uint32_t*>(&L);
}

__device__ __forceinline__ uint32_t pack2h(float a, float b) {
    __half2 H = __halves2half2(__float2half_rn(a), __float2half_rn(b));
    return *reinterpret_cast<uint32_t*>(&H);
}

// ---------------------------------------------------------------------------
// Splits
// ---------------------------------------------------------------------------
__global__ __launch_bounds__(256) void split3_in(
    const float* __restrict__ x0, const float* __restrict__ x1,
    const float* __restrict__ x2,
    __half* hi, __half* lo)
{
    const int i = blockIdx.x * 256 + threadIdx.x;
    const int z = blockIdx.z;
    const float* x = (z == 0) ? x0 : (z == 1) ? x1 : x2;
    float4 v = reinterpret_cast<const float4*>(x)[i];
    uint32_t h0, l0, h1, l1;
    split2h(v.x, v.y, h0, l0);
    split2h(v.z, v.w, h1, l1);
    reinterpret_cast<uint2*>(hi + (size_t)z * MD)[i] = make_uint2(h0, h1);
    reinterpret_cast<uint2*>(lo + (size_t)z * MD)[i] = make_uint2(l0, l1);
}

__global__ __launch_bounds__(256) void split4_wh(
    const float* __restrict__ x0, const float* __restrict__ x1,
    const float* __restrict__ x2, const float* __restrict__ x3,
    __half* wh)
{
    const int i = blockIdx.x * 256 + threadIdx.x;
    const int z = blockIdx.z;
    const float* x = (z == 0) ? x0 : (z == 1) ? x1 : (z == 2) ? x2 : x3;
    float4 v = reinterpret_cast<const float4*>(x)[i];
    reinterpret_cast<uint2*>(wh + (size_t)z * DD)[i] =
        make_uint2(pack2h(v.x, v.y), pack2h(v.z, v.w));
}

// ---------------------------------------------------------------------------
// mma.sync fp16 GEMM (2-pass split-A): C = (Ahi+Alo) @ Wh^T + bias
// OUT_MODE: 0 = fp32, 1 = fp16 hi+lo pair, 2 = fp16 hi only.
// 128x256x32 tiles, 256 threads (2m x 4n warps), 3-stage cp.async.
// ---------------------------------------------------------------------------
#define BGM 128
#define BGN 256
#define BGK 32
#define GP 40
#define A_T (BGM * GP * 2)                // 10240 B
#define B_T (BGN * GP * 2)                // 20480 B
#define OFF_A_HI 0
#define OFF_A_LO A_T
#define OFF_B    (2 * A_T)
#define STG_B (2 * A_T + B_T)             // 40960 B
#define NST 3
#define G_SMEM (NST * STG_B)              // 122880 B

template <int OUT_MODE>
__global__ __launch_bounds__(256, 1) void gemm2_mma(
    const __half* __restrict__ Ahi, const __half* __restrict__ Alo,
    const __half* __restrict__ Wh,
    const float* __restrict__ bias, float* __restrict__ C,
    __half* __restrict__ Chi, __half* __restrict__ Clo,
    int K, int N)
{
    extern __shared__ char dsm[];
    __shared__ float sbias[BGN];

    const int tid = threadIdx.x;
    const int w = tid >> 5;
    const int lane = tid & 31;
    const int wm = w >> 2;
    const int wn = w & 3;
    const int g = lane >> 2;
    const int tq = lane & 3;
    const int bm = blockIdx.y * BGM;
    const int bn = blockIdx.x * BGN;
    const uint32_t sbase = smem_u32(dsm);

    const int lr = tid >> 2;
    const int lc = (tid & 3) * 8;

    auto issue = [&](int c, int buf) {
        const uint32_t sb = sbase + buf * STG_B;
        const int kofs = c * BGK;
#pragma unroll
        for (int it = 0; it < 2; ++it) {
            const int r = lr + it * 64;
            const uint32_t so = (uint32_t)(r * GP + lc) * 2;
            const size_t go = (size_t)(bm + r) * K + kofs + lc;
            CP_ASYNC16(sb + OFF_A_HI + so, (const char*)(Ahi + go));
            CP_ASYNC16(sb + OFF_A_LO + so, (const char*)(Alo + go));
        }
#pragma unroll
        for (int it = 0; it < 4; ++it) {
            const int r = lr + it * 64;
            const uint32_t so = (uint32_t)(r * GP + lc) * 2;
            const size_t go = (size_t)(bn + r) * K + kofs + lc;
            CP_ASYNC16(sb + OFF_B + so, (const char*)(Wh + go));
        }
    };

    issue(0, 0); CP_COMMIT();
    issue(1, 1); CP_COMMIT();

    sbias[tid] = bias[bn + tid];

    float acc[4][8][4];
#pragma unroll
    for (int mi = 0; mi < 4; ++mi)
#pragma unroll
        for (int nb = 0; nb < 8; ++nb)
#pragma unroll
            for (int e = 0; e < 4; ++e) acc[mi][nb][e] = 0.0f;

    const int a_r = (lane & 7) + ((lane >> 3) & 1) * 8;
    const int a_c = ((lane >> 4) & 1) * 8;
    const int b_r = (lane & 7) + ((lane >> 4) & 1) * 8;
    const int b_c = ((lane >> 3) & 1) * 8;

    const int nchunk = K / BGK;   // 32
    for (int c = 0; c < nchunk; ++c) {
        if (c + 1 < nchunk) CP_WAIT1(); else CP_WAIT0();
        __syncthreads();
        if (c + 2 < nchunk) { issue(c + 2, (c + 2) % NST); CP_COMMIT(); }

        const uint32_t sb = sbase + (c % NST) * STG_B;
#pragma unroll
        for (int kk = 0; kk < 2; ++kk) {
            uint32_t ah[4][4], al[4][4];
#pragma unroll
            for (int mi = 0; mi < 4; ++mi) {
                const uint32_t off =
                    (uint32_t)((wm * 64 + mi * 16 + a_r) * GP + kk * 16 + a_c) * 2;
                LDSM_X4(ah[mi][0], ah[mi][1], ah[mi][2], ah[mi][3],
                        sb + OFF_A_HI + off);
                LDSM_X4(al[mi][0], al[mi][1], al[mi][2], al[mi][3],
                        sb + OFF_A_LO + off);
            }
            uint32_t bh[8][2];
#pragma unroll
            for (int np = 0; np < 4; ++np) {
                const uint32_t off =
                    (uint32_t)((wn * 64 + np * 16 + b_r) * GP + kk * 16 + b_c) * 2;
                LDSM_X4(bh[2 * np][0], bh[2 * np][1], bh[2 * np + 1][0], bh[2 * np + 1][1],
                        sb + OFF_B + off);
            }
#pragma unroll
            for (int mi = 0; mi < 4; ++mi)
#pragma unroll
                for (int nb = 0; nb < 8; ++nb) {
                    MMA16816(acc[mi][nb], ah[mi], bh[nb]);
                    MMA16816(acc[mi][nb], al[mi], bh[nb]);
                }
        }
    }

    // epilogue
#pragma unroll
    for (int mi = 0; mi < 4; ++mi) {
        const int row0 = bm + wm * 64 + mi * 16 + g;
        const int row1 = row0 + 8;
#pragma unroll
        for (int nb = 0; nb < 8; ++nb) {
            const int coll = wn * 64 + nb * 8 + 2 * tq;
            const float b0 = sbias[coll];
            const float b1 = sbias[coll + 1];
            const float v0 = acc[mi][nb][0] + b0;
            const float v1 = acc[mi][nb][1] + b1;
            const float v2 = acc[mi][nb][2] + b0;
            const float v3 = acc[mi][nb][3] + b1;
            const size_t o0 = (size_t)row0 * N + bn + coll;
            const size_t o1 = (size_t)row1 * N + bn + coll;
            if (OUT_MODE == 1) {
                uint32_t hi, lo;
                split2h(v0, v1, hi, lo);
                *(uint32_t*)(Chi + o0) = hi;
                *(uint32_t*)(Clo + o0) = lo;
                split2h(v2, v3, hi, lo);
                *(uint32_t*)(Chi + o1) = hi;
                *(uint32_t*)(Clo + o1) = lo;
            } else if (OUT_MODE == 2) {
                *(uint32_t*)(Chi + o0) = pack2h(v0, v1);
                *(uint32_t*)(Chi + o1) = pack2h(v2, v3);
            } else {
                *(float2*)(C + o0) = make_float2(v0, v1);
                *(float2*)(C + o1) = make_float2(v2, v3);
            }
        }
    }
}

// ---------------------------------------------------------------------------
// Register-resident FA2: Q, K, V, P all single fp16 — 1 MMA pass for S,
// 1 for PV. 64-row q-tiles, 128 threads (4 warps), occ 2, heavy CTAs first.
// ---------------------------------------------------------------------------
#define FPITCH 72
#define AQ_OFF 0
#define AKV    9216
#define KV_STAGE 18432                    // K(9216) + V(9216)
#define AK_OFF 0
#define AV_OFF 9216
#define ATT_SMEM (AKV + 2 * KV_STAGE)     // 46080

#define SFC 0.18033688f                   // 0.125 * log2(e)

__global__ __launch_bounds__(128, 2) void flash_attn_mma(
    const __half* __restrict__ qh_g, const __half* __restrict__ kh_g,
    const __half* __restrict__ vh_g,
    __half* __restrict__ ohi, __half* __restrict__ olo)
{
    extern __shared__ char dsm[];
    const int tid = threadIdx.x;
    const int w = tid >> 5;
    const int lane = tid & 31;
    const int g = lane >> 2;
    const int tq = lane & 3;
    const int qt = (int)(gridDim.x - 1) - (int)blockIdx.x;   // heavy first
    const int b = blockIdx.y >> 4;
    const int h = blockIdx.y & 15;
    const size_t rowbase = (size_t)b * PL * PD + (size_t)h * PDK;

    const uint32_t sQ = smem_u32(dsm + AQ_OFF);
    const uint32_t sKV = smem_u32(dsm + AKV);

    const int kr0 = tid >> 3;              // 0..15
    const int kc0 = (tid & 7) * 8;

    // prologue: KV tile 0 into buffer 0
    {
        const uint32_t sb = sKV;
#pragma unroll
        for (int it = 0; it < 4; ++it) {
            const int r = kr0 + it * 16;
            const uint32_t so = (uint32_t)(r * FPITCH + kc0) * 2;
            const size_t go = rowbase + (size_t)r * PD + kc0;
            CP_ASYNC16(sb + AK_OFF + so, (const char*)(kh_g + go));
            CP_ASYNC16(sb + AV_OFF + so, (const char*)(vh_g + go));
        }
        CP_COMMIT();
    }

    // Q tile (64 x 64), hi only
#pragma unroll
    for (int it = 0; it < 4; ++it) {
        const int idx = tid + it * 128;
        const int r = idx >> 3;
        const int c = (idx & 7) * 8;
        const size_t go = rowbase + (size_t)(qt * 64 + r) * PD + c;
        const uint32_t so = (uint32_t)(r * FPITCH + c) * 2;
        *(uint4*)(dsm + AQ_OFF + so) = *(const uint4*)(qh_g + go);
    }
    CP_WAIT0();
    __syncthreads();

    uint32_t qh[4][4];
    {
        const int row = w * 16 + (lane & 7) + ((lane >> 3) & 1) * 8;
#pragma unroll
        for (int kb = 0; kb < 4; ++kb) {
            const int col = kb * 16 + ((lane >> 4) & 1) * 8;
            const uint32_t off = (uint32_t)(row * FPITCH + col) * 2;
            LDSM_X4(qh[kb][0], qh[kb][1], qh[kb][2], qh[kb][3], sQ + off);
        }
    }

    float oacc[8][4];
#pragma unroll
    for (int nb = 0; nb < 8; ++nb)
#pragma unroll
        for (int e = 0; e < 4; ++e) oacc[nb][e] = 0.0f;
    float m0 = -1.0e30f, m1 = -1.0e30f, l0 = 0.0f, l1 = 0.0f;

    const int jmax = qt;
    for (int j = 0; j <= jmax; ++j) {
        const int buf = j & 1;
        const uint32_t sb = sKV + buf * KV_STAGE;

        if (j < jmax) {
            const uint32_t nb_ = sKV + (buf ^ 1) * KV_STAGE;
#pragma unroll
            for (int it = 0; it < 4; ++it) {
                const int r = kr0 + it * 16;
                const uint32_t so = (uint32_t)(r * FPITCH + kc0) * 2;
                const size_t go = rowbase + (size_t)((j + 1) * 64 + r) * PD + kc0;
                CP_ASYNC16(nb_ + AK_OFF + so, (const char*)(kh_g + go));
                CP_ASYNC16(nb_ + AV_OFF + so, (const char*)(vh_g + go));
            }
            CP_COMMIT();
        }

        // S = Q K^T (single pass)
        float sacc[8][4];
#pragma unroll
        for (int nb = 0; nb < 8; ++nb)
#pragma unroll
            for (int e = 0; e < 4; ++e) sacc[nb][e] = 0.0f;

#pragma unroll
        for (int kb = 0; kb < 4; ++kb) {
            uint32_t kh[8][2];
            const int kcol = kb * 16 + ((lane >> 3) & 1) * 8;
#pragma unroll
            for (int np = 0; np < 4; ++np) {
                const int krow = np * 16 + (lane & 7) + ((lane >> 4) & 1) * 8;
                const uint32_t off = (uint32_t)(krow * FPITCH + kcol) * 2;
                LDSM_X4(kh[2 * np][0], kh[2 * np][1], kh[2 * np + 1][0], kh[2 * np + 1][1],
                        sb + AK_OFF + off);
            }
#pragma unroll
            for (int nb = 0; nb < 8; ++nb)
                MMA16816(sacc[nb], qh[kb], kh[nb]);
        }

        if (j == qt) {   // diagonal tile: causal mask
            const int row0 = qt * 64 + w * 16 + g;
            const int row1 = row0 + 8;
            const int cb = j * 64 + 2 * tq;
#pragma unroll
            for (int nb = 0; nb < 8; ++nb) {
                const int c0 = cb + nb * 8, c1 = c0 + 1;
                if (c0 > row0) sacc[nb][0] = -1.0e30f;
                if (c1 > row0) sacc[nb][1] = -1.0e30f;
                if (c0 > row1) sacc[nb][2] = -1.0e30f;
                if (c1 > row1) sacc[nb][3] = -1.0e30f;
            }
        }

        // online softmax
        float mx0 = -1.0e30f, mx1 = -1.0e30f;
#pragma unroll
        for (int nb = 0; nb < 8; ++nb) {
            mx0 = fmaxf(mx0, fmaxf(sacc[nb][0], sacc[nb][1]));
            mx1 = fmaxf(mx1, fmaxf(sacc[nb][2], sacc[nb][3]));
        }
        mx0 = fmaxf(mx0, __shfl_xor_sync(0xffffffffu, mx0, 1));
        mx0 = fmaxf(mx0, __shfl_xor_sync(0xffffffffu, mx0, 2));
        mx1 = fmaxf(mx1, __shfl_xor_sync(0xffffffffu, mx1, 1));
        mx1 = fmaxf(mx1, __shfl_xor_sync(0xffffffffu, mx1, 2));

        const float mn0 = fmaxf(m0, mx0);
        const float mn1 = fmaxf(m1, mx1);
        const float em0 = mn0 * SFC;
        const float em1 = mn1 * SFC;
        const float cr0 = ex2f((m0 - mn0) * SFC);
        const float cr1 = ex2f((m1 - mn1) * SFC);
        m0 = mn0; m1 = mn1;

        float s0 = 0.0f, s1 = 0.0f;
#pragma unroll
        for (int nb = 0; nb < 8; ++nb) {
            float p0 = ex2f(fmaf(sacc[nb][0], SFC, -em0));
            float p1 = ex2f(fmaf(sacc[nb][1], SFC, -em0));
            float p2 = ex2f(fmaf(sacc[nb][2], SFC, -em1));
            float p3 = ex2f(fmaf(sacc[nb][3], SFC, -em1));
            sacc[nb][0] = p0; sacc[nb][1] = p1;
            sacc[nb][2] = p2; sacc[nb][3] = p3;
            s0 += p0 + p1; s1 += p2 + p3;
        }
        s0 += __shfl_xor_sync(0xffffffffu, s0, 1);
        s0 += __shfl_xor_sync(0xffffffffu, s0, 2);
        s1 += __shfl_xor_sync(0xffffffffu, s1, 1);
        s1 += __shfl_xor_sync(0xffffffffu, s1, 2);
        l0 = l0 * cr0 + s0;
        l1 = l1 * cr1 + s1;

#pragma unroll
        for (int nb = 0; nb < 8; ++nb) {
            oacc[nb][0] *= cr0; oacc[nb][1] *= cr0;
            oacc[nb][2] *= cr1; oacc[nb][3] *= cr1;
        }

        // P (single fp16): C-frag -> A-frag relayout in registers
        uint32_t pa[4][4];
#pragma unroll
        for (int kb = 0; kb < 4; ++kb) {
            pa[kb][0] = pack2h(sacc[2 * kb][0], sacc[2 * kb][1]);
            pa[kb][1] = pack2h(sacc[2 * kb][2], sacc[2 * kb][3]);
            pa[kb][2] = pack2h(sacc[2 * kb + 1][0], sacc[2 * kb + 1][1]);
            pa[kb][3] = pack2h(sacc[2 * kb + 1][2], sacc[2 * kb + 1][3]);
        }

        // O += P V (single pass)
#pragma unroll
        for (int kb = 0; kb < 4; ++kb) {
            uint32_t vh[8][2];
            const int vrow = kb * 16 + (lane & 7) + ((lane >> 3) & 1) * 8;
#pragma unroll
            for (int np = 0; np < 4; ++np) {
                const int vcol = np * 16 + ((lane >> 4) & 1) * 8;
                const uint32_t off = (uint32_t)(vrow * FPITCH + vcol) * 2;
                LDSM_X4_T(vh[2 * np][0], vh[2 * np][1], vh[2 * np + 1][0], vh[2 * np + 1][1],
                          sb + AV_OFF + off);
            }
#pragma unroll
            for (int nb = 0; nb < 8; ++nb)
                MMA16816(oacc[nb], pa[kb], vh[nb]);
        }

        if (j < jmax) {
            CP_WAIT0();
            __syncthreads();
        }
    }

    // epilogue: normalize, split hi/lo, store
    const float inv0 = 1.0f / l0;
    const float inv1 = 1.0f / l1;
    const int row0 = qt * 64 + w * 16 + g;
#pragma unroll
    for (int nb = 0; nb < 8; ++nb) {
        const int col = nb * 8 + 2 * tq;
        uint32_t hi, lo;
        split2h(oacc[nb][0] * inv0, oacc[nb][1] * inv0, hi, lo);
        const size_t g0 = rowbase + (size_t)row0 * PD + col;
        *(uint32_t*)(ohi + g0) = hi;
        *(uint32_t*)(olo + g0) = lo;
        split2h(oacc[nb][2] * inv1, oacc[nb][3] * inv1, hi, lo);
        const size_t g1 = rowbase + (size_t)(row0 + 8) * PD + col;
        *(uint32_t*)(ohi + g1) = hi;
        *(uint32_t*)(olo + g1) = lo;
    }
}

// ---------------------------------------------------------------------------
extern "C" void kernel_launch(void* const* d_in, const int* in_sizes, int n_in,
                              void* d_out, int out_size)
{
    const float* Q    = (const float*)d_in[0];
    const float* K    = (const float*)d_in[1];
    const float* V    = (const float*)d_in[2];
    const float* Wq_w = (const float*)d_in[4];
    const float* Wq_b = (const float*)d_in[5];
    const float* Wk_w = (const float*)d_in[6];
    const float* Wk_b = (const float*)d_in[7];
    const float* Wv_w = (const float*)d_in[8];
    const float* Wv_b = (const float*)d_in[9];
    const float* fc_w = (const float*)d_in[10];
    const float* fc_b = (const float*)d_in[11];
    float* out = (float*)d_out;

    __half *xhi, *xlo, *wh, *qh, *kh, *vh, *ahi, *alo;
    cudaGetSymbolAddress((void**)&xhi, g_xhi);
    cudaGetSymbolAddress((void**)&xlo, g_xlo);
    cudaGetSymbolAddress((void**)&wh, g_wh);
    cudaGetSymbolAddress((void**)&qh, g_qh);
    cudaGetSymbolAddress((void**)&kh, g_kh);
    cudaGetSymbolAddress((void**)&vh, g_vh);
    cudaGetSymbolAddress((void**)&ahi, g_ahi);
    cudaGetSymbolAddress((void**)&alo, g_alo);

    cudaFuncSetAttribute(gemm2_mma<0>,
                         cudaFuncAttributeMaxDynamicSharedMemorySize, G_SMEM);
    cudaFuncSetAttribute(gemm2_mma<1>,
                         cudaFuncAttributeMaxDynamicSharedMemorySize, G_SMEM);
    cudaFuncSetAttribute(gemm2_mma<2>,
                         cudaFuncAttributeMaxDynamicSharedMemorySize, G_SMEM);
    cudaFuncSetAttribute(flash_attn_mma,
                         cudaFuncAttributeMaxDynamicSharedMemorySize, ATT_SMEM);

    const int nA4 = MD / 4;
    const int nW4 = DD / 4;
    dim3 ggrid(PD / BGN, PM / BGM);   // (4, 32) = 128 CTAs, single wave

    // Splits (2 launches)
    split3_in<<<dim3(nA4 / 256, 1, 3), 256>>>(Q, K, V, xhi, xlo);
    split4_wh<<<dim3(nW4 / 256, 1, 4), 256>>>(Wq_w, Wk_w, Wv_w, fc_w, wh);

    // Projections: q/k/v all hi-only outputs (2-pass split-A inside)
    gemm2_mma<2><<<ggrid, 256, G_SMEM>>>(
        xhi, xlo, wh, Wq_b, nullptr, qh, nullptr, PD, PD);
    gemm2_mma<2><<<ggrid, 256, G_SMEM>>>(
        xhi + MD, xlo + MD, wh + DD, Wk_b, nullptr, kh, nullptr, PD, PD);
    gemm2_mma<2><<<ggrid, 256, G_SMEM>>>(
        xhi + 2 * (size_t)MD, xlo + 2 * (size_t)MD, wh + 2 * (size_t)DD, Wv_b,
        nullptr, vh, nullptr, PD, PD);

    // Attention (1 S pass, 1 PV pass)
    flash_attn_mma<<<dim3(PL / 64, PB * PH), 128, ATT_SMEM>>>(
        qh, kh, vh, ahi, alo);

    // Output projection (fp32 out, 2-pass split-A — fully protected)
    gemm2_mma<0><<<ggrid, 256, G_SMEM>>>(
        ahi, alo, wh + 3 * (size_t)DD, fc_b, out, nullptr, nullptr, PD, PD);
}

// round 13
// speedup vs baseline: 1.8163x; 1.1405x over previous
#include <cuda_runtime.h>
#include <cuda_fp16.h>
#include <cstdint>
#include <math.h>

// Problem constants
#define PB 2
#define PL 2048
#define PD 1024
#define PH 16
#define PDK 64
#define PM (PB * PL)   // 4096
#define MD (PM * PD)
#define DD (PD * PD)

// Scratch (device globals), fp16
__device__ __half g_xhi[3 * MD];   // Q,K,V input splits (hi)
__device__ __half g_xlo[3 * MD];   //                    (lo)
__device__ __half g_wh[4 * DD];    // Wq,Wk,Wv,fc weights (hi only)
__device__ __half g_qh[MD];        // q projection (hi only)
__device__ __half g_kh[MD];        // k projection (hi only)
__device__ __half g_vh[MD];        // v projection (hi only)
__device__ __half g_ahi[MD];       // attention output (hi)
__device__ __half g_alo[MD];       //                  (lo)

// ---------------------------------------------------------------------------
// PTX helpers
// ---------------------------------------------------------------------------
__device__ __forceinline__ uint32_t smem_u32(const void* p) {
    uint32_t a;
    asm("{ .reg .u64 t; cvta.to.shared.u64 t, %1; cvt.u32.u64 %0, t; }"
        : "=r"(a) : "l"(p));
    return a;
}

#define MMA16816(c, a, b) \
    asm volatile("mma.sync.aligned.m16n8k16.row.col.f32.f16.f16.f32 " \
        "{%0,%1,%2,%3}, {%4,%5,%6,%7}, {%8,%9}, {%0,%1,%2,%3};" \
        : "+f"((c)[0]), "+f"((c)[1]), "+f"((c)[2]), "+f"((c)[3]) \
        : "r"((a)[0]), "r"((a)[1]), "r"((a)[2]), "r"((a)[3]), \
          "r"((b)[0]), "r"((b)[1]))

#define LDSM_X4(r0, r1, r2, r3, addr) \
    asm volatile("ldmatrix.sync.aligned.m8n8.x4.shared.b16 {%0,%1,%2,%3}, [%4];" \
        : "=r"(r0), "=r"(r1), "=r"(r2), "=r"(r3) : "r"(addr))

#define LDSM_X4_T(r0, r1, r2, r3, addr) \
    asm volatile("ldmatrix.sync.aligned.m8n8.x4.trans.shared.b16 {%0,%1,%2,%3}, [%4];" \
        : "=r"(r0), "=r"(r1), "=r"(r2), "=r"(r3) : "r"(addr))

#define CP_ASYNC16(smem, gptr) \
    asm volatile("cp.async.cg.shared.global [%0], [%1], 16;" \
        :: "r"(smem), "l"(gptr))
#define CP_COMMIT() asm volatile("cp.async.commit_group;" ::: "memory")
#define CP_WAIT0()  asm volatile("cp.async.wait_group 0;" ::: "memory")
#define CP_WAIT1()  asm volatile("cp.async.wait_group 1;" ::: "memory")

__device__ __forceinline__ float ex2f(float x) {
    float r;
    asm("ex2.approx.f32 %0, %1;" : "=f"(r) : "f"(x));
    return r;
}

__device__ __forceinline__ void split2h(float a, float b, uint32_t& hi, uint32_t& lo) {
    __half ha = __float2half_rn(a);
    __half hb = __float2half_rn(b);
    float ra = a - __half2float(ha);
    float rb = b - __half2float(hb);
    __half2 H = __halves2half2(ha, hb);
    __half2 L = __halves2half2(__float2half_rn(ra), __float2half_rn(rb));
    hi = *reinterpret_cast<uint32_t*>(&H);
    lo = *reinterpret_cast<uint32_t*>(&L);
}

__device__ __forceinline__ uint32_t pack2h(float a, float b) {
    __half2 H = __halves2half2(__float2half_rn(a), __float2half_rn(b));
    return *reinterpret_cast<uint32_t*>(&H);
}

// ---------------------------------------------------------------------------
// Splits
// ---------------------------------------------------------------------------
__global__ __launch_bounds__(256) void split3_in(
    const float* __restrict__ x0, const float* __restrict__ x1,
    const float* __restrict__ x2,
    __half* hi, __half* lo)
{
    const int i = blockIdx.x * 256 + threadIdx.x;
    const int z = blockIdx.z;
    const float* x = (z == 0) ? x0 : (z == 1) ? x1 : x2;
    float4 v = reinterpret_cast<const float4*>(x)[i];
    uint32_t h0, l0, h1, l1;
    split2h(v.x, v.y, h0, l0);
    split2h(v.z, v.w, h1, l1);
    reinterpret_cast<uint2*>(hi + (size_t)z * MD)[i] = make_uint2(h0, h1);
    reinterpret_cast<uint2*>(lo + (size_t)z * MD)[i] = make_uint2(l0, l1);
}

__global__ __launch_bounds__(256) void split4_wh(
    const float* __restrict__ x0, const float* __restrict__ x1,
    const float* __restrict__ x2, const float* __restrict__ x3,
    __half* wh)
{
    const int i = blockIdx.x * 256 + threadIdx.x;
    const int z = blockIdx.z;
    const float* x = (z == 0) ? x0 : (z == 1) ? x1 : (z == 2) ? x2 : x3;
    float4 v = reinterpret_cast<const float4*>(x)[i];
    reinterpret_cast<uint2*>(wh + (size_t)z * DD)[i] =
        make_uint2(pack2h(v.x, v.y), pack2h(v.z, v.w));
}

// ---------------------------------------------------------------------------
// mma.sync fp16 GEMM: C = A @ Wh^T + bias
// APASS2: true  -> A = Ahi + Alo (2 MMA passes, exact-ish A)
//         false -> A = Ahi only  (1 MMA pass)
// OUT_MODE: 0 = fp32, 1 = fp16 hi+lo pair, 2 = fp16 hi only.
// 128x256x32 tiles, 256 threads (2m x 4n warps), 3-stage cp.async.
// ---------------------------------------------------------------------------
#define BGM 128
#define BGN 256
#define BGK 32
#define GP 40
#define A_T (BGM * GP * 2)                // 10240 B
#define B_T (BGN * GP * 2)                // 20480 B
#define OFF_A_HI 0
#define OFF_A_LO A_T
#define OFF_B    (2 * A_T)
#define STG_B (2 * A_T + B_T)             // 40960 B
#define NST 3
#define G_SMEM (NST * STG_B)              // 122880 B

template <int OUT_MODE, bool APASS2>
__global__ __launch_bounds__(256, 1) void gemm2_mma(
    const __half* __restrict__ Ahi, const __half* __restrict__ Alo,
    const __half* __restrict__ Wh,
    const float* __restrict__ bias, float* __restrict__ C,
    __half* __restrict__ Chi, __half* __restrict__ Clo,
    int K, int N)
{
    extern __shared__ char dsm[];
    __shared__ float sbias[BGN];

    const int tid = threadIdx.x;
    const int w = tid >> 5;
    const int lane = tid & 31;
    const int wm = w >> 2;
    const int wn = w & 3;
    const int g = lane >> 2;
    const int tq = lane & 3;
    const int bm = blockIdx.y * BGM;
    const int bn = blockIdx.x * BGN;
    const uint32_t sbase = smem_u32(dsm);

    const int lr = tid >> 2;
    const int lc = (tid & 3) * 8;

    auto issue = [&](int c, int buf) {
        const uint32_t sb = sbase + buf * STG_B;
        const int kofs = c * BGK;
#pragma unroll
        for (int it = 0; it < 2; ++it) {
            const int r = lr + it * 64;
            const uint32_t so = (uint32_t)(r * GP + lc) * 2;
            const size_t go = (size_t)(bm + r) * K + kofs + lc;
            CP_ASYNC16(sb + OFF_A_HI + so, (const char*)(Ahi + go));
            if (APASS2)
                CP_ASYNC16(sb + OFF_A_LO + so, (const char*)(Alo + go));
        }
#pragma unroll
        for (int it = 0; it < 4; ++it) {
            const int r = lr + it * 64;
            const uint32_t so = (uint32_t)(r * GP + lc) * 2;
            const size_t go = (size_t)(bn + r) * K + kofs + lc;
            CP_ASYNC16(sb + OFF_B + so, (const char*)(Wh + go));
        }
    };

    issue(0, 0); CP_COMMIT();
    issue(1, 1); CP_COMMIT();

    sbias[tid] = bias[bn + tid];

    float acc[4][8][4];
#pragma unroll
    for (int mi = 0; mi < 4; ++mi)
#pragma unroll
        for (int nb = 0; nb < 8; ++nb)
#pragma unroll
            for (int e = 0; e < 4; ++e) acc[mi][nb][e] = 0.0f;

    const int a_r = (lane & 7) + ((lane >> 3) & 1) * 8;
    const int a_c = ((lane >> 4) & 1) * 8;
    const int b_r = (lane & 7) + ((lane >> 4) & 1) * 8;
    const int b_c = ((lane >> 3) & 1) * 8;

    const int nchunk = K / BGK;   // 32
    for (int c = 0; c < nchunk; ++c) {
        if (c + 1 < nchunk) CP_WAIT1(); else CP_WAIT0();
        __syncthreads();
        if (c + 2 < nchunk) { issue(c + 2, (c + 2) % NST); CP_COMMIT(); }

        const uint32_t sb = sbase + (c % NST) * STG_B;
#pragma unroll
        for (int kk = 0; kk < 2; ++kk) {
            uint32_t ah[4][4], al[4][4];
#pragma unroll
            for (int mi = 0; mi < 4; ++mi) {
                const uint32_t off =
                    (uint32_t)((wm * 64 + mi * 16 + a_r) * GP + kk * 16 + a_c) * 2;
                LDSM_X4(ah[mi][0], ah[mi][1], ah[mi][2], ah[mi][3],
                        sb + OFF_A_HI + off);
                if (APASS2)
                    LDSM_X4(al[mi][0], al[mi][1], al[mi][2], al[mi][3],
                            sb + OFF_A_LO + off);
            }
            uint32_t bh[8][2];
#pragma unroll
            for (int np = 0; np < 4; ++np) {
                const uint32_t off =
                    (uint32_t)((wn * 64 + np * 16 + b_r) * GP + kk * 16 + b_c) * 2;
                LDSM_X4(bh[2 * np][0], bh[2 * np][1], bh[2 * np + 1][0], bh[2 * np + 1][1],
                        sb + OFF_B + off);
            }
#pragma unroll
            for (int mi = 0; mi < 4; ++mi)
#pragma unroll
                for (int nb = 0; nb < 8; ++nb) {
                    MMA16816(acc[mi][nb], ah[mi], bh[nb]);
                    if (APASS2)
                        MMA16816(acc[mi][nb], al[mi], bh[nb]);
                }
        }
    }

    // epilogue
#pragma unroll
    for (int mi = 0; mi < 4; ++mi) {
        const int row0 = bm + wm * 64 + mi * 16 + g;
        const int row1 = row0 + 8;
#pragma unroll
        for (int nb = 0; nb < 8; ++nb) {
            const int coll = wn * 64 + nb * 8 + 2 * tq;
            const float b0 = sbias[coll];
            const float b1 = sbias[coll + 1];
            const float v0 = acc[mi][nb][0] + b0;
            const float v1 = acc[mi][nb][1] + b1;
            const float v2 = acc[mi][nb][2] + b0;
            const float v3 = acc[mi][nb][3] + b1;
            const size_t o0 = (size_t)row0 * N + bn + coll;
            const size_t o1 = (size_t)row1 * N + bn + coll;
            if (OUT_MODE == 1) {
                uint32_t hi, lo;
                split2h(v0, v1, hi, lo);
                *(uint32_t*)(Chi + o0) = hi;
                *(uint32_t*)(Clo + o0) = lo;
                split2h(v2, v3, hi, lo);
                *(uint32_t*)(Chi + o1) = hi;
                *(uint32_t*)(Clo + o1) = lo;
            } else if (OUT_MODE == 2) {
                *(uint32_t*)(Chi + o0) = pack2h(v0, v1);
                *(uint32_t*)(Chi + o1) = pack2h(v2, v3);
            } else {
                *(float2*)(C + o0) = make_float2(v0, v1);
                *(float2*)(C + o1) = make_float2(v2, v3);
            }
        }
    }
}

// ---------------------------------------------------------------------------
// Register-resident FA2: Q, K, V, P all single fp16 — 1 MMA pass for S,
// 1 for PV. 64-row q-tiles, 128 threads (4 warps), occ 2, heavy CTAs first.
// (unchanged from round 12)
// ---------------------------------------------------------------------------
#define FPITCH 72
#define AQ_OFF 0
#define AKV    9216
#define KV_STAGE 18432
#define AK_OFF 0
#define AV_OFF 9216
#define ATT_SMEM (AKV + 2 * KV_STAGE)     // 46080

#define SFC 0.18033688f                   // 0.125 * log2(e)

__global__ __launch_bounds__(128, 2) void flash_attn_mma(
    const __half* __restrict__ qh_g, const __half* __restrict__ kh_g,
    const __half* __restrict__ vh_g,
    __half* __restrict__ ohi, __half* __restrict__ olo)
{
    extern __shared__ char dsm[];
    const int tid = threadIdx.x;
    const int w = tid >> 5;
    const int lane = tid & 31;
    const int g = lane >> 2;
    const int tq = lane & 3;
    const int qt = (int)(gridDim.x - 1) - (int)blockIdx.x;
    const int b = blockIdx.y >> 4;
    const int h = blockIdx.y & 15;
    const size_t rowbase = (size_t)b * PL * PD + (size_t)h * PDK;

    const uint32_t sQ = smem_u32(dsm + AQ_OFF);
    const uint32_t sKV = smem_u32(dsm + AKV);

    const int kr0 = tid >> 3;
    const int kc0 = (tid & 7) * 8;

    {
        const uint32_t sb = sKV;
#pragma unroll
        for (int it = 0; it < 4; ++it) {
            const int r = kr0 + it * 16;
            const uint32_t so = (uint32_t)(r * FPITCH + kc0) * 2;
            const size_t go = rowbase + (size_t)r * PD + kc0;
            CP_ASYNC16(sb + AK_OFF + so, (const char*)(kh_g + go));
            CP_ASYNC16(sb + AV_OFF + so, (const char*)(vh_g + go));
        }
        CP_COMMIT();
    }

#pragma unroll
    for (int it = 0; it < 4; ++it) {
        const int idx = tid + it * 128;
        const int r = idx >> 3;
        const int c = (idx & 7) * 8;
        const size_t go = rowbase + (size_t)(qt * 64 + r) * PD + c;
        const uint32_t so = (uint32_t)(r * FPITCH + c) * 2;
        *(uint4*)(dsm + AQ_OFF + so) = *(const uint4*)(qh_g + go);
    }
    CP_WAIT0();
    __syncthreads();

    uint32_t qh[4][4];
    {
        const int row = w * 16 + (lane & 7) + ((lane >> 3) & 1) * 8;
#pragma unroll
        for (int kb = 0; kb < 4; ++kb) {
            const int col = kb * 16 + ((lane >> 4) & 1) * 8;
            const uint32_t off = (uint32_t)(row * FPITCH + col) * 2;
            LDSM_X4(qh[kb][0], qh[kb][1], qh[kb][2], qh[kb][3], sQ + off);
        }
    }

    float oacc[8][4];
#pragma unroll
    for (int nb = 0; nb < 8; ++nb)
#pragma unroll
        for (int e = 0; e < 4; ++e) oacc[nb][e] = 0.0f;
    float m0 = -1.0e30f, m1 = -1.0e30f, l0 = 0.0f, l1 = 0.0f;

    const int jmax = qt;
    for (int j = 0; j <= jmax; ++j) {
        const int buf = j & 1;
        const uint32_t sb = sKV + buf * KV_STAGE;

        if (j < jmax) {
            const uint32_t nb_ = sKV + (buf ^ 1) * KV_STAGE;
#pragma unroll
            for (int it = 0; it < 4; ++it) {
                const int r = kr0 + it * 16;
                const uint32_t so = (uint32_t)(r * FPITCH + kc0) * 2;
                const size_t go = rowbase + (size_t)((j + 1) * 64 + r) * PD + kc0;
                CP_ASYNC16(nb_ + AK_OFF + so, (const char*)(kh_g + go));
                CP_ASYNC16(nb_ + AV_OFF + so, (const char*)(vh_g + go));
            }
            CP_COMMIT();
        }

        float sacc[8][4];
#pragma unroll
        for (int nb = 0; nb < 8; ++nb)
#pragma unroll
            for (int e = 0; e < 4; ++e) sacc[nb][e] = 0.0f;

#pragma unroll
        for (int kb = 0; kb < 4; ++kb) {
            uint32_t kh[8][2];
            const int kcol = kb * 16 + ((lane >> 3) & 1) * 8;
#pragma unroll
            for (int np = 0; np < 4; ++np) {
                const int krow = np * 16 + (lane & 7) + ((lane >> 4) & 1) * 8;
                const uint32_t off = (uint32_t)(krow * FPITCH + kcol) * 2;
                LDSM_X4(kh[2 * np][0], kh[2 * np][1], kh[2 * np + 1][0], kh[2 * np + 1][1],
                        sb + AK_OFF + off);
            }
#pragma unroll
            for (int nb = 0; nb < 8; ++nb)
                MMA16816(sacc[nb], qh[kb], kh[nb]);
        }

        if (j == qt) {
            const int row0 = qt * 64 + w * 16 + g;
            const int row1 = row0 + 8;
            const int cb = j * 64 + 2 * tq;
#pragma unroll
            for (int nb = 0; nb < 8; ++nb) {
                const int c0 = cb + nb * 8, c1 = c0 + 1;
                if (c0 > row0) sacc[nb][0] = -1.0e30f;
                if (c1 > row0) sacc[nb][1] = -1.0e30f;
                if (c0 > row1) sacc[nb][2] = -1.0e30f;
                if (c1 > row1) sacc[nb][3] = -1.0e30f;
            }
        }

        float mx0 = -1.0e30f, mx1 = -1.0e30f;
#pragma unroll
        for (int nb = 0; nb < 8; ++nb) {
            mx0 = fmaxf(mx0, fmaxf(sacc[nb][0], sacc[nb][1]));
            mx1 = fmaxf(mx1, fmaxf(sacc[nb][2], sacc[nb][3]));
        }
        mx0 = fmaxf(mx0, __shfl_xor_sync(0xffffffffu, mx0, 1));
        mx0 = fmaxf(mx0, __shfl_xor_sync(0xffffffffu, mx0, 2));
        mx1 = fmaxf(mx1, __shfl_xor_sync(0xffffffffu, mx1, 1));
        mx1 = fmaxf(mx1, __shfl_xor_sync(0xffffffffu, mx1, 2));

        const float mn0 = fmaxf(m0, mx0);
        const float mn1 = fmaxf(m1, mx1);
        const float em0 = mn0 * SFC;
        const float em1 = mn1 * SFC;
        const float cr0 = ex2f((m0 - mn0) * SFC);
        const float cr1 = ex2f((m1 - mn1) * SFC);
        m0 = mn0; m1 = mn1;

        float s0 = 0.0f, s1 = 0.0f;
#pragma unroll
        for (int nb = 0; nb < 8; ++nb) {
            float p0 = ex2f(fmaf(sacc[nb][0], SFC, -em0));
            float p1 = ex2f(fmaf(sacc[nb][1], SFC, -em0));
            float p2 = ex2f(fmaf(sacc[nb][2], SFC, -em1));
            float p3 = ex2f(fmaf(sacc[nb][3], SFC, -em1));
            sacc[nb][0] = p0; sacc[nb][1] = p1;
            sacc[nb][2] = p2; sacc[nb][3] = p3;
            s0 += p0 + p1; s1 += p2 + p3;
        }
        s0 += __shfl_xor_sync(0xffffffffu, s0, 1);
        s0 += __shfl_xor_sync(0xffffffffu, s0, 2);
        s1 += __shfl_xor_sync(0xffffffffu, s1, 1);
        s1 += __shfl_xor_sync(0xffffffffu, s1, 2);
        l0 = l0 * cr0 + s0;
        l1 = l1 * cr1 + s1;

#pragma unroll
        for (int nb = 0; nb < 8; ++nb) {
            oacc[nb][0] *= cr0; oacc[nb][1] *= cr0;
            oacc[nb][2] *= cr1; oacc[nb][3] *= cr1;
        }

        uint32_t pa[4][4];
#pragma unroll
        for (int kb = 0; kb < 4; ++kb) {
            pa[kb][0] = pack2h(sacc[2 * kb][0], sacc[2 * kb][1]);
            pa[kb][1] = pack2h(sacc[2 * kb][2], sacc[2 * kb][3]);
            pa[kb][2] = pack2h(sacc[2 * kb + 1][0], sacc[2 * kb + 1][1]);
            pa[kb][3] = pack2h(sacc[2 * kb + 1][2], sacc[2 * kb + 1][3]);
        }

#pragma unroll
        for (int kb = 0; kb < 4; ++kb) {
            uint32_t vh[8][2];
            const int vrow = kb * 16 + (lane & 7) + ((lane >> 3) & 1) * 8;
#pragma unroll
            for (int np = 0; np < 4; ++np) {
                const int vcol = np * 16 + ((lane >> 4) & 1) * 8;
                const uint32_t off = (uint32_t)(vrow * FPITCH + vcol) * 2;
                LDSM_X4_T(vh[2 * np][0], vh[2 * np][1], vh[2 * np + 1][0], vh[2 * np + 1][1],
                          sb + AV_OFF + off);
            }
#pragma unroll
            for (int nb = 0; nb < 8; ++nb)
                MMA16816(oacc[nb], pa[kb], vh[nb]);
        }

        if (j < jmax) {
            CP_WAIT0();
            __syncthreads();
        }
    }

    const float inv0 = 1.0f / l0;
    const float inv1 = 1.0f / l1;
    const int row0 = qt * 64 + w * 16 + g;
#pragma unroll
    for (int nb = 0; nb < 8; ++nb) {
        const int col = nb * 8 + 2 * tq;
        uint32_t hi, lo;
        split2h(oacc[nb][0] * inv0, oacc[nb][1] * inv0, hi, lo);
        const size_t g0 = rowbase + (size_t)row0 * PD + col;
        *(uint32_t*)(ohi + g0) = hi;
        *(uint32_t*)(olo + g0) = lo;
        split2h(oacc[nb][2] * inv1, oacc[nb][3] * inv1, hi, lo);
        const size_t g1 = rowbase + (size_t)(row0 + 8) * PD + col;
        *(uint32_t*)(ohi + g1) = hi;
        *(uint32_t*)(olo + g1) = lo;
    }
}

// ---------------------------------------------------------------------------
extern "C" void kernel_launch(void* const* d_in, const int* in_sizes, int n_in,
                              void* d_out, int out_size)
{
    const float* Q    = (const float*)d_in[0];
    const float* K    = (const float*)d_in[1];
    const float* V    = (const float*)d_in[2];
    const float* Wq_w = (const float*)d_in[4];
    const float* Wq_b = (const float*)d_in[5];
    const float* Wk_w = (const float*)d_in[6];
    const float* Wk_b = (const float*)d_in[7];
    const float* Wv_w = (const float*)d_in[8];
    const float* Wv_b = (const float*)d_in[9];
    const float* fc_w = (const float*)d_in[10];
    const float* fc_b = (const float*)d_in[11];
    float* out = (float*)d_out;

    __half *xhi, *xlo, *wh, *qh, *kh, *vh, *ahi, *alo;
    cudaGetSymbolAddress((void**)&xhi, g_xhi);
    cudaGetSymbolAddress((void**)&xlo, g_xlo);
    cudaGetSymbolAddress((void**)&wh, g_wh);
    cudaGetSymbolAddress((void**)&qh, g_qh);
    cudaGetSymbolAddress((void**)&kh, g_kh);
    cudaGetSymbolAddress((void**)&vh, g_vh);
    cudaGetSymbolAddress((void**)&ahi, g_ahi);
    cudaGetSymbolAddress((void**)&alo, g_alo);

    cudaFuncSetAttribute(gemm2_mma<0, true>,
                         cudaFuncAttributeMaxDynamicSharedMemorySize, G_SMEM);
    cudaFuncSetAttribute(gemm2_mma<2, true>,
                         cudaFuncAttributeMaxDynamicSharedMemorySize, G_SMEM);
    cudaFuncSetAttribute(gemm2_mma<2, false>,
                         cudaFuncAttributeMaxDynamicSharedMemorySize, G_SMEM);
    cudaFuncSetAttribute(flash_attn_mma,
                         cudaFuncAttributeMaxDynamicSharedMemorySize, ATT_SMEM);

    const int nA4 = MD / 4;
    const int nW4 = DD / 4;
    dim3 ggrid(PD / BGN, PM / BGM);   // (4, 32) = 128 CTAs, single wave

    // Splits (2 launches)
    split3_in<<<dim3(nA4 / 256, 1, 3), 256>>>(Q, K, V, xhi, xlo);
    split4_wh<<<dim3(nW4 / 256, 1, 4), 256>>>(Wq_w, Wk_w, Wv_w, fc_w, wh);

    // Projections: q/k single-pass (softmax-damped), v 2-pass (direct path)
    gemm2_mma<2, false><<<ggrid, 256, G_SMEM>>>(
        xhi, xlo, wh, Wq_b, nullptr, qh, nullptr, PD, PD);
    gemm2_mma<2, false><<<ggrid, 256, G_SMEM>>>(
        xhi + MD, xlo + MD, wh + DD, Wk_b, nullptr, kh, nullptr, PD, PD);
    gemm2_mma<2, true><<<ggrid, 256, G_SMEM>>>(
        xhi + 2 * (size_t)MD, xlo + 2 * (size_t)MD, wh + 2 * (size_t)DD, Wv_b,
        nullptr, vh, nullptr, PD, PD);

    // Attention (1 S pass, 1 PV pass)
    flash_attn_mma<<<dim3(PL / 64, PB * PH), 128, ATT_SMEM>>>(
        qh, kh, vh, ahi, alo);

    // Output projection (fp32 out, 2-pass — fully protected)
    gemm2_mma<0, true><<<ggrid, 256, G_SMEM>>>(
        ahi, alo, wh + 3 * (size_t)DD, fc_b, out, nullptr, nullptr, PD, PD);
}

// round 14
// speedup vs baseline: 2.1351x; 1.1755x over previous
#include <cuda_runtime.h>
#include <cuda_fp16.h>
#include <cstdint>
#include <math.h>

// Problem constants
#define PB 2
#define PL 2048
#define PD 1024
#define PH 16
#define PDK 64
#define PM (PB * PL)   // 4096
#define MD (PM * PD)
#define DD (PD * PD)

// Scratch (device globals), fp16 — hi planes only (all lo passes retired)
__device__ __half g_xh[3 * MD];    // Q,K,V inputs (fp16)
__device__ __half g_wh[4 * DD];    // Wq,Wk,Wv,fc weights (fp16)
__device__ __half g_qh[MD];        // q projection
__device__ __half g_kh[MD];        // k projection
__device__ __half g_vh[MD];        // v projection
__device__ __half g_ah[MD];        // attention output

// ---------------------------------------------------------------------------
// PTX helpers
// ---------------------------------------------------------------------------
__device__ __forceinline__ uint32_t smem_u32(const void* p) {
    uint32_t a;
    asm("{ .reg .u64 t; cvta.to.shared.u64 t, %1; cvt.u32.u64 %0, t; }"
        : "=r"(a) : "l"(p));
    return a;
}

#define MMA16816(c, a, b) \
    asm volatile("mma.sync.aligned.m16n8k16.row.col.f32.f16.f16.f32 " \
        "{%0,%1,%2,%3}, {%4,%5,%6,%7}, {%8,%9}, {%0,%1,%2,%3};" \
        : "+f"((c)[0]), "+f"((c)[1]), "+f"((c)[2]), "+f"((c)[3]) \
        : "r"((a)[0]), "r"((a)[1]), "r"((a)[2]), "r"((a)[3]), \
          "r"((b)[0]), "r"((b)[1]))

#define LDSM_X4(r0, r1, r2, r3, addr) \
    asm volatile("ldmatrix.sync.aligned.m8n8.x4.shared.b16 {%0,%1,%2,%3}, [%4];" \
        : "=r"(r0), "=r"(r1), "=r"(r2), "=r"(r3) : "r"(addr))

#define LDSM_X4_T(r0, r1, r2, r3, addr) \
    asm volatile("ldmatrix.sync.aligned.m8n8.x4.trans.shared.b16 {%0,%1,%2,%3}, [%4];" \
        : "=r"(r0), "=r"(r1), "=r"(r2), "=r"(r3) : "r"(addr))

#define CP_ASYNC16(smem, gptr) \
    asm volatile("cp.async.cg.shared.global [%0], [%1], 16;" \
        :: "r"(smem), "l"(gptr))
#define CP_COMMIT() asm volatile("cp.async.commit_group;" ::: "memory")
#define CP_WAIT0()  asm volatile("cp.async.wait_group 0;" ::: "memory")
#define CP_WAIT1()  asm volatile("cp.async.wait_group 1;" ::: "memory")

__device__ __forceinline__ float ex2f(float x) {
    float r;
    asm("ex2.approx.f32 %0, %1;" : "=f"(r) : "f"(x));
    return r;
}

__device__ __forceinline__ uint32_t pack2h(float a, float b) {
    __half2 H = __halves2half2(__float2half_rn(a), __float2half_rn(b));
    return *reinterpret_cast<uint32_t*>(&H);
}

// ---------------------------------------------------------------------------
// fp32 -> fp16 converts (batched over grid.z)
// ---------------------------------------------------------------------------
__global__ __launch_bounds__(256) void conv3_in(
    const float* __restrict__ x0, const float* __restrict__ x1,
    const float* __restrict__ x2, __half* xh)
{
    const int i = blockIdx.x * 256 + threadIdx.x;
    const int z = blockIdx.z;
    const float* x = (z == 0) ? x0 : (z == 1) ? x1 : x2;
    float4 v = reinterpret_cast<const float4*>(x)[i];
    reinterpret_cast<uint2*>(xh + (size_t)z * MD)[i] =
        make_uint2(pack2h(v.x, v.y), pack2h(v.z, v.w));
}

__global__ __launch_bounds__(256) void conv4_w(
    const float* __restrict__ x0, const float* __restrict__ x1,
    const float* __restrict__ x2, const float* __restrict__ x3,
    __half* wh)
{
    const int i = blockIdx.x * 256 + threadIdx.x;
    const int z = blockIdx.z;
    const float* x = (z == 0) ? x0 : (z == 1) ? x1 : (z == 2) ? x2 : x3;
    float4 v = reinterpret_cast<const float4*>(x)[i];
    reinterpret_cast<uint2*>(wh + (size_t)z * DD)[i] =
        make_uint2(pack2h(v.x, v.y), pack2h(v.z, v.w));
}

// ---------------------------------------------------------------------------
// mma.sync fp16 GEMM (single pass): C = Ah @ Wh^T + bias
// OUT_MODE: 0 = fp32, 2 = fp16.
// 128x256x32 tiles, 256 threads (2m x 4n warps), 3-stage cp.async.
// ---------------------------------------------------------------------------
#define BGM 128
#define BGN 256
#define BGK 32
#define GP 40
#define A_T (BGM * GP * 2)                // 10240 B
#define B_T (BGN * GP * 2)                // 20480 B
#define OFF_A 0
#define OFF_B A_T
#define STG_B (A_T + B_T)                 // 30720 B
#define NST 3
#define G_SMEM (NST * STG_B)              // 92160 B

template <int OUT_MODE>
__global__ __launch_bounds__(256, 1) void gemm1_mma(
    const __half* __restrict__ Ah, const __half* __restrict__ Wh,
    const float* __restrict__ bias, float* __restrict__ C,
    __half* __restrict__ Ch, int K, int N)
{
    extern __shared__ char dsm[];
    __shared__ float sbias[BGN];

    const int tid = threadIdx.x;
    const int w = tid >> 5;
    const int lane = tid & 31;
    const int wm = w >> 2;
    const int wn = w & 3;
    const int g = lane >> 2;
    const int tq = lane & 3;
    const int bm = blockIdx.y * BGM;
    const int bn = blockIdx.x * BGN;
    const uint32_t sbase = smem_u32(dsm);

    const int lr = tid >> 2;
    const int lc = (tid & 3) * 8;

    auto issue = [&](int c, int buf) {
        const uint32_t sb = sbase + buf * STG_B;
        const int kofs = c * BGK;
#pragma unroll
        for (int it = 0; it < 2; ++it) {
            const int r = lr + it * 64;
            const uint32_t so = (uint32_t)(r * GP + lc) * 2;
            const size_t go = (size_t)(bm + r) * K + kofs + lc;
            CP_ASYNC16(sb + OFF_A + so, (const char*)(Ah + go));
        }
#pragma unroll
        for (int it = 0; it < 4; ++it) {
            const int r = lr + it * 64;
            const uint32_t so = (uint32_t)(r * GP + lc) * 2;
            const size_t go = (size_t)(bn + r) * K + kofs + lc;
            CP_ASYNC16(sb + OFF_B + so, (const char*)(Wh + go));
        }
    };

    issue(0, 0); CP_COMMIT();
    issue(1, 1); CP_COMMIT();

    sbias[tid] = bias[bn + tid];

    float acc[4][8][4];
#pragma unroll
    for (int mi = 0; mi < 4; ++mi)
#pragma unroll
        for (int nb = 0; nb < 8; ++nb)
#pragma unroll
            for (int e = 0; e < 4; ++e) acc[mi][nb][e] = 0.0f;

    const int a_r = (lane & 7) + ((lane >> 3) & 1) * 8;
    const int a_c = ((lane >> 4) & 1) * 8;
    const int b_r = (lane & 7) + ((lane >> 4) & 1) * 8;
    const int b_c = ((lane >> 3) & 1) * 8;

    const int nchunk = K / BGK;   // 32
    for (int c = 0; c < nchunk; ++c) {
        if (c + 1 < nchunk) CP_WAIT1(); else CP_WAIT0();
        __syncthreads();
        if (c + 2 < nchunk) { issue(c + 2, (c + 2) % NST); CP_COMMIT(); }

        const uint32_t sb = sbase + (c % NST) * STG_B;
#pragma unroll
        for (int kk = 0; kk < 2; ++kk) {
            uint32_t ah[4][4];
#pragma unroll
            for (int mi = 0; mi < 4; ++mi) {
                const uint32_t off =
                    (uint32_t)((wm * 64 + mi * 16 + a_r) * GP + kk * 16 + a_c) * 2;
                LDSM_X4(ah[mi][0], ah[mi][1], ah[mi][2], ah[mi][3],
                        sb + OFF_A + off);
            }
            uint32_t bh[8][2];
#pragma unroll
            for (int np = 0; np < 4; ++np) {
                const uint32_t off =
                    (uint32_t)((wn * 64 + np * 16 + b_r) * GP + kk * 16 + b_c) * 2;
                LDSM_X4(bh[2 * np][0], bh[2 * np][1], bh[2 * np + 1][0], bh[2 * np + 1][1],
                        sb + OFF_B + off);
            }
#pragma unroll
            for (int mi = 0; mi < 4; ++mi)
#pragma unroll
                for (int nb = 0; nb < 8; ++nb)
                    MMA16816(acc[mi][nb], ah[mi], bh[nb]);
        }
    }

    // epilogue
#pragma unroll
    for (int mi = 0; mi < 4; ++mi) {
        const int row0 = bm + wm * 64 + mi * 16 + g;
        const int row1 = row0 + 8;
#pragma unroll
        for (int nb = 0; nb < 8; ++nb) {
            const int coll = wn * 64 + nb * 8 + 2 * tq;
            const float b0 = sbias[coll];
            const float b1 = sbias[coll + 1];
            const float v0 = acc[mi][nb][0] + b0;
            const float v1 = acc[mi][nb][1] + b1;
            const float v2 = acc[mi][nb][2] + b0;
            const float v3 = acc[mi][nb][3] + b1;
            const size_t o0 = (size_t)row0 * N + bn + coll;
            const size_t o1 = (size_t)row1 * N + bn + coll;
            if (OUT_MODE == 2) {
                *(uint32_t*)(Ch + o0) = pack2h(v0, v1);
                *(uint32_t*)(Ch + o1) = pack2h(v2, v3);
            } else {
                *(float2*)(C + o0) = make_float2(v0, v1);
                *(float2*)(C + o1) = make_float2(v2, v3);
            }
        }
    }
}

// ---------------------------------------------------------------------------
// Register-resident FA2: all operands single fp16, 1 S pass + 1 PV pass.
// 64-row q-tiles, 128 threads (4 warps), occ 2, heavy CTAs first.
// ---------------------------------------------------------------------------
#define FPITCH 72
#define AQ_OFF 0
#define AKV    9216
#define KV_STAGE 18432
#define AK_OFF 0
#define AV_OFF 9216
#define ATT_SMEM (AKV + 2 * KV_STAGE)     // 46080

#define SFC 0.18033688f                   // 0.125 * log2(e)

__global__ __launch_bounds__(128, 2) void flash_attn_mma(
    const __half* __restrict__ qh_g, const __half* __restrict__ kh_g,
    const __half* __restrict__ vh_g, __half* __restrict__ oh_g)
{
    extern __shared__ char dsm[];
    const int tid = threadIdx.x;
    const int w = tid >> 5;
    const int lane = tid & 31;
    const int g = lane >> 2;
    const int tq = lane & 3;
    const int qt = (int)(gridDim.x - 1) - (int)blockIdx.x;
    const int b = blockIdx.y >> 4;
    const int h = blockIdx.y & 15;
    const size_t rowbase = (size_t)b * PL * PD + (size_t)h * PDK;

    const uint32_t sQ = smem_u32(dsm + AQ_OFF);
    const uint32_t sKV = smem_u32(dsm + AKV);

    const int kr0 = tid >> 3;
    const int kc0 = (tid & 7) * 8;

    {
        const uint32_t sb = sKV;
#pragma unroll
        for (int it = 0; it < 4; ++it) {
            const int r = kr0 + it * 16;
            const uint32_t so = (uint32_t)(r * FPITCH + kc0) * 2;
            const size_t go = rowbase + (size_t)r * PD + kc0;
            CP_ASYNC16(sb + AK_OFF + so, (const char*)(kh_g + go));
            CP_ASYNC16(sb + AV_OFF + so, (const char*)(vh_g + go));
        }
        CP_COMMIT();
    }

#pragma unroll
    for (int it = 0; it < 4; ++it) {
        const int idx = tid + it * 128;
        const int r = idx >> 3;
        const int c = (idx & 7) * 8;
        const size_t go = rowbase + (size_t)(qt * 64 + r) * PD + c;
        const uint32_t so = (uint32_t)(r * FPITCH + c) * 2;
        *(uint4*)(dsm + AQ_OFF + so) = *(const uint4*)(qh_g + go);
    }
    CP_WAIT0();
    __syncthreads();

    uint32_t qh[4][4];
    {
        const int row = w * 16 + (lane & 7) + ((lane >> 3) & 1) * 8;
#pragma unroll
        for (int kb = 0; kb < 4; ++kb) {
            const int col = kb * 16 + ((lane >> 4) & 1) * 8;
            const uint32_t off = (uint32_t)(row * FPITCH + col) * 2;
            LDSM_X4(qh[kb][0], qh[kb][1], qh[kb][2], qh[kb][3], sQ + off);
        }
    }

    float oacc[8][4];
#pragma unroll
    for (int nb = 0; nb < 8; ++nb)
#pragma unroll
        for (int e = 0; e < 4; ++e) oacc[nb][e] = 0.0f;
    float m0 = -1.0e30f, m1 = -1.0e30f, l0 = 0.0f, l1 = 0.0f;

    const int jmax = qt;
    for (int j = 0; j <= jmax; ++j) {
        const int buf = j & 1;
        const uint32_t sb = sKV + buf * KV_STAGE;

        if (j < jmax) {
            const uint32_t nb_ = sKV + (buf ^ 1) * KV_STAGE;
#pragma unroll
            for (int it = 0; it < 4; ++it) {
                const int r = kr0 + it * 16;
                const uint32_t so = (uint32_t)(r * FPITCH + kc0) * 2;
                const size_t go = rowbase + (size_t)((j + 1) * 64 + r) * PD + kc0;
                CP_ASYNC16(nb_ + AK_OFF + so, (const char*)(kh_g + go));
                CP_ASYNC16(nb_ + AV_OFF + so, (const char*)(vh_g + go));
            }
            CP_COMMIT();
        }

        float sacc[8][4];
#pragma unroll
        for (int nb = 0; nb < 8; ++nb)
#pragma unroll
            for (int e = 0; e < 4; ++e) sacc[nb][e] = 0.0f;

#pragma unroll
        for (int kb = 0; kb < 4; ++kb) {
            uint32_t kh[8][2];
            const int kcol = kb * 16 + ((lane >> 3) & 1) * 8;
#pragma unroll
            for (int np = 0; np < 4; ++np) {
                const int krow = np * 16 + (lane & 7) + ((lane >> 4) & 1) * 8;
                const uint32_t off = (uint32_t)(krow * FPITCH + kcol) * 2;
                LDSM_X4(kh[2 * np][0], kh[2 * np][1], kh[2 * np + 1][0], kh[2 * np + 1][1],
                        sb + AK_OFF + off);
            }
#pragma unroll
            for (int nb = 0; nb < 8; ++nb)
                MMA16816(sacc[nb], qh[kb], kh[nb]);
        }

        if (j == qt) {
            const int row0 = qt * 64 + w * 16 + g;
            const int row1 = row0 + 8;
            const int cb = j * 64 + 2 * tq;
#pragma unroll
            for (int nb = 0; nb < 8; ++nb) {
                const int c0 = cb + nb * 8, c1 = c0 + 1;
                if (c0 > row0) sacc[nb][0] = -1.0e30f;
                if (c1 > row0) sacc[nb][1] = -1.0e30f;
                if (c0 > row1) sacc[nb][2] = -1.0e30f;
                if (c1 > row1) sacc[nb][3] = -1.0e30f;
            }
        }

        float mx0 = -1.0e30f, mx1 = -1.0e30f;
#pragma unroll
        for (int nb = 0; nb < 8; ++nb) {
            mx0 = fmaxf(mx0, fmaxf(sacc[nb][0], sacc[nb][1]));
            mx1 = fmaxf(mx1, fmaxf(sacc[nb][2], sacc[nb][3]));
        }
        mx0 = fmaxf(mx0, __shfl_xor_sync(0xffffffffu, mx0, 1));
        mx0 = fmaxf(mx0, __shfl_xor_sync(0xffffffffu, mx0, 2));
        mx1 = fmaxf(mx1, __shfl_xor_sync(0xffffffffu, mx1, 1));
        mx1 = fmaxf(mx1, __shfl_xor_sync(0xffffffffu, mx1, 2));

        const float mn0 = fmaxf(m0, mx0);
        const float mn1 = fmaxf(m1, mx1);
        const float em0 = mn0 * SFC;
        const float em1 = mn1 * SFC;
        const float cr0 = ex2f((m0 - mn0) * SFC);
        const float cr1 = ex2f((m1 - mn1) * SFC);
        m0 = mn0; m1 = mn1;

        float s0 = 0.0f, s1 = 0.0f;
#pragma unroll
        for (int nb = 0; nb < 8; ++nb) {
            float p0 = ex2f(fmaf(sacc[nb][0], SFC, -em0));
            float p1 = ex2f(fmaf(sacc[nb][1], SFC, -em0));
            float p2 = ex2f(fmaf(sacc[nb][2], SFC, -em1));
            float p3 = ex2f(fmaf(sacc[nb][3], SFC, -em1));
            sacc[nb][0] = p0; sacc[nb][1] = p1;
            sacc[nb][2] = p2; sacc[nb][3] = p3;
            s0 += p0 + p1; s1 += p2 + p3;
        }
        s0 += __shfl_xor_sync(0xffffffffu, s0, 1);
        s0 += __shfl_xor_sync(0xffffffffu, s0, 2);
        s1 += __shfl_xor_sync(0xffffffffu, s1, 1);
        s1 += __shfl_xor_sync(0xffffffffu, s1, 2);
        l0 = l0 * cr0 + s0;
        l1 = l1 * cr1 + s1;

#pragma unroll
        for (int nb = 0; nb < 8; ++nb) {
            oacc[nb][0] *= cr0; oacc[nb][1] *= cr0;
            oacc[nb][2] *= cr1; oacc[nb][3] *= cr1;
        }

        uint32_t pa[4][4];
#pragma unroll
        for (int kb = 0; kb < 4; ++kb) {
            pa[kb][0] = pack2h(sacc[2 * kb][0], sacc[2 * kb][1]);
            pa[kb][1] = pack2h(sacc[2 * kb][2], sacc[2 * kb][3]);
            pa[kb][2] = pack2h(sacc[2 * kb + 1][0], sacc[2 * kb + 1][1]);
            pa[kb][3] = pack2h(sacc[2 * kb + 1][2], sacc[2 * kb + 1][3]);
        }

#pragma unroll
        for (int kb = 0; kb < 4; ++kb) {
            uint32_t vh[8][2];
            const int vrow = kb * 16 + (lane & 7) + ((lane >> 3) & 1) * 8;
#pragma unroll
            for (int np = 0; np < 4; ++np) {
                const int vcol = np * 16 + ((lane >> 4) & 1) * 8;
                const uint32_t off = (uint32_t)(vrow * FPITCH + vcol) * 2;
                LDSM_X4_T(vh[2 * np][0], vh[2 * np][1], vh[2 * np + 1][0], vh[2 * np + 1][1],
                          sb + AV_OFF + off);
            }
#pragma unroll
            for (int nb = 0; nb < 8; ++nb)
                MMA16816(oacc[nb], pa[kb], vh[nb]);
        }

        if (j < jmax) {
            CP_WAIT0();
            __syncthreads();
        }
    }

    // epilogue: normalize, fp16, store
    const float inv0 = 1.0f / l0;
    const float inv1 = 1.0f / l1;
    const int row0 = qt * 64 + w * 16 + g;
#pragma unroll
    for (int nb = 0; nb < 8; ++nb) {
        const int col = nb * 8 + 2 * tq;
        const size_t g0 = rowbase + (size_t)row0 * PD + col;
        const size_t g1 = rowbase + (size_t)(row0 + 8) * PD + col;
        *(uint32_t*)(oh_g + g0) = pack2h(oacc[nb][0] * inv0, oacc[nb][1] * inv0);
        *(uint32_t*)(oh_g + g1) = pack2h(oacc[nb][2] * inv1, oacc[nb][3] * inv1);
    }
}

// ---------------------------------------------------------------------------
extern "C" void kernel_launch(void* const* d_in, const int* in_sizes, int n_in,
                              void* d_out, int out_size)
{
    const float* Q    = (const float*)d_in[0];
    const float* K    = (const float*)d_in[1];
    const float* V    = (const float*)d_in[2];
    const float* Wq_w = (const float*)d_in[4];
    const float* Wq_b = (const float*)d_in[5];
    const float* Wk_w = (const float*)d_in[6];
    const float* Wk_b = (const float*)d_in[7];
    const float* Wv_w = (const float*)d_in[8];
    const float* Wv_b = (const float*)d_in[9];
    const float* fc_w = (const float*)d_in[10];
    const float* fc_b = (const float*)d_in[11];
    float* out = (float*)d_out;

    __half *xh, *wh, *qh, *kh, *vh, *ah;
    cudaGetSymbolAddress((void**)&xh, g_xh);
    cudaGetSymbolAddress((void**)&wh, g_wh);
    cudaGetSymbolAddress((void**)&qh, g_qh);
    cudaGetSymbolAddress((void**)&kh, g_kh);
    cudaGetSymbolAddress((void**)&vh, g_vh);
    cudaGetSymbolAddress((void**)&ah, g_ah);

    cudaFuncSetAttribute(gemm1_mma<0>,
                         cudaFuncAttributeMaxDynamicSharedMemorySize, G_SMEM);
    cudaFuncSetAttribute(gemm1_mma<2>,
                         cudaFuncAttributeMaxDynamicSharedMemorySize, G_SMEM);
    cudaFuncSetAttribute(flash_attn_mma,
                         cudaFuncAttributeMaxDynamicSharedMemorySize, ATT_SMEM);

    const int nA4 = MD / 4;
    const int nW4 = DD / 4;
    dim3 ggrid(PD / BGN, PM / BGM);   // (4, 32) = 128 CTAs, single wave

    // Converts (2 launches)
    conv3_in<<<dim3(nA4 / 256, 1, 3), 256>>>(Q, K, V, xh);
    conv4_w<<<dim3(nW4 / 256, 1, 4), 256>>>(Wq_w, Wk_w, Wv_w, fc_w, wh);

    // Projections (all single-pass fp16)
    gemm1_mma<2><<<ggrid, 256, G_SMEM>>>(xh, wh, Wq_b, nullptr, qh, PD, PD);
    gemm1_mma<2><<<ggrid, 256, G_SMEM>>>(xh + MD, wh + DD, Wk_b, nullptr, kh, PD, PD);
    gemm1_mma<2><<<ggrid, 256, G_SMEM>>>(xh + 2 * (size_t)MD, wh + 2 * (size_t)DD,
                                         Wv_b, nullptr, vh, PD, PD);

    // Attention
    flash_attn_mma<<<dim3(PL / 64, PB * PH), 128, ATT_SMEM>>>(qh, kh, vh, ah);

    // Output projection (fp32 out)
    gemm1_mma<0><<<ggrid, 256, G_SMEM>>>(ah, wh + 3 * (size_t)DD, fc_b,
                                         out, nullptr, PD, PD);
}

// round 15
// speedup vs baseline: 2.2199x; 1.0397x over previous
#include <cuda_runtime.h>
#include <cuda_fp16.h>
#include <cstdint>
#include <math.h>

// Problem constants
#define PB 2
#define PL 2048
#define PD 1024
#define PH 16
#define PDK 64
#define PM (PB * PL)   // 4096
#define MD (PM * PD)
#define DD (PD * PD)

// Scratch (device globals), fp16
__device__ __half g_xh[3 * MD];    // Q,K,V inputs (fp16)
__device__ __half g_wh[4 * DD];    // Wq,Wk,Wv,fc weights (fp16)
__device__ __half g_qh[MD];        // q projection
__device__ __half g_kh[MD];        // k projection
__device__ __half g_vh[MD];        // v projection
__device__ __half g_ah[MD];        // attention output

// ---------------------------------------------------------------------------
// PTX helpers
// ---------------------------------------------------------------------------
__device__ __forceinline__ uint32_t smem_u32(const void* p) {
    uint32_t a;
    asm("{ .reg .u64 t; cvta.to.shared.u64 t, %1; cvt.u32.u64 %0, t; }"
        : "=r"(a) : "l"(p));
    return a;
}

#define MMA16816(c, a, b) \
    asm volatile("mma.sync.aligned.m16n8k16.row.col.f32.f16.f16.f32 " \
        "{%0,%1,%2,%3}, {%4,%5,%6,%7}, {%8,%9}, {%0,%1,%2,%3};" \
        : "+f"((c)[0]), "+f"((c)[1]), "+f"((c)[2]), "+f"((c)[3]) \
        : "r"((a)[0]), "r"((a)[1]), "r"((a)[2]), "r"((a)[3]), \
          "r"((b)[0]), "r"((b)[1]))

#define LDSM_X4(r0, r1, r2, r3, addr) \
    asm volatile("ldmatrix.sync.aligned.m8n8.x4.shared.b16 {%0,%1,%2,%3}, [%4];" \
        : "=r"(r0), "=r"(r1), "=r"(r2), "=r"(r3) : "r"(addr))

#define LDSM_X4_T(r0, r1, r2, r3, addr) \
    asm volatile("ldmatrix.sync.aligned.m8n8.x4.trans.shared.b16 {%0,%1,%2,%3}, [%4];" \
        : "=r"(r0), "=r"(r1), "=r"(r2), "=r"(r3) : "r"(addr))

#define CP_ASYNC16(smem, gptr) \
    asm volatile("cp.async.cg.shared.global [%0], [%1], 16;" \
        :: "r"(smem), "l"(gptr))
#define CP_COMMIT() asm volatile("cp.async.commit_group;" ::: "memory")
#define CP_WAIT0()  asm volatile("cp.async.wait_group 0;" ::: "memory")
#define CP_WAIT1()  asm volatile("cp.async.wait_group 1;" ::: "memory")

__device__ __forceinline__ float ex2f(float x) {
    float r;
    asm("ex2.approx.f32 %0, %1;" : "=f"(r) : "f"(x));
    return r;
}

__device__ __forceinline__ uint32_t pack2h(float a, float b) {
    __half2 H = __halves2half2(__float2half_rn(a), __float2half_rn(b));
    return *reinterpret_cast<uint32_t*>(&H);
}

// ---------------------------------------------------------------------------
// fp32 -> fp16 converts (batched over grid.z)
// ---------------------------------------------------------------------------
__global__ __launch_bounds__(256) void conv3_in(
    const float* __restrict__ x0, const float* __restrict__ x1,
    const float* __restrict__ x2, __half* xh)
{
    const int i = blockIdx.x * 256 + threadIdx.x;
    const int z = blockIdx.z;
    const float* x = (z == 0) ? x0 : (z == 1) ? x1 : x2;
    float4 v = reinterpret_cast<const float4*>(x)[i];
    reinterpret_cast<uint2*>(xh + (size_t)z * MD)[i] =
        make_uint2(pack2h(v.x, v.y), pack2h(v.z, v.w));
}

__global__ __launch_bounds__(256) void conv4_w(
    const float* __restrict__ x0, const float* __restrict__ x1,
    const float* __restrict__ x2, const float* __restrict__ x3,
    __half* wh)
{
    const int i = blockIdx.x * 256 + threadIdx.x;
    const int z = blockIdx.z;
    const float* x = (z == 0) ? x0 : (z == 1) ? x1 : (z == 2) ? x2 : x3;
    float4 v = reinterpret_cast<const float4*>(x)[i];
    reinterpret_cast<uint2*>(wh + (size_t)z * DD)[i] =
        make_uint2(pack2h(v.x, v.y), pack2h(v.z, v.w));
}

// ---------------------------------------------------------------------------
// mma.sync fp16 GEMM (single pass), occupancy 2: C = Ah @ Wh^T + bias
// 128x128x32 tiles, 128 threads (2m x 2n warps, 64x64 warp tile),
// 3-stage cp.async. OUT_MODE: 0 = fp32, 2 = fp16.
// ---------------------------------------------------------------------------
#define BGM 128
#define BGN 128
#define BGK 32
#define GP 40
#define A_T (BGM * GP * 2)                // 10240 B
#define B_T (BGN * GP * 2)                // 10240 B
#define OFF_A 0
#define OFF_B A_T
#define STG_B (A_T + B_T)                 // 20480 B
#define NST 3
#define G_SMEM (NST * STG_B)              // 61440 B per CTA (x2 CTAs = 120K)

template <int OUT_MODE>
__global__ __launch_bounds__(128, 2) void gemm1_mma(
    const __half* __restrict__ Ah, const __half* __restrict__ Wh,
    const float* __restrict__ bias, float* __restrict__ C,
    __half* __restrict__ Ch, int K, int N)
{
    extern __shared__ char dsm[];
    __shared__ float sbias[BGN];

    const int tid = threadIdx.x;
    const int w = tid >> 5;
    const int lane = tid & 31;
    const int wm = w >> 1;          // 0..1
    const int wn = w & 1;           // 0..1
    const int g = lane >> 2;
    const int tq = lane & 3;
    const int bm = blockIdx.y * BGM;
    const int bn = blockIdx.x * BGN;
    const uint32_t sbase = smem_u32(dsm);

    // cp.async mapping: 128 rows x 32 cols per array, 128 threads, 4 iters
    const int lr = tid >> 2;              // 0..31
    const int lc = (tid & 3) * 8;         // 0,8,16,24

    auto issue = [&](int c, int buf) {
        const uint32_t sb = sbase + buf * STG_B;
        const int kofs = c * BGK;
#pragma unroll
        for (int it = 0; it < 4; ++it) {
            const int r = lr + it * 32;
            const uint32_t so = (uint32_t)(r * GP + lc) * 2;
            const size_t goA = (size_t)(bm + r) * K + kofs + lc;
            const size_t goB = (size_t)(bn + r) * K + kofs + lc;
            CP_ASYNC16(sb + OFF_A + so, (const char*)(Ah + goA));
            CP_ASYNC16(sb + OFF_B + so, (const char*)(Wh + goB));
        }
    };

    issue(0, 0); CP_COMMIT();
    issue(1, 1); CP_COMMIT();

    sbias[tid] = bias[bn + tid];   // blockDim == BGN == 128

    float acc[4][8][4];
#pragma unroll
    for (int mi = 0; mi < 4; ++mi)
#pragma unroll
        for (int nb = 0; nb < 8; ++nb)
#pragma unroll
            for (int e = 0; e < 4; ++e) acc[mi][nb][e] = 0.0f;

    const int a_r = (lane & 7) + ((lane >> 3) & 1) * 8;
    const int a_c = ((lane >> 4) & 1) * 8;
    const int b_r = (lane & 7) + ((lane >> 4) & 1) * 8;
    const int b_c = ((lane >> 3) & 1) * 8;

    const int nchunk = K / BGK;   // 32
    for (int c = 0; c < nchunk; ++c) {
        if (c + 1 < nchunk) CP_WAIT1(); else CP_WAIT0();
        __syncthreads();
        if (c + 2 < nchunk) { issue(c + 2, (c + 2) % NST); CP_COMMIT(); }

        const uint32_t sb = sbase + (c % NST) * STG_B;
#pragma unroll
        for (int kk = 0; kk < 2; ++kk) {
            uint32_t ah[4][4];
#pragma unroll
            for (int mi = 0; mi < 4; ++mi) {
                const uint32_t off =
                    (uint32_t)((wm * 64 + mi * 16 + a_r) * GP + kk * 16 + a_c) * 2;
                LDSM_X4(ah[mi][0], ah[mi][1], ah[mi][2], ah[mi][3],
                        sb + OFF_A + off);
            }
            uint32_t bh[8][2];
#pragma unroll
            for (int np = 0; np < 4; ++np) {
                const uint32_t off =
                    (uint32_t)((wn * 64 + np * 16 + b_r) * GP + kk * 16 + b_c) * 2;
                LDSM_X4(bh[2 * np][0], bh[2 * np][1], bh[2 * np + 1][0], bh[2 * np + 1][1],
                        sb + OFF_B + off);
            }
#pragma unroll
            for (int mi = 0; mi < 4; ++mi)
#pragma unroll
                for (int nb = 0; nb < 8; ++nb)
                    MMA16816(acc[mi][nb], ah[mi], bh[nb]);
        }
    }

    // epilogue
#pragma unroll
    for (int mi = 0; mi < 4; ++mi) {
        const int row0 = bm + wm * 64 + mi * 16 + g;
        const int row1 = row0 + 8;
#pragma unroll
        for (int nb = 0; nb < 8; ++nb) {
            const int coll = wn * 64 + nb * 8 + 2 * tq;
            const float b0 = sbias[coll];
            const float b1 = sbias[coll + 1];
            const float v0 = acc[mi][nb][0] + b0;
            const float v1 = acc[mi][nb][1] + b1;
            const float v2 = acc[mi][nb][2] + b0;
            const float v3 = acc[mi][nb][3] + b1;
            const size_t o0 = (size_t)row0 * N + bn + coll;
            const size_t o1 = (size_t)row1 * N + bn + coll;
            if (OUT_MODE == 2) {
                *(uint32_t*)(Ch + o0) = pack2h(v0, v1);
                *(uint32_t*)(Ch + o1) = pack2h(v2, v3);
            } else {
                *(float2*)(C + o0) = make_float2(v0, v1);
                *(float2*)(C + o1) = make_float2(v2, v3);
            }
        }
    }
}

// ---------------------------------------------------------------------------
// Register-resident FA2 (unchanged from round 14): all single fp16,
// 1 S pass + 1 PV pass, 64-row q-tiles, 128 threads, occ 2.
// ---------------------------------------------------------------------------
#define FPITCH 72
#define AQ_OFF 0
#define AKV    9216
#define KV_STAGE 18432
#define AK_OFF 0
#define AV_OFF 9216
#define ATT_SMEM (AKV + 2 * KV_STAGE)     // 46080

#define SFC 0.18033688f                   // 0.125 * log2(e)

__global__ __launch_bounds__(128, 2) void flash_attn_mma(
    const __half* __restrict__ qh_g, const __half* __restrict__ kh_g,
    const __half* __restrict__ vh_g, __half* __restrict__ oh_g)
{
    extern __shared__ char dsm[];
    const int tid = threadIdx.x;
    const int w = tid >> 5;
    const int lane = tid & 31;
    const int g = lane >> 2;
    const int tq = lane & 3;
    const int qt = (int)(gridDim.x - 1) - (int)blockIdx.x;
    const int b = blockIdx.y >> 4;
    const int h = blockIdx.y & 15;
    const size_t rowbase = (size_t)b * PL * PD + (size_t)h * PDK;

    const uint32_t sQ = smem_u32(dsm + AQ_OFF);
    const uint32_t sKV = smem_u32(dsm + AKV);

    const int kr0 = tid >> 3;
    const int kc0 = (tid & 7) * 8;

    {
        const uint32_t sb = sKV;
#pragma unroll
        for (int it = 0; it < 4; ++it) {
            const int r = kr0 + it * 16;
            const uint32_t so = (uint32_t)(r * FPITCH + kc0) * 2;
            const size_t go = rowbase + (size_t)r * PD + kc0;
            CP_ASYNC16(sb + AK_OFF + so, (const char*)(kh_g + go));
            CP_ASYNC16(sb + AV_OFF + so, (const char*)(vh_g + go));
        }
        CP_COMMIT();
    }

#pragma unroll
    for (int it = 0; it < 4; ++it) {
        const int idx = tid + it * 128;
        const int r = idx >> 3;
        const int c = (idx & 7) * 8;
        const size_t go = rowbase + (size_t)(qt * 64 + r) * PD + c;
        const uint32_t so = (uint32_t)(r * FPITCH + c) * 2;
        *(uint4*)(dsm + AQ_OFF + so) = *(const uint4*)(qh_g + go);
    }
    CP_WAIT0();
    __syncthreads();

    uint32_t qh[4][4];
    {
        const int row = w * 16 + (lane & 7) + ((lane >> 3) & 1) * 8;
#pragma unroll
        for (int kb = 0; kb < 4; ++kb) {
            const int col = kb * 16 + ((lane >> 4) & 1) * 8;
            const uint32_t off = (uint32_t)(row * FPITCH + col) * 2;
            LDSM_X4(qh[kb][0], qh[kb][1], qh[kb][2], qh[kb][3], sQ + off);
        }
    }

    float oacc[8][4];
#pragma unroll
    for (int nb = 0; nb < 8; ++nb)
#pragma unroll
        for (int e = 0; e < 4; ++e) oacc[nb][e] = 0.0f;
    float m0 = -1.0e30f, m1 = -1.0e30f, l0 = 0.0f, l1 = 0.0f;

    const int jmax = qt;
    for (int j = 0; j <= jmax; ++j) {
        const int buf = j & 1;
        const uint32_t sb = sKV + buf * KV_STAGE;

        if (j < jmax) {
            const uint32_t nb_ = sKV + (buf ^ 1) * KV_STAGE;
#pragma unroll
            for (int it = 0; it < 4; ++it) {
                const int r = kr0 + it * 16;
                const uint32_t so = (uint32_t)(r * FPITCH + kc0) * 2;
                const size_t go = rowbase + (size_t)((j + 1) * 64 + r) * PD + kc0;
                CP_ASYNC16(nb_ + AK_OFF + so, (const char*)(kh_g + go));
                CP_ASYNC16(nb_ + AV_OFF + so, (const char*)(vh_g + go));
            }
            CP_COMMIT();
        }

        float sacc[8][4];
#pragma unroll
        for (int nb = 0; nb < 8; ++nb)
#pragma unroll
            for (int e = 0; e < 4; ++e) sacc[nb][e] = 0.0f;

#pragma unroll
        for (int kb = 0; kb < 4; ++kb) {
            uint32_t kh[8][2];
            const int kcol = kb * 16 + ((lane >> 3) & 1) * 8;
#pragma unroll
            for (int np = 0; np < 4; ++np) {
                const int krow = np * 16 + (lane & 7) + ((lane >> 4) & 1) * 8;
                const uint32_t off = (uint32_t)(krow * FPITCH + kcol) * 2;
                LDSM_X4(kh[2 * np][0], kh[2 * np][1], kh[2 * np + 1][0], kh[2 * np + 1][1],
                        sb + AK_OFF + off);
            }
#pragma unroll
            for (int nb = 0; nb < 8; ++nb)
                MMA16816(sacc[nb], qh[kb], kh[nb]);
        }

        if (j == qt) {
            const int row0 = qt * 64 + w * 16 + g;
            const int row1 = row0 + 8;
            const int cb = j * 64 + 2 * tq;
#pragma unroll
            for (int nb = 0; nb < 8; ++nb) {
                const int c0 = cb + nb * 8, c1 = c0 + 1;
                if (c0 > row0) sacc[nb][0] = -1.0e30f;
                if (c1 > row0) sacc[nb][1] = -1.0e30f;
                if (c0 > row1) sacc[nb][2] = -1.0e30f;
                if (c1 > row1) sacc[nb][3] = -1.0e30f;
            }
        }

        float mx0 = -1.0e30f, mx1 = -1.0e30f;
#pragma unroll
        for (int nb = 0; nb < 8; ++nb) {
            mx0 = fmaxf(mx0, fmaxf(sacc[nb][0], sacc[nb][1]));
            mx1 = fmaxf(mx1, fmaxf(sacc[nb][2], sacc[nb][3]));
        }
        mx0 = fmaxf(mx0, __shfl_xor_sync(0xffffffffu, mx0, 1));
        mx0 = fmaxf(mx0, __shfl_xor_sync(0xffffffffu, mx0, 2));
        mx1 = fmaxf(mx1, __shfl_xor_sync(0xffffffffu, mx1, 1));
        mx1 = fmaxf(mx1, __shfl_xor_sync(0xffffffffu, mx1, 2));

        const float mn0 = fmaxf(m0, mx0);
        const float mn1 = fmaxf(m1, mx1);
        const float em0 = mn0 * SFC;
        const float em1 = mn1 * SFC;
        const float cr0 = ex2f((m0 - mn0) * SFC);
        const float cr1 = ex2f((m1 - mn1) * SFC);
        m0 = mn0; m1 = mn1;

        float s0 = 0.0f, s1 = 0.0f;
#pragma unroll
        for (int nb = 0; nb < 8; ++nb) {
            float p0 = ex2f(fmaf(sacc[nb][0], SFC, -em0));
            float p1 = ex2f(fmaf(sacc[nb][1], SFC, -em0));
            float p2 = ex2f(fmaf(sacc[nb][2], SFC, -em1));
            float p3 = ex2f(fmaf(sacc[nb][3], SFC, -em1));
            sacc[nb][0] = p0; sacc[nb][1] = p1;
            sacc[nb][2] = p2; sacc[nb][3] = p3;
            s0 += p0 + p1; s1 += p2 + p3;
        }
        s0 += __shfl_xor_sync(0xffffffffu, s0, 1);
        s0 += __shfl_xor_sync(0xffffffffu, s0, 2);
        s1 += __shfl_xor_sync(0xffffffffu, s1, 1);
        s1 += __shfl_xor_sync(0xffffffffu, s1, 2);
        l0 = l0 * cr0 + s0;
        l1 = l1 * cr1 + s1;

#pragma unroll
        for (int nb = 0; nb < 8; ++nb) {
            oacc[nb][0] *= cr0; oacc[nb][1] *= cr0;
            oacc[nb][2] *= cr1; oacc[nb][3] *= cr1;
        }

        uint32_t pa[4][4];
#pragma unroll
        for (int kb = 0; kb < 4; ++kb) {
            pa[kb][0] = pack2h(sacc[2 * kb][0], sacc[2 * kb][1]);
            pa[kb][1] = pack2h(sacc[2 * kb][2], sacc[2 * kb][3]);
            pa[kb][2] = pack2h(sacc[2 * kb + 1][0], sacc[2 * kb + 1][1]);
            pa[kb][3] = pack2h(sacc[2 * kb + 1][2], sacc[2 * kb + 1][3]);
        }

#pragma unroll
        for (int kb = 0; kb < 4; ++kb) {
            uint32_t vh[8][2];
            const int vrow = kb * 16 + (lane & 7) + ((lane >> 3) & 1) * 8;
#pragma unroll
            for (int np = 0; np < 4; ++np) {
                const int vcol = np * 16 + ((lane >> 4) & 1) * 8;
                const uint32_t off = (uint32_t)(vrow * FPITCH + vcol) * 2;
                LDSM_X4_T(vh[2 * np][0], vh[2 * np][1], vh[2 * np + 1][0], vh[2 * np + 1][1],
                          sb + AV_OFF + off);
            }
#pragma unroll
            for (int nb = 0; nb < 8; ++nb)
                MMA16816(oacc[nb], pa[kb], vh[nb]);
        }

        if (j < jmax) {
            CP_WAIT0();
            __syncthreads();
        }
    }

    const float inv0 = 1.0f / l0;
    const float inv1 = 1.0f / l1;
    const int row0 = qt * 64 + w * 16 + g;
#pragma unroll
    for (int nb = 0; nb < 8; ++nb) {
        const int col = nb * 8 + 2 * tq;
        const size_t g0 = rowbase + (size_t)row0 * PD + col;
        const size_t g1 = rowbase + (size_t)(row0 + 8) * PD + col;
        *(uint32_t*)(oh_g + g0) = pack2h(oacc[nb][0] * inv0, oacc[nb][1] * inv0);
        *(uint32_t*)(oh_g + g1) = pack2h(oacc[nb][2] * inv1, oacc[nb][3] * inv1);
    }
}

// ---------------------------------------------------------------------------
extern "C" void kernel_launch(void* const* d_in, const int* in_sizes, int n_in,
                              void* d_out, int out_size)
{
    const float* Q    = (const float*)d_in[0];
    const float* K    = (const float*)d_in[1];
    const float* V    = (const float*)d_in[2];
    const float* Wq_w = (const float*)d_in[4];
    const float* Wq_b = (const float*)d_in[5];
    const float* Wk_w = (const float*)d_in[6];
    const float* Wk_b = (const float*)d_in[7];
    const float* Wv_w = (const float*)d_in[8];
    const float* Wv_b = (const float*)d_in[9];
    const float* fc_w = (const float*)d_in[10];
    const float* fc_b = (const float*)d_in[11];
    float* out = (float*)d_out;

    __half *xh, *wh, *qh, *kh, *vh, *ah;
    cudaGetSymbolAddress((void**)&xh, g_xh);
    cudaGetSymbolAddress((void**)&wh, g_wh);
    cudaGetSymbolAddress((void**)&qh, g_qh);
    cudaGetSymbolAddress((void**)&kh, g_kh);
    cudaGetSymbolAddress((void**)&vh, g_vh);
    cudaGetSymbolAddress((void**)&ah, g_ah);

    cudaFuncSetAttribute(gemm1_mma<0>,
                         cudaFuncAttributeMaxDynamicSharedMemorySize, G_SMEM);
    cudaFuncSetAttribute(gemm1_mma<2>,
                         cudaFuncAttributeMaxDynamicSharedMemorySize, G_SMEM);
    cudaFuncSetAttribute(flash_attn_mma,
                         cudaFuncAttributeMaxDynamicSharedMemorySize, ATT_SMEM);

    const int nA4 = MD / 4;
    const int nW4 = DD / 4;
    dim3 ggrid(PD / BGN, PM / BGM);   // (8, 32) = 256 CTAs, occ 2 single wave

    // Converts (2 launches)
    conv3_in<<<dim3(nA4 / 256, 1, 3), 256>>>(Q, K, V, xh);
    conv4_w<<<dim3(nW4 / 256, 1, 4), 256>>>(Wq_w, Wk_w, Wv_w, fc_w, wh);

    // Projections (single-pass fp16, occupancy 2)
    gemm1_mma<2><<<ggrid, 128, G_SMEM>>>(xh, wh, Wq_b, nullptr, qh, PD, PD);
    gemm1_mma<2><<<ggrid, 128, G_SMEM>>>(xh + MD, wh + DD, Wk_b, nullptr, kh, PD, PD);
    gemm1_mma<2><<<ggrid, 128, G_SMEM>>>(xh + 2 * (size_t)MD, wh + 2 * (size_t)DD,
                                         Wv_b, nullptr, vh, PD, PD);

    // Attention
    flash_attn_mma<<<dim3(PL / 64, PB * PH), 128, ATT_SMEM>>>(qh, kh, vh, ah);

    // Output projection (fp32 out)
    gemm1_mma<0><<<ggrid, 128, G_SMEM>>>(ah, wh + 3 * (size_t)DD, fc_b,
                                         out, nullptr, PD, PD);
}

// round 16
// speedup vs baseline: 2.3160x; 1.0433x over previous
#include <cuda_runtime.h>
#include <cuda_fp16.h>
#include <cstdint>
#include <math.h>

// Problem constants
#define PB 2
#define PL 2048
#define PD 1024
#define PH 16
#define PDK 64
#define PM (PB * PL)   // 4096
#define MD (PM * PD)
#define DD (PD * PD)

// Scratch (device globals), fp16
__device__ __half g_xh[3 * MD];    // Q,K,V inputs (fp16)
__device__ __half g_wh[4 * DD];    // Wq,Wk,Wv,fc weights (fp16)
__device__ __half g_qh[MD];        // q projection
__device__ __half g_kh[MD];        // k projection
__device__ __half g_vh[MD];        // v projection
__device__ __half g_ah[MD];        // attention output

// ---------------------------------------------------------------------------
// PTX helpers
// ---------------------------------------------------------------------------
__device__ __forceinline__ uint32_t smem_u32(const void* p) {
    uint32_t a;
    asm("{ .reg .u64 t; cvta.to.shared.u64 t, %1; cvt.u32.u64 %0, t; }"
        : "=r"(a) : "l"(p));
    return a;
}

#define MMA16816(c, a, b) \
    asm volatile("mma.sync.aligned.m16n8k16.row.col.f32.f16.f16.f32 " \
        "{%0,%1,%2,%3}, {%4,%5,%6,%7}, {%8,%9}, {%0,%1,%2,%3};" \
        : "+f"((c)[0]), "+f"((c)[1]), "+f"((c)[2]), "+f"((c)[3]) \
        : "r"((a)[0]), "r"((a)[1]), "r"((a)[2]), "r"((a)[3]), \
          "r"((b)[0]), "r"((b)[1]))

#define LDSM_X4(r0, r1, r2, r3, addr) \
    asm volatile("ldmatrix.sync.aligned.m8n8.x4.shared.b16 {%0,%1,%2,%3}, [%4];" \
        : "=r"(r0), "=r"(r1), "=r"(r2), "=r"(r3) : "r"(addr))

#define LDSM_X4_T(r0, r1, r2, r3, addr) \
    asm volatile("ldmatrix.sync.aligned.m8n8.x4.trans.shared.b16 {%0,%1,%2,%3}, [%4];" \
        : "=r"(r0), "=r"(r1), "=r"(r2), "=r"(r3) : "r"(addr))

#define CP_ASYNC16(smem, gptr) \
    asm volatile("cp.async.cg.shared.global [%0], [%1], 16;" \
        :: "r"(smem), "l"(gptr))
#define CP_COMMIT() asm volatile("cp.async.commit_group;" ::: "memory")
#define CP_WAIT0()  asm volatile("cp.async.wait_group 0;" ::: "memory")
#define CP_WAIT1()  asm volatile("cp.async.wait_group 1;" ::: "memory")

__device__ __forceinline__ float ex2f(float x) {
    float r;
    asm("ex2.approx.f32 %0, %1;" : "=f"(r) : "f"(x));
    return r;
}

__device__ __forceinline__ uint32_t pack2h(float a, float b) {
    __half2 H = __halves2half2(__float2half_rn(a), __float2half_rn(b));
    return *reinterpret_cast<uint32_t*>(&H);
}

// ---------------------------------------------------------------------------
// fp32 -> fp16 converts (batched over grid.z)
// ---------------------------------------------------------------------------
__global__ __launch_bounds__(256) void conv3_in(
    const float* __restrict__ x0, const float* __restrict__ x1,
    const float* __restrict__ x2, __half* xh)
{
    const int i = blockIdx.x * 256 + threadIdx.x;
    const int z = blockIdx.z;
    const float* x = (z == 0) ? x0 : (z == 1) ? x1 : x2;
    float4 v = reinterpret_cast<const float4*>(x)[i];
    reinterpret_cast<uint2*>(xh + (size_t)z * MD)[i] =
        make_uint2(pack2h(v.x, v.y), pack2h(v.z, v.w));
}

__global__ __launch_bounds__(256) void conv4_w(
    const float* __restrict__ x0, const float* __restrict__ x1,
    const float* __restrict__ x2, const float* __restrict__ x3,
    __half* wh)
{
    const int i = blockIdx.x * 256 + threadIdx.x;
    const int z = blockIdx.z;
    const float* x = (z == 0) ? x0 : (z == 1) ? x1 : (z == 2) ? x2 : x3;
    float4 v = reinterpret_cast<const float4*>(x)[i];
    reinterpret_cast<uint2*>(wh + (size_t)z * DD)[i] =
        make_uint2(pack2h(v.x, v.y), pack2h(v.z, v.w));
}

// ---------------------------------------------------------------------------
// mma.sync fp16 GEMM (single pass), occupancy 2, BGK=64:
// C = Ah @ Wh^T + bias.  128x128x64 tiles, 128 threads (2x2 warps,
// 64x64 warp tile), 3-stage cp.async, WAIT1.  16 chunks (half the barriers).
// OUT_MODE: 0 = fp32, 2 = fp16.
// ---------------------------------------------------------------------------
#define BGM 128
#define BGN 128
#define BGK 64
#define GP 72                             // smem pitch (fp16): 64 + 8 pad
#define A_T (BGM * GP * 2)                // 18432 B
#define B_T (BGN * GP * 2)                // 18432 B
#define OFF_A 0
#define OFF_B A_T
#define STG_B (A_T + B_T)                 // 36864 B
#define NST 3
#define G_SMEM (NST * STG_B)              // 110592 B per CTA (x2 = 221184)

template <int OUT_MODE>
__global__ __launch_bounds__(128, 2) void gemm1_mma(
    const __half* __restrict__ Ah, const __half* __restrict__ Wh,
    const float* __restrict__ bias, float* __restrict__ C,
    __half* __restrict__ Ch, int K, int N)
{
    extern __shared__ char dsm[];
    __shared__ float sbias[BGN];

    const int tid = threadIdx.x;
    const int w = tid >> 5;
    const int lane = tid & 31;
    const int wm = w >> 1;          // 0..1
    const int wn = w & 1;           // 0..1
    const int g = lane >> 2;
    const int tq = lane & 3;
    const int bm = blockIdx.y * BGM;
    const int bn = blockIdx.x * BGN;
    const uint32_t sbase = smem_u32(dsm);

    // cp.async mapping: 128 rows x 64 cols fp16 per array, 128 threads,
    // 8 iters of 16B per array
    const int lr = tid >> 3;              // 0..15
    const int lc = (tid & 7) * 8;         // 0..56

    auto issue = [&](int c, int buf) {
        const uint32_t sb = sbase + buf * STG_B;
        const int kofs = c * BGK;
#pragma unroll
        for (int it = 0; it < 8; ++it) {
            const int r = lr + it * 16;
            const uint32_t so = (uint32_t)(r * GP + lc) * 2;
            const size_t goA = (size_t)(bm + r) * K + kofs + lc;
            const size_t goB = (size_t)(bn + r) * K + kofs + lc;
            CP_ASYNC16(sb + OFF_A + so, (const char*)(Ah + goA));
            CP_ASYNC16(sb + OFF_B + so, (const char*)(Wh + goB));
        }
    };

    issue(0, 0); CP_COMMIT();
    issue(1, 1); CP_COMMIT();

    sbias[tid] = bias[bn + tid];   // blockDim == BGN == 128

    float acc[4][8][4];
#pragma unroll
    for (int mi = 0; mi < 4; ++mi)
#pragma unroll
        for (int nb = 0; nb < 8; ++nb)
#pragma unroll
            for (int e = 0; e < 4; ++e) acc[mi][nb][e] = 0.0f;

    const int a_r = (lane & 7) + ((lane >> 3) & 1) * 8;
    const int a_c = ((lane >> 4) & 1) * 8;
    const int b_r = (lane & 7) + ((lane >> 4) & 1) * 8;
    const int b_c = ((lane >> 3) & 1) * 8;

    const int nchunk = K / BGK;   // 16
    for (int c = 0; c < nchunk; ++c) {
        if (c + 1 < nchunk) CP_WAIT1(); else CP_WAIT0();
        __syncthreads();
        if (c + 2 < nchunk) { issue(c + 2, (c + 2) % NST); CP_COMMIT(); }

        const uint32_t sb = sbase + (c % NST) * STG_B;
#pragma unroll
        for (int kk = 0; kk < 4; ++kk) {
            uint32_t ah[4][4];
#pragma unroll
            for (int mi = 0; mi < 4; ++mi) {
                const uint32_t off =
                    (uint32_t)((wm * 64 + mi * 16 + a_r) * GP + kk * 16 + a_c) * 2;
                LDSM_X4(ah[mi][0], ah[mi][1], ah[mi][2], ah[mi][3],
                        sb + OFF_A + off);
            }
            uint32_t bh[8][2];
#pragma unroll
            for (int np = 0; np < 4; ++np) {
                const uint32_t off =
                    (uint32_t)((wn * 64 + np * 16 + b_r) * GP + kk * 16 + b_c) * 2;
                LDSM_X4(bh[2 * np][0], bh[2 * np][1], bh[2 * np + 1][0], bh[2 * np + 1][1],
                        sb + OFF_B + off);
            }
#pragma unroll
            for (int mi = 0; mi < 4; ++mi)
#pragma unroll
                for (int nb = 0; nb < 8; ++nb)
                    MMA16816(acc[mi][nb], ah[mi], bh[nb]);
        }
    }

    // epilogue
#pragma unroll
    for (int mi = 0; mi < 4; ++mi) {
        const int row0 = bm + wm * 64 + mi * 16 + g;
        const int row1 = row0 + 8;
#pragma unroll
        for (int nb = 0; nb < 8; ++nb) {
            const int coll = wn * 64 + nb * 8 + 2 * tq;
            const float b0 = sbias[coll];
            const float b1 = sbias[coll + 1];
            const float v0 = acc[mi][nb][0] + b0;
            const float v1 = acc[mi][nb][1] + b1;
            const float v2 = acc[mi][nb][2] + b0;
            const float v3 = acc[mi][nb][3] + b1;
            const size_t o0 = (size_t)row0 * N + bn + coll;
            const size_t o1 = (size_t)row1 * N + bn + coll;
            if (OUT_MODE == 2) {
                *(uint32_t*)(Ch + o0) = pack2h(v0, v1);
                *(uint32_t*)(Ch + o1) = pack2h(v2, v3);
            } else {
                *(float2*)(C + o0) = make_float2(v0, v1);
                *(float2*)(C + o1) = make_float2(v2, v3);
            }
        }
    }
}

// ---------------------------------------------------------------------------
// Register-resident FA2 (unchanged): all single fp16, 1 S pass + 1 PV pass,
// 64-row q-tiles, 128 threads, occ 2, heavy CTAs first.
// ---------------------------------------------------------------------------
#define FPITCH 72
#define AQ_OFF 0
#define AKV    9216
#define KV_STAGE 18432
#define AK_OFF 0
#define AV_OFF 9216
#define ATT_SMEM (AKV + 2 * KV_STAGE)     // 46080

#define SFC 0.18033688f                   // 0.125 * log2(e)

__global__ __launch_bounds__(128, 2) void flash_attn_mma(
    const __half* __restrict__ qh_g, const __half* __restrict__ kh_g,
    const __half* __restrict__ vh_g, __half* __restrict__ oh_g)
{
    extern __shared__ char dsm[];
    const int tid = threadIdx.x;
    const int w = tid >> 5;
    const int lane = tid & 31;
    const int g = lane >> 2;
    const int tq = lane & 3;
    const int qt = (int)(gridDim.x - 1) - (int)blockIdx.x;
    const int b = blockIdx.y >> 4;
    const int h = blockIdx.y & 15;
    const size_t rowbase = (size_t)b * PL * PD + (size_t)h * PDK;

    const uint32_t sQ = smem_u32(dsm + AQ_OFF);
    const uint32_t sKV = smem_u32(dsm + AKV);

    const int kr0 = tid >> 3;
    const int kc0 = (tid & 7) * 8;

    {
        const uint32_t sb = sKV;
#pragma unroll
        for (int it = 0; it < 4; ++it) {
            const int r = kr0 + it * 16;
            const uint32_t so = (uint32_t)(r * FPITCH + kc0) * 2;
            const size_t go = rowbase + (size_t)r * PD + kc0;
            CP_ASYNC16(sb + AK_OFF + so, (const char*)(kh_g + go));
            CP_ASYNC16(sb + AV_OFF + so, (const char*)(vh_g + go));
        }
        CP_COMMIT();
    }

#pragma unroll
    for (int it = 0; it < 4; ++it) {
        const int idx = tid + it * 128;
        const int r = idx >> 3;
        const int c = (idx & 7) * 8;
        const size_t go = rowbase + (size_t)(qt * 64 + r) * PD + c;
        const uint32_t so = (uint32_t)(r * FPITCH + c) * 2;
        *(uint4*)(dsm + AQ_OFF + so) = *(const uint4*)(qh_g + go);
    }
    CP_WAIT0();
    __syncthreads();

    uint32_t qh[4][4];
    {
        const int row = w * 16 + (lane & 7) + ((lane >> 3) & 1) * 8;
#pragma unroll
        for (int kb = 0; kb < 4; ++kb) {
            const int col = kb * 16 + ((lane >> 4) & 1) * 8;
            const uint32_t off = (uint32_t)(row * FPITCH + col) * 2;
            LDSM_X4(qh[kb][0], qh[kb][1], qh[kb][2], qh[kb][3], sQ + off);
        }
    }

    float oacc[8][4];
#pragma unroll
    for (int nb = 0; nb < 8; ++nb)
#pragma unroll
        for (int e = 0; e < 4; ++e) oacc[nb][e] = 0.0f;
    float m0 = -1.0e30f, m1 = -1.0e30f, l0 = 0.0f, l1 = 0.0f;

    const int jmax = qt;
    for (int j = 0; j <= jmax; ++j) {
        const int buf = j & 1;
        const uint32_t sb = sKV + buf * KV_STAGE;

        if (j < jmax) {
            const uint32_t nb_ = sKV + (buf ^ 1) * KV_STAGE;
#pragma unroll
            for (int it = 0; it < 4; ++it) {
                const int r = kr0 + it * 16;
                const uint32_t so = (uint32_t)(r * FPITCH + kc0) * 2;
                const size_t go = rowbase + (size_t)((j + 1) * 64 + r) * PD + kc0;
                CP_ASYNC16(nb_ + AK_OFF + so, (const char*)(kh_g + go));
                CP_ASYNC16(nb_ + AV_OFF + so, (const char*)(vh_g + go));
            }
            CP_COMMIT();
        }

        float sacc[8][4];
#pragma unroll
        for (int nb = 0; nb < 8; ++nb)
#pragma unroll
            for (int e = 0; e < 4; ++e) sacc[nb][e] = 0.0f;

#pragma unroll
        for (int kb = 0; kb < 4; ++kb) {
            uint32_t kh[8][2];
            const int kcol = kb * 16 + ((lane >> 3) & 1) * 8;
#pragma unroll
            for (int np = 0; np < 4; ++np) {
                const int krow = np * 16 + (lane & 7) + ((lane >> 4) & 1) * 8;
                const uint32_t off = (uint32_t)(krow * FPITCH + kcol) * 2;
                LDSM_X4(kh[2 * np][0], kh[2 * np][1], kh[2 * np + 1][0], kh[2 * np + 1][1],
                        sb + AK_OFF + off);
            }
#pragma unroll
            for (int nb = 0; nb < 8; ++nb)
                MMA16816(sacc[nb], qh[kb], kh[nb]);
        }

        if (j == qt) {
            const int row0 = qt * 64 + w * 16 + g;
            const int row1 = row0 + 8;
            const int cb = j * 64 + 2 * tq;
#pragma unroll
            for (int nb = 0; nb < 8; ++nb) {
                const int c0 = cb + nb * 8, c1 = c0 + 1;
                if (c0 > row0) sacc[nb][0] = -1.0e30f;
                if (c1 > row0) sacc[nb][1] = -1.0e30f;
                if (c0 > row1) sacc[nb][2] = -1.0e30f;
                if (c1 > row1) sacc[nb][3] = -1.0e30f;
            }
        }

        float mx0 = -1.0e30f, mx1 = -1.0e30f;
#pragma unroll
        for (int nb = 0; nb < 8; ++nb) {
            mx0 = fmaxf(mx0, fmaxf(sacc[nb][0], sacc[nb][1]));
            mx1 = fmaxf(mx1, fmaxf(sacc[nb][2], sacc[nb][3]));
        }
        mx0 = fmaxf(mx0, __shfl_xor_sync(0xffffffffu, mx0, 1));
        mx0 = fmaxf(mx0, __shfl_xor_sync(0xffffffffu, mx0, 2));
        mx1 = fmaxf(mx1, __shfl_xor_sync(0xffffffffu, mx1, 1));
        mx1 = fmaxf(mx1, __shfl_xor_sync(0xffffffffu, mx1, 2));

        const float mn0 = fmaxf(m0, mx0);
        const float mn1 = fmaxf(m1, mx1);
        const float em0 = mn0 * SFC;
        const float em1 = mn1 * SFC;
        const float cr0 = ex2f((m0 - mn0) * SFC);
        const float cr1 = ex2f((m1 - mn1) * SFC);
        m0 = mn0; m1 = mn1;

        float s0 = 0.0f, s1 = 0.0f;
#pragma unroll
        for (int nb = 0; nb < 8; ++nb) {
            float p0 = ex2f(fmaf(sacc[nb][0], SFC, -em0));
            float p1 = ex2f(fmaf(sacc[nb][1], SFC, -em0));
            float p2 = ex2f(fmaf(sacc[nb][2], SFC, -em1));
            float p3 = ex2f(fmaf(sacc[nb][3], SFC, -em1));
            sacc[nb][0] = p0; sacc[nb][1] = p1;
            sacc[nb][2] = p2; sacc[nb][3] = p3;
            s0 += p0 + p1; s1 += p2 + p3;
        }
        s0 += __shfl_xor_sync(0xffffffffu, s0, 1);
        s0 += __shfl_xor_sync(0xffffffffu, s0, 2);
        s1 += __shfl_xor_sync(0xffffffffu, s1, 1);
        s1 += __shfl_xor_sync(0xffffffffu, s1, 2);
        l0 = l0 * cr0 + s0;
        l1 = l1 * cr1 + s1;

#pragma unroll
        for (int nb = 0; nb < 8; ++nb) {
            oacc[nb][0] *= cr0; oacc[nb][1] *= cr0;
            oacc[nb][2] *= cr1; oacc[nb][3] *= cr1;
        }

        uint32_t pa[4][4];
#pragma unroll
        for (int kb = 0; kb < 4; ++kb) {
            pa[kb][0] = pack2h(sacc[2 * kb][0], sacc[2 * kb][1]);
            pa[kb][1] = pack2h(sacc[2 * kb][2], sacc[2 * kb][3]);
            pa[kb][2] = pack2h(sacc[2 * kb + 1][0], sacc[2 * kb + 1][1]);
            pa[kb][3] = pack2h(sacc[2 * kb + 1][2], sacc[2 * kb + 1][3]);
        }

#pragma unroll
        for (int kb = 0; kb < 4; ++kb) {
            uint32_t vh[8][2];
            const int vrow = kb * 16 + (lane & 7) + ((lane >> 3) & 1) * 8;
#pragma unroll
            for (int np = 0; np < 4; ++np) {
                const int vcol = np * 16 + ((lane >> 4) & 1) * 8;
                const uint32_t off = (uint32_t)(vrow * FPITCH + vcol) * 2;
                LDSM_X4_T(vh[2 * np][0], vh[2 * np][1], vh[2 * np + 1][0], vh[2 * np + 1][1],
                          sb + AV_OFF + off);
            }
#pragma unroll
            for (int nb = 0; nb < 8; ++nb)
                MMA16816(oacc[nb], pa[kb], vh[nb]);
        }

        if (j < jmax) {
            CP_WAIT0();
            __syncthreads();
        }
    }

    const float inv0 = 1.0f / l0;
    const float inv1 = 1.0f / l1;
    const int row0 = qt * 64 + w * 16 + g;
#pragma unroll
    for (int nb = 0; nb < 8; ++nb) {
        const int col = nb * 8 + 2 * tq;
        const size_t g0 = rowbase + (size_t)row0 * PD + col;
        const size_t g1 = rowbase + (size_t)(row0 + 8) * PD + col;
        *(uint32_t*)(oh_g + g0) = pack2h(oacc[nb][0] * inv0, oacc[nb][1] * inv0);
        *(uint32_t*)(oh_g + g1) = pack2h(oacc[nb][2] * inv1, oacc[nb][3] * inv1);
    }
}

// ---------------------------------------------------------------------------
extern "C" void kernel_launch(void* const* d_in, const int* in_sizes, int n_in,
                              void* d_out, int out_size)
{
    const float* Q    = (const float*)d_in[0];
    const float* K    = (const float*)d_in[1];
    const float* V    = (const float*)d_in[2];
    const float* Wq_w = (const float*)d_in[4];
    const float* Wq_b = (const float*)d_in[5];
    const float* Wk_w = (const float*)d_in[6];
    const float* Wk_b = (const float*)d_in[7];
    const float* Wv_w = (const float*)d_in[8];
    const float* Wv_b = (const float*)d_in[9];
    const float* fc_w = (const float*)d_in[10];
    const float* fc_b = (const float*)d_in[11];
    float* out = (float*)d_out;

    __half *xh, *wh, *qh, *kh, *vh, *ah;
    cudaGetSymbolAddress((void**)&xh, g_xh);
    cudaGetSymbolAddress((void**)&wh, g_wh);
    cudaGetSymbolAddress((void**)&qh, g_qh);
    cudaGetSymbolAddress((void**)&kh, g_kh);
    cudaGetSymbolAddress((void**)&vh, g_vh);
    cudaGetSymbolAddress((void**)&ah, g_ah);

    cudaFuncSetAttribute(gemm1_mma<0>,
                         cudaFuncAttributeMaxDynamicSharedMemorySize, G_SMEM);
    cudaFuncSetAttribute(gemm1_mma<2>,
                         cudaFuncAttributeMaxDynamicSharedMemorySize, G_SMEM);
    cudaFuncSetAttribute(flash_attn_mma,
                         cudaFuncAttributeMaxDynamicSharedMemorySize, ATT_SMEM);

    const int nA4 = MD / 4;
    const int nW4 = DD / 4;
    dim3 ggrid(PD / BGN, PM / BGM);   // (8, 32) = 256 CTAs, occ 2 single wave

    // Converts (2 launches)
    conv3_in<<<dim3(nA4 / 256, 1, 3), 256>>>(Q, K, V, xh);
    conv4_w<<<dim3(nW4 / 256, 1, 4), 256>>>(Wq_w, Wk_w, Wv_w, fc_w, wh);

    // Projections (single-pass fp16, occ 2, BGK=64)
    gemm1_mma<2><<<ggrid, 128, G_SMEM>>>(xh, wh, Wq_b, nullptr, qh, PD, PD);
    gemm1_mma<2><<<ggrid, 128, G_SMEM>>>(xh + MD, wh + DD, Wk_b, nullptr, kh, PD, PD);
    gemm1_mma<2><<<ggrid, 128, G_SMEM>>>(xh + 2 * (size_t)MD, wh + 2 * (size_t)DD,
                                         Wv_b, nullptr, vh, PD, PD);

    // Attention
    flash_attn_mma<<<dim3(PL / 64, PB * PH), 128, ATT_SMEM>>>(qh, kh, vh, ah);

    // Output projection (fp32 out)
    gemm1_mma<0><<<ggrid, 128, G_SMEM>>>(ah, wh + 3 * (size_t)DD, fc_b,
                                         out, nullptr, PD, PD);
}

// round 17
// speedup vs baseline: 2.4087x; 1.0401x over previous
#include <cuda_runtime.h>
#include <cuda_fp16.h>
#include <cstdint>
#include <math.h>

// Problem constants
#define PB 2
#define PL 2048
#define PD 1024
#define PH 16
#define PDK 64
#define PM (PB * PL)   // 4096
#define MD (PM * PD)
#define DD (PD * PD)

// Scratch (device globals), fp16
__device__ __half g_xh[3 * MD];    // Q,K,V inputs (fp16)
__device__ __half g_wh[4 * DD];    // Wq,Wk,Wv,fc weights (fp16, contiguous)
__device__ __half g_qkv[3 * MD];   // q,k,v projections (contiguous)
__device__ __half g_ah[MD];        // attention output

// ---------------------------------------------------------------------------
// PTX helpers
// ---------------------------------------------------------------------------
__device__ __forceinline__ uint32_t smem_u32(const void* p) {
    uint32_t a;
    asm("{ .reg .u64 t; cvta.to.shared.u64 t, %1; cvt.u32.u64 %0, t; }"
        : "=r"(a) : "l"(p));
    return a;
}

#define MMA16816(c, a, b) \
    asm volatile("mma.sync.aligned.m16n8k16.row.col.f32.f16.f16.f32 " \
        "{%0,%1,%2,%3}, {%4,%5,%6,%7}, {%8,%9}, {%0,%1,%2,%3};" \
        : "+f"((c)[0]), "+f"((c)[1]), "+f"((c)[2]), "+f"((c)[3]) \
        : "r"((a)[0]), "r"((a)[1]), "r"((a)[2]), "r"((a)[3]), \
          "r"((b)[0]), "r"((b)[1]))

#define LDSM_X4(r0, r1, r2, r3, addr) \
    asm volatile("ldmatrix.sync.aligned.m8n8.x4.shared.b16 {%0,%1,%2,%3}, [%4];" \
        : "=r"(r0), "=r"(r1), "=r"(r2), "=r"(r3) : "r"(addr))

#define LDSM_X4_T(r0, r1, r2, r3, addr) \
    asm volatile("ldmatrix.sync.aligned.m8n8.x4.trans.shared.b16 {%0,%1,%2,%3}, [%4];" \
        : "=r"(r0), "=r"(r1), "=r"(r2), "=r"(r3) : "r"(addr))

#define CP_ASYNC16(smem, gptr) \
    asm volatile("cp.async.cg.shared.global [%0], [%1], 16;" \
        :: "r"(smem), "l"(gptr))
#define CP_COMMIT() asm volatile("cp.async.commit_group;" ::: "memory")
#define CP_WAIT0()  asm volatile("cp.async.wait_group 0;" ::: "memory")
#define CP_WAIT1()  asm volatile("cp.async.wait_group 1;" ::: "memory")

__device__ __forceinline__ float ex2f(float x) {
    float r;
    asm("ex2.approx.f32 %0, %1;" : "=f"(r) : "f"(x));
    return r;
}

__device__ __forceinline__ uint32_t pack2h(float a, float b) {
    __half2 H = __halves2half2(__float2half_rn(a), __float2half_rn(b));
    return *reinterpret_cast<uint32_t*>(&H);
}

// ---------------------------------------------------------------------------
// Fused fp32 -> fp16 converts: z = 0..2 inputs (nA4 blocks),
// z = 3..6 weights (nW4 blocks; excess x-blocks return).
// ---------------------------------------------------------------------------
#define NA4 (MD / 4)
#define NW4 (DD / 4)

__global__ __launch_bounds__(256) void conv_all(
    const float* __restrict__ x0, const float* __restrict__ x1,
    const float* __restrict__ x2,
    const float* __restrict__ w0, const float* __restrict__ w1,
    const float* __restrict__ w2, const float* __restrict__ w3,
    __half* xh, __half* wh)
{
    const int z = blockIdx.z;
    const int i = blockIdx.x * 256 + threadIdx.x;
    const float* src;
    __half* dst;
    if (z < 3) {
        src = (z == 0) ? x0 : (z == 1) ? x1 : x2;
        dst = xh + (size_t)z * MD;
    } else {
        if (i >= NW4) return;
        const int zw = z - 3;
        src = (zw == 0) ? w0 : (zw == 1) ? w1 : (zw == 2) ? w2 : w3;
        dst = wh + (size_t)zw * DD;
    }
    float4 v = reinterpret_cast<const float4*>(src)[i];
    reinterpret_cast<uint2*>(dst)[i] =
        make_uint2(pack2h(v.x, v.y), pack2h(v.z, v.w));
}

// ---------------------------------------------------------------------------
// mma.sync fp16 GEMM (single pass), occ 2, BGK=64, z-batched:
// C[z] = A[z] @ W[z]^T + bias[z].  128x128x64 tiles, 128 threads (2x2 warps),
// 3-stage cp.async, WAIT1, 16 chunks.  OUT_MODE: 0 = fp32, 2 = fp16.
// ---------------------------------------------------------------------------
#define BGM 128
#define BGN 128
#define BGK 64
#define GP 72
#define A_T (BGM * GP * 2)                // 18432 B
#define B_T (BGN * GP * 2)                // 18432 B
#define OFF_A 0
#define OFF_B A_T
#define STG_B (A_T + B_T)                 // 36864 B
#define NST 3
#define G_SMEM (NST * STG_B)              // 110592 B per CTA (x2 = 221184)

template <int OUT_MODE>
__global__ __launch_bounds__(128, 2) void gemm1_mma(
    const __half* __restrict__ Ah, const __half* __restrict__ Wh,
    const float* __restrict__ b0, const float* __restrict__ b1,
    const float* __restrict__ b2,
    float* __restrict__ C, __half* __restrict__ Ch, int K, int N)
{
    extern __shared__ char dsm[];
    __shared__ float sbias[BGN];

    const int tid = threadIdx.x;
    const int w = tid >> 5;
    const int lane = tid & 31;
    const int wm = w >> 1;
    const int wn = w & 1;
    const int g = lane >> 2;
    const int tq = lane & 3;
    const int bm = blockIdx.y * BGM;
    const int bn = blockIdx.x * BGN;
    const int z = blockIdx.z;
    const uint32_t sbase = smem_u32(dsm);

    const __half* Az = Ah + (size_t)z * MD;
    const __half* Wz = Wh + (size_t)z * DD;
    const float* bias = (z == 0) ? b0 : (z == 1) ? b1 : b2;
    __half* Cz = (OUT_MODE == 2) ? Ch + (size_t)z * MD : nullptr;

    const int lr = tid >> 3;              // 0..15
    const int lc = (tid & 7) * 8;         // 0..56

    auto issue = [&](int c, int buf) {
        const uint32_t sb = sbase + buf * STG_B;
        const int kofs = c * BGK;
#pragma unroll
        for (int it = 0; it < 8; ++it) {
            const int r = lr + it * 16;
            const uint32_t so = (uint32_t)(r * GP + lc) * 2;
            const size_t goA = (size_t)(bm + r) * K + kofs + lc;
            const size_t goB = (size_t)(bn + r) * K + kofs + lc;
            CP_ASYNC16(sb + OFF_A + so, (const char*)(Az + goA));
            CP_ASYNC16(sb + OFF_B + so, (const char*)(Wz + goB));
        }
    };

    issue(0, 0); CP_COMMIT();
    issue(1, 1); CP_COMMIT();

    sbias[tid] = bias[bn + tid];   // blockDim == BGN == 128

    float acc[4][8][4];
#pragma unroll
    for (int mi = 0; mi < 4; ++mi)
#pragma unroll
        for (int nb = 0; nb < 8; ++nb)
#pragma unroll
            for (int e = 0; e < 4; ++e) acc[mi][nb][e] = 0.0f;

    const int a_r = (lane & 7) + ((lane >> 3) & 1) * 8;
    const int a_c = ((lane >> 4) & 1) * 8;
    const int b_r = (lane & 7) + ((lane >> 4) & 1) * 8;
    const int b_c = ((lane >> 3) & 1) * 8;

    const int nchunk = K / BGK;   // 16
    for (int c = 0; c < nchunk; ++c) {
        if (c + 1 < nchunk) CP_WAIT1(); else CP_WAIT0();
        __syncthreads();
        if (c + 2 < nchunk) { issue(c + 2, (c + 2) % NST); CP_COMMIT(); }

        const uint32_t sb = sbase + (c % NST) * STG_B;
#pragma unroll
        for (int kk = 0; kk < 4; ++kk) {
            uint32_t ah[4][4];
#pragma unroll
            for (int mi = 0; mi < 4; ++mi) {
                const uint32_t off =
                    (uint32_t)((wm * 64 + mi * 16 + a_r) * GP + kk * 16 + a_c) * 2;
                LDSM_X4(ah[mi][0], ah[mi][1], ah[mi][2], ah[mi][3],
                        sb + OFF_A + off);
            }
            uint32_t bh[8][2];
#pragma unroll
            for (int np = 0; np < 4; ++np) {
                const uint32_t off =
                    (uint32_t)((wn * 64 + np * 16 + b_r) * GP + kk * 16 + b_c) * 2;
                LDSM_X4(bh[2 * np][0], bh[2 * np][1], bh[2 * np + 1][0], bh[2 * np + 1][1],
                        sb + OFF_B + off);
            }
#pragma unroll
            for (int mi = 0; mi < 4; ++mi)
#pragma unroll
                for (int nb = 0; nb < 8; ++nb)
                    MMA16816(acc[mi][nb], ah[mi], bh[nb]);
        }
    }

    // epilogue
#pragma unroll
    for (int mi = 0; mi < 4; ++mi) {
        const int row0 = bm + wm * 64 + mi * 16 + g;
        const int row1 = row0 + 8;
#pragma unroll
        for (int nb = 0; nb < 8; ++nb) {
            const int coll = wn * 64 + nb * 8 + 2 * tq;
            const float bb0 = sbias[coll];
            const float bb1 = sbias[coll + 1];
            const float v0 = acc[mi][nb][0] + bb0;
            const float v1 = acc[mi][nb][1] + bb1;
            const float v2 = acc[mi][nb][2] + bb0;
            const float v3 = acc[mi][nb][3] + bb1;
            const size_t o0 = (size_t)row0 * N + bn + coll;
            const size_t o1 = (size_t)row1 * N + bn + coll;
            if (OUT_MODE == 2) {
                *(uint32_t*)(Cz + o0) = pack2h(v0, v1);
                *(uint32_t*)(Cz + o1) = pack2h(v2, v3);
            } else {
                *(float2*)(C + o0) = make_float2(v0, v1);
                *(float2*)(C + o1) = make_float2(v2, v3);
            }
        }
    }
}

// ---------------------------------------------------------------------------
// Register-resident FA2 (unchanged from round 16).
// ---------------------------------------------------------------------------
#define FPITCH 72
#define AQ_OFF 0
#define AKV    9216
#define KV_STAGE 18432
#define AK_OFF 0
#define AV_OFF 9216
#define ATT_SMEM (AKV + 2 * KV_STAGE)     // 46080

#define SFC 0.18033688f                   // 0.125 * log2(e)

__global__ __launch_bounds__(128, 2) void flash_attn_mma(
    const __half* __restrict__ qh_g, const __half* __restrict__ kh_g,
    const __half* __restrict__ vh_g, __half* __restrict__ oh_g)
{
    extern __shared__ char dsm[];
    const int tid = threadIdx.x;
    const int w = tid >> 5;
    const int lane = tid & 31;
    const int g = lane >> 2;
    const int tq = lane & 3;
    const int qt = (int)(gridDim.x - 1) - (int)blockIdx.x;
    const int b = blockIdx.y >> 4;
    const int h = blockIdx.y & 15;
    const size_t rowbase = (size_t)b * PL * PD + (size_t)h * PDK;

    const uint32_t sQ = smem_u32(dsm + AQ_OFF);
    const uint32_t sKV = smem_u32(dsm + AKV);

    const int kr0 = tid >> 3;
    const int kc0 = (tid & 7) * 8;

    {
        const uint32_t sb = sKV;
#pragma unroll
        for (int it = 0; it < 4; ++it) {
            const int r = kr0 + it * 16;
            const uint32_t so = (uint32_t)(r * FPITCH + kc0) * 2;
            const size_t go = rowbase + (size_t)r * PD + kc0;
            CP_ASYNC16(sb + AK_OFF + so, (const char*)(kh_g + go));
            CP_ASYNC16(sb + AV_OFF + so, (const char*)(vh_g + go));
        }
        CP_COMMIT();
    }

#pragma unroll
    for (int it = 0; it < 4; ++it) {
        const int idx = tid + it * 128;
        const int r = idx >> 3;
        const int c = (idx & 7) * 8;
        const size_t go = rowbase + (size_t)(qt * 64 + r) * PD + c;
        const uint32_t so = (uint32_t)(r * FPITCH + c) * 2;
        *(uint4*)(dsm + AQ_OFF + so) = *(const uint4*)(qh_g + go);
    }
    CP_WAIT0();
    __syncthreads();

    uint32_t qh[4][4];
    {
        const int row = w * 16 + (lane & 7) + ((lane >> 3) & 1) * 8;
#pragma unroll
        for (int kb = 0; kb < 4; ++kb) {
            const int col = kb * 16 + ((lane >> 4) & 1) * 8;
            const uint32_t off = (uint32_t)(row * FPITCH + col) * 2;
            LDSM_X4(qh[kb][0], qh[kb][1], qh[kb][2], qh[kb][3], sQ + off);
        }
    }

    float oacc[8][4];
#pragma unroll
    for (int nb = 0; nb < 8; ++nb)
#pragma unroll
        for (int e = 0; e < 4; ++e) oacc[nb][e] = 0.0f;
    float m0 = -1.0e30f, m1 = -1.0e30f, l0 = 0.0f, l1 = 0.0f;

    const int jmax = qt;
    for (int j = 0; j <= jmax; ++j) {
        const int buf = j & 1;
        const uint32_t sb = sKV + buf * KV_STAGE;

        if (j < jmax) {
            const uint32_t nb_ = sKV + (buf ^ 1) * KV_STAGE;
#pragma unroll
            for (int it = 0; it < 4; ++it) {
                const int r = kr0 + it * 16;
                const uint32_t so = (uint32_t)(r * FPITCH + kc0) * 2;
                const size_t go = rowbase + (size_t)((j + 1) * 64 + r) * PD + kc0;
                CP_ASYNC16(nb_ + AK_OFF + so, (const char*)(kh_g + go));
                CP_ASYNC16(nb_ + AV_OFF + so, (const char*)(vh_g + go));
            }
            CP_COMMIT();
        }

        float sacc[8][4];
#pragma unroll
        for (int nb = 0; nb < 8; ++nb)
#pragma unroll
            for (int e = 0; e < 4; ++e) sacc[nb][e] = 0.0f;

#pragma unroll
        for (int kb = 0; kb < 4; ++kb) {
            uint32_t kh[8][2];
            const int kcol = kb * 16 + ((lane >> 3) & 1) * 8;
#pragma unroll
            for (int np = 0; np < 4; ++np) {
                const int krow = np * 16 + (lane & 7) + ((lane >> 4) & 1) * 8;
                const uint32_t off = (uint32_t)(krow * FPITCH + kcol) * 2;
                LDSM_X4(kh[2 * np][0], kh[2 * np][1], kh[2 * np + 1][0], kh[2 * np + 1][1],
                        sb + AK_OFF + off);
            }
#pragma unroll
            for (int nb = 0; nb < 8; ++nb)
                MMA16816(sacc[nb], qh[kb], kh[nb]);
        }

        if (j == qt) {
            const int row0 = qt * 64 + w * 16 + g;
            const int row1 = row0 + 8;
            const int cb = j * 64 + 2 * tq;
#pragma unroll
            for (int nb = 0; nb < 8; ++nb) {
                const int c0 = cb + nb * 8, c1 = c0 + 1;
                if (c0 > row0) sacc[nb][0] = -1.0e30f;
                if (c1 > row0) sacc[nb][1] = -1.0e30f;
                if (c0 > row1) sacc[nb][2] = -1.0e30f;
                if (c1 > row1) sacc[nb][3] = -1.0e30f;
            }
        }

        float mx0 = -1.0e30f, mx1 = -1.0e30f;
#pragma unroll
        for (int nb = 0; nb < 8; ++nb) {
            mx0 = fmaxf(mx0, fmaxf(sacc[nb][0], sacc[nb][1]));
            mx1 = fmaxf(mx1, fmaxf(sacc[nb][2], sacc[nb][3]));
        }
        mx0 = fmaxf(mx0, __shfl_xor_sync(0xffffffffu, mx0, 1));
        mx0 = fmaxf(mx0, __shfl_xor_sync(0xffffffffu, mx0, 2));
        mx1 = fmaxf(mx1, __shfl_xor_sync(0xffffffffu, mx1, 1));
        mx1 = fmaxf(mx1, __shfl_xor_sync(0xffffffffu, mx1, 2));

        const float mn0 = fmaxf(m0, mx0);
        const float mn1 = fmaxf(m1, mx1);
        const float em0 = mn0 * SFC;
        const float em1 = mn1 * SFC;
        const float cr0 = ex2f((m0 - mn0) * SFC);
        const float cr1 = ex2f((m1 - mn1) * SFC);
        m0 = mn0; m1 = mn1;

        float s0 = 0.0f, s1 = 0.0f;
#pragma unroll
        for (int nb = 0; nb < 8; ++nb) {
            float p0 = ex2f(fmaf(sacc[nb][0], SFC, -em0));
            float p1 = ex2f(fmaf(sacc[nb][1], SFC, -em0));
            float p2 = ex2f(fmaf(sacc[nb][2], SFC, -em1));
            float p3 = ex2f(fmaf(sacc[nb][3], SFC, -em1));
            sacc[nb][0] = p0; sacc[nb][1] = p1;
            sacc[nb][2] = p2; sacc[nb][3] = p3;
            s0 += p0 + p1; s1 += p2 + p3;
        }
        s0 += __shfl_xor_sync(0xffffffffu, s0, 1);
        s0 += __shfl_xor_sync(0xffffffffu, s0, 2);
        s1 += __shfl_xor_sync(0xffffffffu, s1, 1);
        s1 += __shfl_xor_sync(0xffffffffu, s1, 2);
        l0 = l0 * cr0 + s0;
        l1 = l1 * cr1 + s1;

#pragma unroll
        for (int nb = 0; nb < 8; ++nb) {
            oacc[nb][0] *= cr0; oacc[nb][1] *= cr0;
            oacc[nb][2] *= cr1; oacc[nb][3] *= cr1;
        }

        uint32_t pa[4][4];
#pragma unroll
        for (int kb = 0; kb < 4; ++kb) {
            pa[kb][0] = pack2h(sacc[2 * kb][0], sacc[2 * kb][1]);
            pa[kb][1] = pack2h(sacc[2 * kb][2], sacc[2 * kb][3]);
            pa[kb][2] = pack2h(sacc[2 * kb + 1][0], sacc[2 * kb + 1][1]);
            pa[kb][3] = pack2h(sacc[2 * kb + 1][2], sacc[2 * kb + 1][3]);
        }

#pragma unroll
        for (int kb = 0; kb < 4; ++kb) {
            uint32_t vh[8][2];
            const int vrow = kb * 16 + (lane & 7) + ((lane >> 3) & 1) * 8;
#pragma unroll
            for (int np = 0; np < 4; ++np) {
                const int vcol = np * 16 + ((lane >> 4) & 1) * 8;
                const uint32_t off = (uint32_t)(vrow * FPITCH + vcol) * 2;
                LDSM_X4_T(vh[2 * np][0], vh[2 * np][1], vh[2 * np + 1][0], vh[2 * np + 1][1],
                          sb + AV_OFF + off);
            }
#pragma unroll
            for (int nb = 0; nb < 8; ++nb)
                MMA16816(oacc[nb], pa[kb], vh[nb]);
        }

        if (j < jmax) {
            CP_WAIT0();
            __syncthreads();
        }
    }

    const float inv0 = 1.0f / l0;
    const float inv1 = 1.0f / l1;
    const int row0 = qt * 64 + w * 16 + g;
#pragma unroll
    for (int nb = 0; nb < 8; ++nb) {
        const int col = nb * 8 + 2 * tq;
        const size_t g0 = rowbase + (size_t)row0 * PD + col;
        const size_t g1 = rowbase + (size_t)(row0 + 8) * PD + col;
        *(uint32_t*)(oh_g + g0) = pack2h(oacc[nb][0] * inv0, oacc[nb][1] * inv0);
        *(uint32_t*)(oh_g + g1) = pack2h(oacc[nb][2] * inv1, oacc[nb][3] * inv1);
    }
}

// ---------------------------------------------------------------------------
extern "C" void kernel_launch(void* const* d_in, const int* in_sizes, int n_in,
                              void* d_out, int out_size)
{
    const float* Q    = (const float*)d_in[0];
    const float* K    = (const float*)d_in[1];
    const float* V    = (const float*)d_in[2];
    const float* Wq_w = (const float*)d_in[4];
    const float* Wq_b = (const float*)d_in[5];
    const float* Wk_w = (const float*)d_in[6];
    const float* Wk_b = (const float*)d_in[7];
    const float* Wv_w = (const float*)d_in[8];
    const float* Wv_b = (const float*)d_in[9];
    const float* fc_w = (const float*)d_in[10];
    const float* fc_b = (const float*)d_in[11];
    float* out = (float*)d_out;

    __half *xh, *wh, *qkv, *ah;
    cudaGetSymbolAddress((void**)&xh, g_xh);
    cudaGetSymbolAddress((void**)&wh, g_wh);
    cudaGetSymbolAddress((void**)&qkv, g_qkv);
    cudaGetSymbolAddress((void**)&ah, g_ah);

    cudaFuncSetAttribute(gemm1_mma<0>,
                         cudaFuncAttributeMaxDynamicSharedMemorySize, G_SMEM);
    cudaFuncSetAttribute(gemm1_mma<2>,
                         cudaFuncAttributeMaxDynamicSharedMemorySize, G_SMEM);
    cudaFuncSetAttribute(flash_attn_mma,
                         cudaFuncAttributeMaxDynamicSharedMemorySize, ATT_SMEM);

    // 1) All converts in one launch
    conv_all<<<dim3(NA4 / 256, 1, 7), 256>>>(Q, K, V, Wq_w, Wk_w, Wv_w, fc_w,
                                             xh, wh);

    // 2) All three projections in one z-batched launch (768 CTAs, occ 2)
    gemm1_mma<2><<<dim3(PD / BGN, PM / BGM, 3), 128, G_SMEM>>>(
        xh, wh, Wq_b, Wk_b, Wv_b, nullptr, qkv, PD, PD);

    // 3) Attention
    flash_attn_mma<<<dim3(PL / 64, PB * PH), 128, ATT_SMEM>>>(
        qkv, qkv + MD, qkv + 2 * (size_t)MD, ah);

    // 4) Output projection (fp32 out; z = 0, weight slice 3)
    gemm1_mma<0><<<dim3(PD / BGN, PM / BGM, 1), 128, G_SMEM>>>(
        ah, wh + 3 * (size_t)DD, fc_b, fc_b, fc_b, out, nullptr, PD, PD);
}